// round 10
// baseline (speedup 1.0000x reference)
#include <cuda_runtime.h>
#include <cuda_bf16.h>
#include <math.h>
#include <stdint.h>
#include <stddef.h>

// Problem constants
#define BB 32
#define NN 1024
#define EE 16384
#define ETOT (EE + NN)
#define IND 768
#define HIDD 512
#define OUTD 400
#define PAIRD 800
#define BNR (BB * NN)          // 32768
#define BER (BB * EE)          // 524288
#define FEAT_ELEMS ((size_t)BNR * OUTD)

typedef __nv_bfloat16 bf16;

#if defined(__CUDA_ARCH_FEAT_SM103_ALL) || defined(__CUDA_ARCH_FEAT_SM100_ALL) || defined(__CUDA_ARCH_FEAT_SM101_ALL)
#define HAS_TC 1
#else
#define HAS_TC 0
#endif

// ---------------- device scratch ----------------
__device__ bf16  g_Xhi[(size_t)BNR * IND];
__device__ bf16  g_Xlo[(size_t)BNR * IND];
__device__ bf16  g_hid_hi[(size_t)BNR * HIDD];
__device__ bf16  g_hid_lo[(size_t)BNR * HIDD];
__device__ float g_enc[(size_t)BNR * OUTD];
__device__ bf16  g_enc_hi[(size_t)BNR * OUTD];
__device__ bf16  g_enc_lo[(size_t)BNR * OUTD];
__device__ float g_wh[(size_t)BNR * OUTD];
__device__ bf16  g_feat_hi[(size_t)BNR * OUTD];
__device__ bf16  g_feat_lo[(size_t)BNR * OUTD];
__device__ float g_U[(size_t)BNR * PAIRD];        // feat @ W1top [32768,800]
__device__ float g_V[(size_t)BNR * PAIRD];        // feat @ W1bot
// transposed/split weights [N][K]
__device__ bf16  g_w1t_hi[HIDD * IND],  g_w1t_lo[HIDD * IND];
__device__ bf16  g_w2t_hi[OUTD * HIDD], g_w2t_lo[OUTD * HIDD];
__device__ bf16  g_wgt_hi[OUTD * OUTD], g_wgt_lo[OUTD * OUTD];
__device__ bf16  g_w1a_hi[PAIRD * OUTD], g_w1a_lo[PAIRD * OUTD];   // W1top^T [800,400]
__device__ bf16  g_w1b_hi[PAIRD * OUTD], g_w1b_lo[PAIRD * OUTD];   // W1bot^T
__device__ bf16  g_h2t_hi[(PAIRD/2) * PAIRD], g_h2t_lo[(PAIRD/2) * PAIRD];
__device__ float g_as[BNR * 2], g_ad[BNR * 2];
__device__ int   g_counts[NN], g_rowstart[NN + 1], g_fill[NN], g_csrsrc[ETOT];

// tanhf lowers to the HW MUFU.TANH path on sm_103a — measured faster than any
// __expf-based sigmoid form (round-8 isolation test).
__device__ __forceinline__ float gelu_tanh(float x) {
    const float c = 0.7978845608028654f;
    float x3 = x * x * x;
    return 0.5f * x * (1.0f + tanhf(c * (x + 0.044715f * x3)));
}

// ---------------- PTX helpers ----------------
__device__ __forceinline__ uint32_t smem_u32(const void* p) {
    uint32_t a;
    asm("{ .reg .u64 t; cvta.to.shared.u64 t, %1; cvt.u32.u64 %0, t; }" : "=r"(a) : "l"(p));
    return a;
}
__device__ __forceinline__ uint32_t elect1() {
    uint32_t r;
    asm volatile("{\n\t.reg .pred p;\n\telect.sync _|p, 0xFFFFFFFF;\n\tselp.b32 %0, 1, 0, p;\n\t}" : "=r"(r));
    return r;
}
#define SW128(o) ((o) ^ (((o) >> 3) & 0x70))

__device__ __forceinline__ uint64_t mk_desc(uint32_t addr) {
    const uint64_t base = (uint64_t(2) << 61) | (uint64_t(1) << 46) |
                          (uint64_t(64) << 32) | (uint64_t(1) << 16);
    return base | ((uint64_t)(addr >> 4) & 0x3FFF);
}

#define MBARRIER_INIT(addr, cnt) \
    asm volatile("mbarrier.init.shared.b64 [%0], %1;" :: "r"((uint32_t)(addr)), "r"((uint32_t)(cnt)) : "memory")

#define MBARRIER_WAIT_PARITY(addr, parity) do { \
    uint32_t _mbar = (uint32_t)(addr); \
    uint32_t _par = (uint32_t)(parity); \
    uint32_t _done; \
    asm volatile("{\n\t.reg .pred p;\n\t" \
        "mbarrier.try_wait.parity.acquire.cta.shared::cta.b64 p, [%1], %2;\n\t" \
        "selp.b32 %0, 1, 0, p;\n\t}" : "=r"(_done) : "r"(_mbar), "r"(_par) : "memory"); \
    if (!_done) { \
        asm volatile("{\n\t.reg .pred P1;\n\t" \
            "WAIT_LOOP_%=:\n\t" \
            "mbarrier.try_wait.parity.acquire.cta.shared::cta.b64 P1, [%0], %1, 0x989680;\n\t" \
            "@P1 bra.uni WAIT_DONE_%=;\n\t" \
            "bra.uni WAIT_LOOP_%=;\n\t" \
            "WAIT_DONE_%=:\n\t}" :: "r"(_mbar), "r"(_par) : "memory"); \
    } \
} while (0)

#if HAS_TC
#define TCGEN05_ALLOC(smem_addr, nCols) \
    asm volatile("tcgen05.alloc.cta_group::1.sync.aligned.shared::cta.b32 [%0], %1;" \
        :: "r"((uint32_t)(smem_addr)), "r"((uint32_t)(nCols)) : "memory")
#define TCGEN05_DEALLOC(tmem, nCols) \
    asm volatile("tcgen05.dealloc.cta_group::1.sync.aligned.b32 %0, %1;" :: "r"(tmem), "r"((uint32_t)(nCols)))
#define TCGEN05_COMMIT(mbar) \
    asm volatile("tcgen05.commit.cta_group::1.mbarrier::arrive::one.shared::cluster.b64 [%0];" \
        :: "r"((uint32_t)(mbar)) : "memory")
#define TCGEN05_FENCE_AFTER() asm volatile("tcgen05.fence::after_thread_sync;" ::: "memory")
#define TCGEN05_WAIT_LD() asm volatile("tcgen05.wait::ld.sync.aligned;" ::: "memory")

#define TCGEN05_LD_32X32B_X32(r, tmem_addr) \
    asm volatile( \
        "tcgen05.ld.sync.aligned.32x32b.x32.b32 " \
        "{%0, %1, %2, %3, %4, %5, %6, %7, " \
        " %8, %9, %10, %11, %12, %13, %14, %15, " \
        " %16, %17, %18, %19, %20, %21, %22, %23, " \
        " %24, %25, %26, %27, %28, %29, %30, %31}, [%32];" \
        : "=r"((r)[0]),  "=r"((r)[1]),  "=r"((r)[2]),  "=r"((r)[3]), \
          "=r"((r)[4]),  "=r"((r)[5]),  "=r"((r)[6]),  "=r"((r)[7]), \
          "=r"((r)[8]),  "=r"((r)[9]),  "=r"((r)[10]), "=r"((r)[11]), \
          "=r"((r)[12]), "=r"((r)[13]), "=r"((r)[14]), "=r"((r)[15]), \
          "=r"((r)[16]), "=r"((r)[17]), "=r"((r)[18]), "=r"((r)[19]), \
          "=r"((r)[20]), "=r"((r)[21]), "=r"((r)[22]), "=r"((r)[23]), \
          "=r"((r)[24]), "=r"((r)[25]), "=r"((r)[26]), "=r"((r)[27]), \
          "=r"((r)[28]), "=r"((r)[29]), "=r"((r)[30]), "=r"((r)[31]) \
        : "r"(tmem_addr))

__device__ __forceinline__ void mma_bf16_ss(uint32_t d, uint64_t ad, uint64_t bd,
                                            uint32_t idesc, uint32_t en) {
    asm volatile(
        "{\n\t.reg .pred p;\n\tsetp.ne.u32 p, %5, 0;\n\t"
        "tcgen05.mma.cta_group::1.kind::f16 [%0], %1, %2, %3, {%4, %4, %4, %4}, p;\n\t}"
        :: "r"(d), "l"(ad), "l"(bd), "r"(idesc), "r"(0u), "r"(en) : "memory");
}
#endif // HAS_TC

// ---------------- prep kernels ----------------
__global__ void split_kernel(const float* __restrict__ in, bf16* __restrict__ hi,
                             bf16* __restrict__ lo, size_t n) {
    size_t i = (size_t)blockIdx.x * 256 + threadIdx.x;
    if (i < n) {
        float v = in[i];
        bf16 h = __float2bfloat16(v);
        hi[i] = h;
        lo[i] = __float2bfloat16(v - __bfloat162float(h));
    }
}
// out[n*Kw+k] = W[(rowOff+k)*ldW + n]  (transpose + split)
__global__ void tsplit_kernel(const float* __restrict__ W, bf16* __restrict__ hi,
                              bf16* __restrict__ lo, int Kw, int Nw, int rowOff, int ldW) {
    int i = blockIdx.x * 256 + threadIdx.x;
    if (i < Kw * Nw) {
        int n = i / Kw, k = i - n * Kw;
        float v = W[(size_t)(rowOff + k) * ldW + n];
        bf16 h = __float2bfloat16(v);
        hi[i] = h;
        lo[i] = __float2bfloat16(v - __bfloat162float(h));
    }
}

// ---------------- split-bf16 tcgen05 GEMM, BM=128, BN<=256, BK=64 ----------------
#define MMK_STAGES 2
#define STAGE_BYTES 98304        // A hi/lo 32KB + B hi/lo 64KB
#define HDR_BYTES 8192
#define SMEM_TOTAL_MM (HDR_BYTES + MMK_STAGES * STAGE_BYTES)
#define CPITCH 65

template<bool BIAS, bool GELU_, bool WF32, bool WHILO>
__global__ __launch_bounds__(256, 1) void mm_kernel(
    const bf16* __restrict__ Ahi, const bf16* __restrict__ Alo,
    const bf16* __restrict__ Bhi, const bf16* __restrict__ Blo,
    const float* __restrict__ bias,
    float* __restrict__ Cf, bf16* __restrict__ Chi, bf16* __restrict__ Clo,
    int N, int K)
{
#if HAS_TC
    extern __shared__ char dsm[];
    const int tid = threadIdx.x;
    const int wid = tid >> 5;
    const uint32_t sb = smem_u32(dsm);
    const int mBase = blockIdx.y * 128;
    const int nBase = blockIdx.x * 256;
    const int nValid = min(256, N - nBase);

    if (tid == 0) {
        for (int s = 0; s < MMK_STAGES; s++) MBARRIER_INIT(sb + 16 + s * 8, 1);
    }
    if (wid == 0) TCGEN05_ALLOC(sb, 256);
    __syncthreads();
    uint32_t tmem;
    asm volatile("ld.shared.b32 %0, [%1];" : "=r"(tmem) : "r"(sb));

    const uint32_t idesc = (1u << 4) | (1u << 7) | (1u << 10) |
                           ((uint32_t)(nValid >> 3) << 17) | (8u << 24);
    const int NC = (K + 63) >> 6;

    for (int c = 0; c < NC; c++) {
        int s = c & 1;
        if (c >= MMK_STAGES) {
            MBARRIER_WAIT_PARITY(sb + 16 + s * 8, ((c >> 1) - 1) & 1);
        }
        char* stg = dsm + HDR_BYTES + s * STAGE_BYTES;
        int k0 = c << 6;
        // ---- A planes (128 x 64) ----
#pragma unroll
        for (int i = 0; i < 4; i++) {
            int idx = i * 256 + tid;
            int row = idx >> 3, seg = idx & 7;
            int col = k0 + seg * 8;
            if (col < K) {
                size_t off = (size_t)(mBase + row) * K + col;
                uint4 vh = *(const uint4*)(Ahi + off);
                uint4 vl = *(const uint4*)(Alo + off);
                uint32_t sw = SW128(row * 128 + seg * 16);
                *(uint4*)(stg + sw) = vh;
                *(uint4*)(stg + 16384 + sw) = vl;
            }
        }
        // ---- B planes (nValid x 64) ----
#pragma unroll
        for (int i = 0; i < 8; i++) {
            int idx = i * 256 + tid;
            int row = idx >> 3, seg = idx & 7;
            int col = k0 + seg * 8;
            if (row < nValid && col < K) {
                size_t off = (size_t)(nBase + row) * K + col;
                uint4 vh = *(const uint4*)(Bhi + off);
                uint4 vl = *(const uint4*)(Blo + off);
                uint32_t sw = SW128(row * 128 + seg * 16);
                *(uint4*)(stg + 32768 + sw) = vh;
                *(uint4*)(stg + 65536 + sw) = vl;
            }
        }
        asm volatile("fence.proxy.async.shared::cta;" ::: "memory");
        __syncthreads();
        if (wid == 0 && elect1()) {
            uint32_t sg = sb + HDR_BYTES + s * STAGE_BYTES;
            uint64_t dAh = mk_desc(sg);
            uint64_t dAl = mk_desc(sg + 16384);
            uint64_t dBh = mk_desc(sg + 32768);
            uint64_t dBl = mk_desc(sg + 65536);
            int ksteps = min(4, (K - k0 + 15) >> 4);
            for (int ks = 0; ks < ksteps; ks++) {
                uint64_t o = (uint64_t)(ks * 2);
                mma_bf16_ss(tmem, dAh + o, dBh + o, idesc, (c | ks) ? 1u : 0u);
                mma_bf16_ss(tmem, dAh + o, dBl + o, idesc, 1u);
                mma_bf16_ss(tmem, dAl + o, dBh + o, idesc, 1u);
            }
            TCGEN05_COMMIT(sb + 16 + s * 8);
        }
    }
    {
        int lc = NC - 1;
        MBARRIER_WAIT_PARITY(sb + 16 + (lc & 1) * 8, (lc >> 1) & 1);
    }
    TCGEN05_FENCE_AFTER();

    // ---- epilogue ----
    {
        int sub = wid & 3, cg = wid >> 2;
        int lane = tid & 31;
        float* cst = (float*)(dsm + HDR_BYTES);
        for (int cb0 = 0; cb0 < nValid; cb0 += 64) {
            int cb = cb0 + cg * 32;
            if (cb < nValid) {
                uint32_t regs[32];
                TCGEN05_LD_32X32B_X32(regs, tmem + cb);
                TCGEN05_WAIT_LD();
                int r = sub * 32 + lane;
#pragma unroll
                for (int j = 0; j < 32; j++) {
                    int col = cb + j;
                    if (col < nValid) {
                        float v = __uint_as_float(regs[j]);
                        if (BIAS) v += bias[nBase + col];
                        if (GELU_) v = gelu_tanh(v);
                        cst[r * CPITCH + (cg * 32 + j)] = v;
                    }
                }
            }
            __syncthreads();
            int cw = min(64, nValid - cb0);
            for (int i = tid; i < 128 * cw; i += 256) {
                int row = i / cw, col = i - row * cw;
                float v = cst[row * CPITCH + col];
                size_t gr = (size_t)(mBase + row);
                int gc = nBase + cb0 + col;
                if (WF32) Cf[gr * N + gc] = v;
                if (WHILO) {
                    bf16 h = __float2bfloat16(v);
                    Chi[gr * N + gc] = h;
                    Clo[gr * N + gc] = __float2bfloat16(v - __bfloat162float(h));
                }
            }
            __syncthreads();
        }
    }
    __syncthreads();
    if (wid == 0) TCGEN05_DEALLOC(tmem, 256);

#else // !HAS_TC — naive correct fallback (compile-only for non-'a' PTX pass)
    const int tid = threadIdx.x;
    const int mBase = blockIdx.y * 128;
    const int nBase = blockIdx.x * 256;
    const int nValid = min(256, N - nBase);
    if (tid >= 128) return;
    int row = mBase + tid;
    for (int col = 0; col < nValid; col++) {
        int gc = nBase + col;
        float acc = 0.f;
        for (int k = 0; k < K; k++) {
            size_t off = (size_t)row * K + k;
            float a = __bfloat162float(Ahi[off]) + __bfloat162float(Alo[off]);
            size_t bo = (size_t)gc * K + k;
            float bb = __bfloat162float(Bhi[bo]) + __bfloat162float(Blo[bo]);
            acc += a * bb;
        }
        if (BIAS) acc += bias[gc];
        if (GELU_) acc = gelu_tanh(acc);
        if (WF32) Cf[(size_t)row * N + gc] = acc;
        if (WHILO) {
            bf16 h = __float2bfloat16(acc);
            Chi[(size_t)row * N + gc] = h;
            Clo[(size_t)row * N + gc] = __float2bfloat16(acc - __bfloat162float(h));
        }
    }
#endif
}

// ---------------- fused head2: one CTA owns all N=400 columns ----------------
// A row r = gelu(U[sn]+V[dn]+b1), K=800.  Two TMEM accumulators (cols 0-199 /
// 200-399, idesc N=200).  A double-buffered; B split into two N-half buffers
// with PER-HALF mbarriers so B loads overlap MMA of the other half.
// Epilogue: gelu(.+b2) dot W3 + b3 -> pred directly.
#define H2_HDR 8192
#define H2_ASTAGE 32768                 // A hi 16KB + lo 16KB
#define H2_BHALF 51200                  // one N-half: hi 25.6KB + lo 25.6KB
#define H2_BBASE (H2_HDR + 2 * H2_ASTAGE)
#define H2_SMEM (H2_BBASE + 2 * H2_BHALF)   // 176128

__global__ __launch_bounds__(256, 1) void head2_kernel(
    const float* __restrict__ U, const float* __restrict__ V,
    const bf16* __restrict__ Bhi, const bf16* __restrict__ Blo,   // h2t [400][800]
    const float* __restrict__ b1, const float* __restrict__ b2,
    const float* __restrict__ w3, const float* __restrict__ b3,
    const int* __restrict__ src0, const int* __restrict__ dst0,
    float* __restrict__ pred)
{
#if HAS_TC
    extern __shared__ char dsm[];
    const int tid = threadIdx.x;
    const int wid = tid >> 5;
    const uint32_t sb = smem_u32(dsm);
    const int mBase = blockIdx.x * 128;
    const int K = PAIRD;                  // 800
    const int NC = 13;
    int* sSrc = (int*)(dsm + 64);
    int* sDst = (int*)(dsm + 576);
    float* sw3 = (float*)(dsm + 1152);    // 1200 floats
    const uint32_t mbB0 = sb + 16, mbB1 = sb + 24;

    if (tid == 0) { MBARRIER_INIT(mbB0, 1); MBARRIER_INIT(mbB1, 1); }
    if (wid == 0) TCGEN05_ALLOC(sb, 512);
    if (tid < 128) {
        int r = mBase + tid;
        int e = r & (EE - 1), b = r >> 14;
        sSrc[tid] = (b << 10) + src0[e];
        sDst[tid] = (b << 10) + dst0[e];
    }
    for (int i = tid; i < 1200; i += 256) sw3[i] = w3[i];
    __syncthreads();
    uint32_t tmem;
    asm volatile("ld.shared.b32 %0, [%1];" : "=r"(tmem) : "r"(sb));

    const uint32_t idesc = (1u << 4) | (1u << 7) | (1u << 10) | (25u << 17) | (8u << 24); // N=200

    for (int c = 0; c < NC; c++) {
        int k0 = c << 6;
        char* astg = dsm + H2_HDR + (c & 1) * H2_ASTAGE;
        // A stage (c&1) free once chunk c-2 fully consumed (its h1 commit on mbB1)
        if (c >= 2) MBARRIER_WAIT_PARITY(mbB1, (c - 2) & 1);
        // ---- A-gen: gelu(U[sn]+V[dn]+b1), hi/lo split ----
#pragma unroll
        for (int i = 0; i < 4; i++) {
            int idx = i * 256 + tid;
            int row = idx >> 3, seg = idx & 7;
            int col = k0 + seg * 8;
            if (col < K) {
                int sn = sSrc[row], dn = sDst[row];
                const float* up = U + (size_t)sn * PAIRD + col;
                const float* vp = V + (size_t)dn * PAIRD + col;
                float4 u0 = *(const float4*)up, u1 = *(const float4*)(up + 4);
                float4 v0 = *(const float4*)vp, v1 = *(const float4*)(vp + 4);
                float4 b0 = *(const float4*)(b1 + col);
                float4 b1v = *(const float4*)(b1 + col + 4);
                float r8[8];
                r8[0] = gelu_tanh(u0.x + v0.x + b0.x);
                r8[1] = gelu_tanh(u0.y + v0.y + b0.y);
                r8[2] = gelu_tanh(u0.z + v0.z + b0.z);
                r8[3] = gelu_tanh(u0.w + v0.w + b0.w);
                r8[4] = gelu_tanh(u1.x + v1.x + b1v.x);
                r8[5] = gelu_tanh(u1.y + v1.y + b1v.y);
                r8[6] = gelu_tanh(u1.z + v1.z + b1v.z);
                r8[7] = gelu_tanh(u1.w + v1.w + b1v.w);
                uint32_t hw[4], lw[4];
#pragma unroll
                for (int q = 0; q < 4; q++) {
                    bf16 h0 = __float2bfloat16(r8[q*2+0]);
                    bf16 h1 = __float2bfloat16(r8[q*2+1]);
                    bf16 l0 = __float2bfloat16(r8[q*2+0] - __bfloat162float(h0));
                    bf16 l1 = __float2bfloat16(r8[q*2+1] - __bfloat162float(h1));
                    hw[q] = ((uint32_t)__bfloat16_as_ushort(h1) << 16) | __bfloat16_as_ushort(h0);
                    lw[q] = ((uint32_t)__bfloat16_as_ushort(l1) << 16) | __bfloat16_as_ushort(l0);
                }
                uint32_t sw = SW128(row * 128 + seg * 16);
                *(uint4*)(astg + sw) = make_uint4(hw[0], hw[1], hw[2], hw[3]);
                *(uint4*)(astg + 16384 + sw) = make_uint4(lw[0], lw[1], lw[2], lw[3]);
            }
        }
        // ---- B half 0 (rows 0..199): free when MMA(c-1, h0) done ----
        if (c >= 1) MBARRIER_WAIT_PARITY(mbB0, (c - 1) & 1);
        {
            char* bstg = dsm + H2_BBASE;
#pragma unroll 1
            for (int i = 0; i < 7; i++) {
                int idx = i * 256 + tid;
                if (idx < 1600) {
                    int row = idx >> 3, seg = idx & 7;
                    int col = k0 + seg * 8;
                    if (col < K) {
                        size_t off = (size_t)row * K + col;
                        uint4 vh = *(const uint4*)(Bhi + off);
                        uint4 vl = *(const uint4*)(Blo + off);
                        uint32_t sw = SW128(row * 128 + seg * 16);
                        *(uint4*)(bstg + sw) = vh;
                        *(uint4*)(bstg + 25600 + sw) = vl;
                    }
                }
            }
        }
        asm volatile("fence.proxy.async.shared::cta;" ::: "memory");
        __syncthreads();
        // ---- MMA half 0 (overlaps the B1 load below) ----
        int ksteps = min(4, (K - k0) >> 4);
        if (wid == 0 && elect1()) {
            uint32_t ag = sb + H2_HDR + (c & 1) * H2_ASTAGE;
            uint64_t dAh = mk_desc(ag);
            uint64_t dAl = mk_desc(ag + 16384);
            uint32_t bg = sb + H2_BBASE;
            uint64_t dBh = mk_desc(bg);
            uint64_t dBl = mk_desc(bg + 25600);
            for (int ks = 0; ks < ksteps; ks++) {
                uint64_t o = (uint64_t)(ks * 2);
                mma_bf16_ss(tmem, dAh + o, dBh + o, idesc, (c | ks) ? 1u : 0u);
                mma_bf16_ss(tmem, dAh + o, dBl + o, idesc, 1u);
                mma_bf16_ss(tmem, dAl + o, dBh + o, idesc, 1u);
            }
            TCGEN05_COMMIT(mbB0);
        }
        // ---- B half 1 (rows 200..399): free when MMA(c-1, h1) done ----
        if (c >= 1) MBARRIER_WAIT_PARITY(mbB1, (c - 1) & 1);
        {
            char* bstg = dsm + H2_BBASE + H2_BHALF;
#pragma unroll 1
            for (int i = 0; i < 7; i++) {
                int idx = i * 256 + tid;
                if (idx < 1600) {
                    int row = idx >> 3, seg = idx & 7;
                    int col = k0 + seg * 8;
                    if (col < K) {
                        size_t off = (size_t)(200 + row) * K + col;
                        uint4 vh = *(const uint4*)(Bhi + off);
                        uint4 vl = *(const uint4*)(Blo + off);
                        uint32_t sw = SW128(row * 128 + seg * 16);
                        *(uint4*)(bstg + sw) = vh;
                        *(uint4*)(bstg + 25600 + sw) = vl;
                    }
                }
            }
        }
        asm volatile("fence.proxy.async.shared::cta;" ::: "memory");
        __syncthreads();
        // ---- MMA half 1 (overlaps next chunk's A-gen / B0 load) ----
        if (wid == 0 && elect1()) {
            uint32_t ag = sb + H2_HDR + (c & 1) * H2_ASTAGE;
            uint64_t dAh = mk_desc(ag);
            uint64_t dAl = mk_desc(ag + 16384);
            uint32_t bg = sb + H2_BBASE + H2_BHALF;
            uint64_t dBh = mk_desc(bg);
            uint64_t dBl = mk_desc(bg + 25600);
            uint32_t d = tmem + 200;
            for (int ks = 0; ks < ksteps; ks++) {
                uint64_t o = (uint64_t)(ks * 2);
                mma_bf16_ss(d, dAh + o, dBh + o, idesc, (c | ks) ? 1u : 0u);
                mma_bf16_ss(d, dAh + o, dBl + o, idesc, 1u);
                mma_bf16_ss(d, dAl + o, dBh + o, idesc, 1u);
            }
            TCGEN05_COMMIT(mbB1);
        }
    }
    // all MMAs done: commit #12 (parity 0) on both barriers
    MBARRIER_WAIT_PARITY(mbB0, (NC - 1) & 1);
    MBARRIER_WAIT_PARITY(mbB1, (NC - 1) & 1);
    TCGEN05_FENCE_AFTER();

    // ---- epilogue: gelu(.+b2) dot W3 -> pred ----
    {
        int sub = wid & 3, cg = wid >> 2;
        int lane = tid & 31;
        float* cst = (float*)(dsm + H2_HDR);
        float d0 = 0.f, d1 = 0.f, d2 = 0.f;
        for (int cb0 = 0; cb0 < 400; cb0 += 64) {
            int cb = cb0 + cg * 32;
            if (cb < 400) {
                uint32_t regs[32];
                TCGEN05_LD_32X32B_X32(regs, tmem + cb);
                TCGEN05_WAIT_LD();
                int r = sub * 32 + lane;
#pragma unroll
                for (int j = 0; j < 32; j++) {
                    int col = cb + j;
                    if (col < 400) {
                        float v = __uint_as_float(regs[j]) + b2[col];
                        v = gelu_tanh(v);
                        cst[r * CPITCH + (cg * 32 + j)] = v;
                    }
                }
            }
            __syncthreads();
            int cw = min(64, 400 - cb0);
            if (tid < 128) {
                for (int col = 0; col < cw; col++) {
                    float v = cst[tid * CPITCH + col];
                    int wc = (cb0 + col) * 3;
                    d0 += v * sw3[wc + 0];
                    d1 += v * sw3[wc + 1];
                    d2 += v * sw3[wc + 2];
                }
            }
            __syncthreads();
        }
        if (tid < 128) {
            size_t r = (size_t)(mBase + tid);
            pred[r * 3 + 0] = d0 + b3[0];
            pred[r * 3 + 1] = d1 + b3[1];
            pred[r * 3 + 2] = d2 + b3[2];
        }
    }
    __syncthreads();
    if (wid == 0) TCGEN05_DEALLOC(tmem, 512);

#else // !HAS_TC — naive correct fallback (compile-only)
    const int tid = threadIdx.x;
    const int mBase = blockIdx.x * 128;
    if (tid >= 128) return;
    int row = mBase + tid;
    int e = row & (EE - 1), b = row >> 14;
    int sn = (b << 10) + src0[e];
    int dn = (b << 10) + dst0[e];
    float d0 = 0.f, d1 = 0.f, d2 = 0.f;
    for (int col = 0; col < 400; col++) {
        float acc = 0.f;
        for (int k = 0; k < PAIRD; k++) {
            float a = gelu_tanh(U[(size_t)sn * PAIRD + k] + V[(size_t)dn * PAIRD + k] + b1[k]);
            size_t bo = (size_t)col * PAIRD + k;
            float bb = __bfloat162float(Bhi[bo]) + __bfloat162float(Blo[bo]);
            acc += a * bb;
        }
        acc = gelu_tanh(acc + b2[col]);
        d0 += acc * w3[col * 3 + 0];
        d1 += acc * w3[col * 3 + 1];
        d2 += acc * w3[col * 3 + 2];
    }
    pred[(size_t)row * 3 + 0] = d0 + b3[0];
    pred[(size_t)row * 3 + 1] = d1 + b3[1];
    pred[(size_t)row * 3 + 2] = d2 + b3[2];
#endif
}

// ---------------- attention scores ----------------
__global__ void attn_score_kernel(const float* __restrict__ wh,
                                  const float* __restrict__ att_src,
                                  const float* __restrict__ att_dst,
                                  float* __restrict__ as_, float* __restrict__ ad_)
{
    int bn = blockIdx.x;
    int h = threadIdx.x >> 5, lane = threadIdx.x & 31;
    const float* w = wh + (size_t)bn * OUTD + h * 200;
    float s = 0.f, d = 0.f;
    for (int f = lane; f < 200; f += 32) {
        float v = w[f];
        s += v * att_src[h * 200 + f];
        d += v * att_dst[h * 200 + f];
    }
#pragma unroll
    for (int o = 16; o; o >>= 1) {
        s += __shfl_down_sync(0xffffffffu, s, o);
        d += __shfl_down_sync(0xffffffffu, d, o);
    }
    if (lane == 0) { as_[bn * 2 + h] = s; ad_[bn * 2 + h] = d; }
}

// ---------------- CSR build ----------------
__global__ void zero_counts_kernel(int* counts) { counts[threadIdx.x] = 0; }

__global__ void count_kernel(const int* __restrict__ edges, int* __restrict__ counts) {
    int et = blockIdx.x * 256 + threadIdx.x;
    if (et >= ETOT) return;
    int dst = (et < EE) ? edges[EE + et] : (et - EE);
    atomicAdd(&counts[dst], 1);
}

__global__ void scan_kernel(const int* __restrict__ counts, int* __restrict__ rowstart,
                            int* __restrict__ fill) {
    __shared__ int s[NN];
    int t = threadIdx.x;
    int c = counts[t];
    s[t] = c;
    __syncthreads();
    for (int o = 1; o < NN; o <<= 1) {
        int v = (t >= o) ? s[t - o] : 0;
        __syncthreads();
        s[t] += v;
        __syncthreads();
    }
    rowstart[t + 1] = s[t];
    if (t == 0) rowstart[0] = 0;
    fill[t] = s[t] - c;
}

__global__ void scatter_kernel(const int* __restrict__ edges, int* __restrict__ fill,
                               int* __restrict__ csrsrc) {
    int et = blockIdx.x * 256 + threadIdx.x;
    if (et >= ETOT) return;
    int src = (et < EE) ? edges[et] : (et - EE);
    int dst = (et < EE) ? edges[EE + et] : (et - EE);
    int pos = atomicAdd(&fill[dst], 1);
    csrsrc[pos] = src;
}

// ---------------- GAT softmax + aggregation + residual ----------------
#define CHUNK 256
__global__ void gat_kernel(const float* __restrict__ wh, const float* __restrict__ as_,
                           const float* __restrict__ ad_, const float* __restrict__ enc,
                           const float* __restrict__ gat_b,
                           const int* __restrict__ rowstart, const int* __restrict__ csrsrc,
                           float* __restrict__ feat, bf16* __restrict__ feat_hi,
                           bf16* __restrict__ feat_lo)
{
    __shared__ float red0[256], red1[256];
    __shared__ int   s_src[CHUNK];
    __shared__ float s_c0[CHUNK], s_c1[CHUNK];
    __shared__ float sh_m0, sh_m1, sh_z0, sh_z1;

    int bn = blockIdx.x;
    int b = bn >> 10, n = bn & 1023;
    int tid = threadIdx.x;
    int start = rowstart[n];
    int deg = rowstart[n + 1] - start;

    float ad0 = ad_[bn * 2 + 0], ad1 = ad_[bn * 2 + 1];

    float m0 = -1e30f, m1 = -1e30f;
    for (int i = tid; i < deg; i += 256) {
        int s = csrsrc[start + i];
        int sb2 = (b << 10) + s;
        float e0 = as_[sb2 * 2 + 0] + ad0; e0 = (e0 > 0.f) ? e0 : 0.2f * e0;
        float e1 = as_[sb2 * 2 + 1] + ad1; e1 = (e1 > 0.f) ? e1 : 0.2f * e1;
        m0 = fmaxf(m0, e0); m1 = fmaxf(m1, e1);
    }
    red0[tid] = m0; red1[tid] = m1;
    __syncthreads();
    for (int o = 128; o; o >>= 1) {
        if (tid < o) {
            red0[tid] = fmaxf(red0[tid], red0[tid + o]);
            red1[tid] = fmaxf(red1[tid], red1[tid + o]);
        }
        __syncthreads();
    }
    if (tid == 0) { sh_m0 = red0[0]; sh_m1 = red1[0]; }
    __syncthreads();
    m0 = sh_m0; m1 = sh_m1;
    __syncthreads();

    float z0 = 0.f, z1 = 0.f;
    for (int i = tid; i < deg; i += 256) {
        int s = csrsrc[start + i];
        int sb2 = (b << 10) + s;
        float e0 = as_[sb2 * 2 + 0] + ad0; e0 = (e0 > 0.f) ? e0 : 0.2f * e0;
        float e1 = as_[sb2 * 2 + 1] + ad1; e1 = (e1 > 0.f) ? e1 : 0.2f * e1;
        z0 += expf(e0 - m0);
        z1 += expf(e1 - m1);
    }
    red0[tid] = z0; red1[tid] = z1;
    __syncthreads();
    for (int o = 128; o; o >>= 1) {
        if (tid < o) { red0[tid] += red0[tid + o]; red1[tid] += red1[tid + o]; }
        __syncthreads();
    }
    if (tid == 0) { sh_z0 = red0[0]; sh_z1 = red1[0]; }
    __syncthreads();
    z0 = sh_z0; z1 = sh_z1;
    float inv0 = 1.f / z0, inv1 = 1.f / z1;

    float acc0 = 0.f, acc1 = 0.f;
    for (int c0 = 0; c0 < deg; c0 += CHUNK) {
        int cn = min(CHUNK, deg - c0);
        __syncthreads();
        if (tid < cn) {
            int s = csrsrc[start + c0 + tid];
            int sb2 = (b << 10) + s;
            float e0 = as_[sb2 * 2 + 0] + ad0; e0 = (e0 > 0.f) ? e0 : 0.2f * e0;
            float e1 = as_[sb2 * 2 + 1] + ad1; e1 = (e1 > 0.f) ? e1 : 0.2f * e1;
            s_src[tid] = sb2;
            s_c0[tid] = expf(e0 - m0) * inv0;
            s_c1[tid] = expf(e1 - m1) * inv1;
        }
        __syncthreads();
        for (int i = 0; i < cn; i++) {
            const float* whrow = wh + (size_t)s_src[i] * OUTD;
            float coef = (tid < 200) ? s_c0[i] : s_c1[i];
            acc0 += coef * whrow[tid];
            if (tid < OUTD - 256) acc1 += s_c1[i] * whrow[tid + 256];
        }
    }

    size_t base = (size_t)bn * OUTD;
    {
        float v = enc[base + tid] + acc0 + gat_b[tid];
        feat[base + tid] = v;
        bf16 h = __float2bfloat16(v);
        feat_hi[base + tid] = h;
        feat_lo[base + tid] = __float2bfloat16(v - __bfloat162float(h));
    }
    if (tid < OUTD - 256) {
        float v = enc[base + tid + 256] + acc1 + gat_b[tid + 256];
        feat[base + tid + 256] = v;
        bf16 h = __float2bfloat16(v);
        feat_hi[base + tid + 256] = h;
        feat_lo[base + tid + 256] = __float2bfloat16(v - __bfloat162float(h));
    }
}

// ---------------- launch ----------------
extern "C" void kernel_launch(void* const* d_in, const int* in_sizes, int n_in,
                              void* d_out, int out_size)
{
    const float* X       = (const float*)d_in[0];
    const int*   edges   = (const int*)  d_in[1];
    const float* enc_w1  = (const float*)d_in[2];
    const float* enc_b1  = (const float*)d_in[3];
    const float* enc_w2  = (const float*)d_in[4];
    const float* enc_b2  = (const float*)d_in[5];
    const float* gat_w   = (const float*)d_in[6];
    const float* att_src = (const float*)d_in[7];
    const float* att_dst = (const float*)d_in[8];
    const float* gat_b   = (const float*)d_in[9];
    const float* h_w1    = (const float*)d_in[10];
    const float* h_b1    = (const float*)d_in[11];
    const float* h_w2    = (const float*)d_in[12];
    const float* h_b2    = (const float*)d_in[13];
    const float* h_w3    = (const float*)d_in[14];
    const float* h_b3    = (const float*)d_in[15];

    float* out  = (float*)d_out;
    float* feat = out;
    float* pred = out + FEAT_ELEMS;

    bf16 *Xhi, *Xlo, *hid_hi, *hid_lo, *enc_hi, *enc_lo, *feat_hi, *feat_lo;
    bf16 *w1t_hi, *w1t_lo, *w2t_hi, *w2t_lo, *wgt_hi, *wgt_lo;
    bf16 *w1a_hi, *w1a_lo, *w1b_hi, *w1b_lo, *h2t_hi, *h2t_lo;
    float *enc, *wh, *as_, *ad_, *U, *V;
    int *counts, *rowstart, *fill, *csrsrc;
    cudaGetSymbolAddress((void**)&Xhi, g_Xhi);       cudaGetSymbolAddress((void**)&Xlo, g_Xlo);
    cudaGetSymbolAddress((void**)&hid_hi, g_hid_hi); cudaGetSymbolAddress((void**)&hid_lo, g_hid_lo);
    cudaGetSymbolAddress((void**)&enc, g_enc);
    cudaGetSymbolAddress((void**)&enc_hi, g_enc_hi); cudaGetSymbolAddress((void**)&enc_lo, g_enc_lo);
    cudaGetSymbolAddress((void**)&wh, g_wh);
    cudaGetSymbolAddress((void**)&feat_hi, g_feat_hi); cudaGetSymbolAddress((void**)&feat_lo, g_feat_lo);
    cudaGetSymbolAddress((void**)&U, g_U);           cudaGetSymbolAddress((void**)&V, g_V);
    cudaGetSymbolAddress((void**)&w1t_hi, g_w1t_hi); cudaGetSymbolAddress((void**)&w1t_lo, g_w1t_lo);
    cudaGetSymbolAddress((void**)&w2t_hi, g_w2t_hi); cudaGetSymbolAddress((void**)&w2t_lo, g_w2t_lo);
    cudaGetSymbolAddress((void**)&wgt_hi, g_wgt_hi); cudaGetSymbolAddress((void**)&wgt_lo, g_wgt_lo);
    cudaGetSymbolAddress((void**)&w1a_hi, g_w1a_hi); cudaGetSymbolAddress((void**)&w1a_lo, g_w1a_lo);
    cudaGetSymbolAddress((void**)&w1b_hi, g_w1b_hi); cudaGetSymbolAddress((void**)&w1b_lo, g_w1b_lo);
    cudaGetSymbolAddress((void**)&h2t_hi, g_h2t_hi); cudaGetSymbolAddress((void**)&h2t_lo, g_h2t_lo);
    cudaGetSymbolAddress((void**)&as_, g_as);        cudaGetSymbolAddress((void**)&ad_, g_ad);
    cudaGetSymbolAddress((void**)&counts, g_counts); cudaGetSymbolAddress((void**)&rowstart, g_rowstart);
    cudaGetSymbolAddress((void**)&fill, g_fill);     cudaGetSymbolAddress((void**)&csrsrc, g_csrsrc);

    const int* src0 = edges;
    const int* dst0 = edges + EE;

    cudaFuncSetAttribute(mm_kernel<true ,true ,false,true >, cudaFuncAttributeMaxDynamicSharedMemorySize, SMEM_TOTAL_MM);
    cudaFuncSetAttribute(mm_kernel<true ,false,true ,true >, cudaFuncAttributeMaxDynamicSharedMemorySize, SMEM_TOTAL_MM);
    cudaFuncSetAttribute(mm_kernel<false,false,true ,false>, cudaFuncAttributeMaxDynamicSharedMemorySize, SMEM_TOTAL_MM);
    cudaFuncSetAttribute(head2_kernel, cudaFuncAttributeMaxDynamicSharedMemorySize, H2_SMEM);

    // ---- prep: split X, transpose+split weights ----
    {
        size_t nX = (size_t)BNR * IND;
        split_kernel<<<(unsigned)((nX + 255) / 256), 256>>>(X, Xhi, Xlo, nX);
        tsplit_kernel<<<(IND * HIDD + 255) / 256, 256>>>(enc_w1, w1t_hi, w1t_lo, IND, HIDD, 0, HIDD);
        tsplit_kernel<<<(HIDD * OUTD + 255) / 256, 256>>>(enc_w2, w2t_hi, w2t_lo, HIDD, OUTD, 0, OUTD);
        tsplit_kernel<<<(OUTD * OUTD + 255) / 256, 256>>>(gat_w, wgt_hi, wgt_lo, OUTD, OUTD, 0, OUTD);
        tsplit_kernel<<<(OUTD * PAIRD + 255) / 256, 256>>>(h_w1, w1a_hi, w1a_lo, OUTD, PAIRD, 0, PAIRD);
        tsplit_kernel<<<(OUTD * PAIRD + 255) / 256, 256>>>(h_w1, w1b_hi, w1b_lo, OUTD, PAIRD, OUTD, PAIRD);
        tsplit_kernel<<<(PAIRD * (PAIRD/2) + 255) / 256, 256>>>(h_w2, h2t_hi, h2t_lo, PAIRD, PAIRD/2, 0, PAIRD/2);
    }

    // 1) enc1: [32768,768] -> [32768,512], GELU, write hid hi/lo
    mm_kernel<true,true,false,true><<<dim3(2, BNR/128), 256, SMEM_TOTAL_MM>>>(
        Xhi, Xlo, w1t_hi, w1t_lo, enc_b1, nullptr, hid_hi, hid_lo, HIDD, IND);
    // 2) enc2: [32768,512] -> [32768,400], write enc f32 + hi/lo
    mm_kernel<true,false,true,true><<<dim3(2, BNR/128), 256, SMEM_TOTAL_MM>>>(
        hid_hi, hid_lo, w2t_hi, w2t_lo, enc_b2, enc, enc_hi, enc_lo, OUTD, HIDD);
    // 3) wh = enc @ gat_w
    mm_kernel<false,false,true,false><<<dim3(2, BNR/128), 256, SMEM_TOTAL_MM>>>(
        enc_hi, enc_lo, wgt_hi, wgt_lo, nullptr, wh, nullptr, nullptr, OUTD, OUTD);
    // 4) attention scores
    attn_score_kernel<<<BNR, 64>>>(wh, att_src, att_dst, as_, ad_);
    // 5) CSR build
    zero_counts_kernel<<<1, NN>>>(counts);
    count_kernel<<<(ETOT + 255) / 256, 256>>>(edges, counts);
    scan_kernel<<<1, NN>>>(counts, rowstart, fill);
    scatter_kernel<<<(ETOT + 255) / 256, 256>>>(edges, fill, csrsrc);
    // 6) GAT aggregate + residual -> feat (output) + feat hi/lo
    gat_kernel<<<BNR, 256>>>(wh, as_, ad_, enc, gat_b, rowstart, csrsrc, feat, feat_hi, feat_lo);
    // 7a) U = feat @ W1top: [32768,400] x [400,800]
    mm_kernel<false,false,true,false><<<dim3(4, BNR/128), 256, SMEM_TOTAL_MM>>>(
        feat_hi, feat_lo, w1a_hi, w1a_lo, nullptr, U, nullptr, nullptr, PAIRD, OUTD);
    // 7b) V = feat @ W1bot
    mm_kernel<false,false,true,false><<<dim3(4, BNR/128), 256, SMEM_TOTAL_MM>>>(
        feat_hi, feat_lo, w1b_hi, w1b_lo, nullptr, V, nullptr, nullptr, PAIRD, OUTD);
    // 8) head2 fused single-pass, per-half pipelined B
    head2_kernel<<<BER / 128, 256, H2_SMEM>>>(
        U, V, h2t_hi, h2t_lo, h_b1, h_b2, h_w3, h_b3, src0, dst0, pred);
}

// round 11
// speedup vs baseline: 1.1513x; 1.1513x over previous
#include <cuda_runtime.h>
#include <cuda_bf16.h>
#include <math.h>
#include <stdint.h>
#include <stddef.h>

// Problem constants
#define BB 32
#define NN 1024
#define EE 16384
#define ETOT (EE + NN)
#define IND 768
#define HIDD 512
#define OUTD 400
#define PAIRD 800
#define BNR (BB * NN)          // 32768
#define BER (BB * EE)          // 524288
#define FEAT_ELEMS ((size_t)BNR * OUTD)

typedef __nv_bfloat16 bf16;

#if defined(__CUDA_ARCH_FEAT_SM103_ALL) || defined(__CUDA_ARCH_FEAT_SM100_ALL) || defined(__CUDA_ARCH_FEAT_SM101_ALL)
#define HAS_TC 1
#else
#define HAS_TC 0
#endif

// ---------------- device scratch ----------------
__device__ bf16  g_Xhi[(size_t)BNR * IND];
__device__ bf16  g_Xlo[(size_t)BNR * IND];
__device__ bf16  g_hid_hi[(size_t)BNR * HIDD];
__device__ bf16  g_hid_lo[(size_t)BNR * HIDD];
__device__ float g_enc[(size_t)BNR * OUTD];
__device__ bf16  g_enc_hi[(size_t)BNR * OUTD];
__device__ bf16  g_enc_lo[(size_t)BNR * OUTD];
__device__ float g_wh[(size_t)BNR * OUTD];
__device__ bf16  g_feat_hi[(size_t)BNR * OUTD];
__device__ bf16  g_feat_lo[(size_t)BNR * OUTD];
__device__ float g_U[(size_t)BNR * PAIRD];        // feat @ W1top [32768,800]
__device__ float g_V[(size_t)BNR * PAIRD];        // feat @ W1bot
// transposed/split weights [N][K]
__device__ bf16  g_w1t_hi[HIDD * IND],  g_w1t_lo[HIDD * IND];
__device__ bf16  g_w2t_hi[OUTD * HIDD], g_w2t_lo[OUTD * HIDD];
__device__ bf16  g_wgt_hi[OUTD * OUTD], g_wgt_lo[OUTD * OUTD];
__device__ bf16  g_w1a_hi[PAIRD * OUTD], g_w1a_lo[PAIRD * OUTD];   // W1top^T [800,400]
__device__ bf16  g_w1b_hi[PAIRD * OUTD], g_w1b_lo[PAIRD * OUTD];   // W1bot^T
__device__ bf16  g_h2t_hi[(PAIRD/2) * PAIRD], g_h2t_lo[(PAIRD/2) * PAIRD];
__device__ float g_as[BNR * 2], g_ad[BNR * 2];
__device__ int   g_counts[NN], g_rowstart[NN + 1], g_fill[NN], g_csrsrc[ETOT];

// tanhf lowers to the HW MUFU.TANH path on sm_103a — measured faster than the
// __expf-based sigmoid form (round-8 isolation test).
__device__ __forceinline__ float gelu_tanh(float x) {
    const float c = 0.7978845608028654f;
    float x3 = x * x * x;
    return 0.5f * x * (1.0f + tanhf(c * (x + 0.044715f * x3)));
}

// ---------------- PTX helpers ----------------
__device__ __forceinline__ uint32_t smem_u32(const void* p) {
    uint32_t a;
    asm("{ .reg .u64 t; cvta.to.shared.u64 t, %1; cvt.u32.u64 %0, t; }" : "=r"(a) : "l"(p));
    return a;
}
__device__ __forceinline__ uint32_t elect1() {
    uint32_t r;
    asm volatile("{\n\t.reg .pred p;\n\telect.sync _|p, 0xFFFFFFFF;\n\tselp.b32 %0, 1, 0, p;\n\t}" : "=r"(r));
    return r;
}
#define SW128(o) ((o) ^ (((o) >> 3) & 0x70))
#define SW64(o)  ((o) ^ (((o) >> 3) & 0x30))

__device__ __forceinline__ uint64_t mk_desc(uint32_t addr) {
    const uint64_t base = (uint64_t(2) << 61) | (uint64_t(1) << 46) |
                          (uint64_t(64) << 32) | (uint64_t(1) << 16);
    return base | ((uint64_t)(addr >> 4) & 0x3FFF);
}
__device__ __forceinline__ uint64_t mk_desc64(uint32_t addr) {
    const uint64_t base = (uint64_t(4) << 61) | (uint64_t(1) << 46) |
                          (uint64_t(32) << 32) | (uint64_t(1) << 16);
    return base | ((uint64_t)(addr >> 4) & 0x3FFF);
}

__device__ __forceinline__ void cp16(uint32_t saddr, const void* g) {
    asm volatile("cp.async.cg.shared.global [%0], [%1], 16;" :: "r"(saddr), "l"(g));
}
#define CP_COMMIT() asm volatile("cp.async.commit_group;" ::: "memory")
#define CP_WAIT(n)  asm volatile("cp.async.wait_group %0;" :: "n"(n) : "memory")

#define MBARRIER_INIT(addr, cnt) \
    asm volatile("mbarrier.init.shared.b64 [%0], %1;" :: "r"((uint32_t)(addr)), "r"((uint32_t)(cnt)) : "memory")

#define MBARRIER_WAIT_PARITY(addr, parity) do { \
    uint32_t _mbar = (uint32_t)(addr); \
    uint32_t _par = (uint32_t)(parity); \
    uint32_t _done; \
    asm volatile("{\n\t.reg .pred p;\n\t" \
        "mbarrier.try_wait.parity.acquire.cta.shared::cta.b64 p, [%1], %2;\n\t" \
        "selp.b32 %0, 1, 0, p;\n\t}" : "=r"(_done) : "r"(_mbar), "r"(_par) : "memory"); \
    if (!_done) { \
        asm volatile("{\n\t.reg .pred P1;\n\t" \
            "WAIT_LOOP_%=:\n\t" \
            "mbarrier.try_wait.parity.acquire.cta.shared::cta.b64 P1, [%0], %1, 0x989680;\n\t" \
            "@P1 bra.uni WAIT_DONE_%=;\n\t" \
            "bra.uni WAIT_LOOP_%=;\n\t" \
            "WAIT_DONE_%=:\n\t}" :: "r"(_mbar), "r"(_par) : "memory"); \
    } \
} while (0)

#if HAS_TC
#define TCGEN05_ALLOC(smem_addr, nCols) \
    asm volatile("tcgen05.alloc.cta_group::1.sync.aligned.shared::cta.b32 [%0], %1;" \
        :: "r"((uint32_t)(smem_addr)), "r"((uint32_t)(nCols)) : "memory")
#define TCGEN05_DEALLOC(tmem, nCols) \
    asm volatile("tcgen05.dealloc.cta_group::1.sync.aligned.b32 %0, %1;" :: "r"(tmem), "r"((uint32_t)(nCols)))
#define TCGEN05_COMMIT(mbar) \
    asm volatile("tcgen05.commit.cta_group::1.mbarrier::arrive::one.shared::cluster.b64 [%0];" \
        :: "r"((uint32_t)(mbar)) : "memory")
#define TCGEN05_FENCE_AFTER() asm volatile("tcgen05.fence::after_thread_sync;" ::: "memory")
#define TCGEN05_WAIT_LD() asm volatile("tcgen05.wait::ld.sync.aligned;" ::: "memory")

#define TCGEN05_LD_32X32B_X32(r, tmem_addr) \
    asm volatile( \
        "tcgen05.ld.sync.aligned.32x32b.x32.b32 " \
        "{%0, %1, %2, %3, %4, %5, %6, %7, " \
        " %8, %9, %10, %11, %12, %13, %14, %15, " \
        " %16, %17, %18, %19, %20, %21, %22, %23, " \
        " %24, %25, %26, %27, %28, %29, %30, %31}, [%32];" \
        : "=r"((r)[0]),  "=r"((r)[1]),  "=r"((r)[2]),  "=r"((r)[3]), \
          "=r"((r)[4]),  "=r"((r)[5]),  "=r"((r)[6]),  "=r"((r)[7]), \
          "=r"((r)[8]),  "=r"((r)[9]),  "=r"((r)[10]), "=r"((r)[11]), \
          "=r"((r)[12]), "=r"((r)[13]), "=r"((r)[14]), "=r"((r)[15]), \
          "=r"((r)[16]), "=r"((r)[17]), "=r"((r)[18]), "=r"((r)[19]), \
          "=r"((r)[20]), "=r"((r)[21]), "=r"((r)[22]), "=r"((r)[23]), \
          "=r"((r)[24]), "=r"((r)[25]), "=r"((r)[26]), "=r"((r)[27]), \
          "=r"((r)[28]), "=r"((r)[29]), "=r"((r)[30]), "=r"((r)[31]) \
        : "r"(tmem_addr))

__device__ __forceinline__ void mma_bf16_ss(uint32_t d, uint64_t ad, uint64_t bd,
                                            uint32_t idesc, uint32_t en) {
    asm volatile(
        "{\n\t.reg .pred p;\n\tsetp.ne.u32 p, %5, 0;\n\t"
        "tcgen05.mma.cta_group::1.kind::f16 [%0], %1, %2, %3, {%4, %4, %4, %4}, p;\n\t}"
        :: "r"(d), "l"(ad), "l"(bd), "r"(idesc), "r"(0u), "r"(en) : "memory");
}
#endif // HAS_TC

// ---------------- prep kernels ----------------
__global__ void split_kernel(const float* __restrict__ in, bf16* __restrict__ hi,
                             bf16* __restrict__ lo, size_t n) {
    size_t i = (size_t)blockIdx.x * 256 + threadIdx.x;
    if (i < n) {
        float v = in[i];
        bf16 h = __float2bfloat16(v);
        hi[i] = h;
        lo[i] = __float2bfloat16(v - __bfloat162float(h));
    }
}
// out[n*Kw+k] = W[(rowOff+k)*ldW + n]  (transpose + split)
__global__ void tsplit_kernel(const float* __restrict__ W, bf16* __restrict__ hi,
                              bf16* __restrict__ lo, int Kw, int Nw, int rowOff, int ldW) {
    int i = blockIdx.x * 256 + threadIdx.x;
    if (i < Kw * Nw) {
        int n = i / Kw, k = i - n * Kw;
        float v = W[(size_t)(rowOff + k) * ldW + n];
        bf16 h = __float2bfloat16(v);
        hi[i] = h;
        lo[i] = __float2bfloat16(v - __bfloat162float(h));
    }
}

// ---------------- split-bf16 tcgen05 GEMM, BM=128, BN<=256, BK=64 ----------------
#define MMK_STAGES 2
#define STAGE_BYTES 98304        // A hi/lo 32KB + B hi/lo 64KB
#define HDR_BYTES 8192
#define SMEM_TOTAL_MM (HDR_BYTES + MMK_STAGES * STAGE_BYTES)
#define CPITCH 65

template<bool BIAS, bool GELU_, bool WF32, bool WHILO>
__global__ __launch_bounds__(256, 1) void mm_kernel(
    const bf16* __restrict__ Ahi, const bf16* __restrict__ Alo,
    const bf16* __restrict__ Bhi, const bf16* __restrict__ Blo,
    const float* __restrict__ bias,
    float* __restrict__ Cf, bf16* __restrict__ Chi, bf16* __restrict__ Clo,
    int N, int K)
{
#if HAS_TC
    extern __shared__ char dsm[];
    const int tid = threadIdx.x;
    const int wid = tid >> 5;
    const uint32_t sb = smem_u32(dsm);
    const int mBase = blockIdx.y * 128;
    const int nBase = blockIdx.x * 256;
    const int nValid = min(256, N - nBase);

    if (tid == 0) {
        for (int s = 0; s < MMK_STAGES; s++) MBARRIER_INIT(sb + 16 + s * 8, 1);
    }
    if (wid == 0) TCGEN05_ALLOC(sb, 256);
    __syncthreads();
    uint32_t tmem;
    asm volatile("ld.shared.b32 %0, [%1];" : "=r"(tmem) : "r"(sb));

    const uint32_t idesc = (1u << 4) | (1u << 7) | (1u << 10) |
                           ((uint32_t)(nValid >> 3) << 17) | (8u << 24);
    const int NC = (K + 63) >> 6;

    for (int c = 0; c < NC; c++) {
        int s = c & 1;
        if (c >= MMK_STAGES) {
            MBARRIER_WAIT_PARITY(sb + 16 + s * 8, ((c >> 1) - 1) & 1);
        }
        char* stg = dsm + HDR_BYTES + s * STAGE_BYTES;
        int k0 = c << 6;
        // ---- A planes (128 x 64) ----
#pragma unroll
        for (int i = 0; i < 4; i++) {
            int idx = i * 256 + tid;
            int row = idx >> 3, seg = idx & 7;
            int col = k0 + seg * 8;
            if (col < K) {
                size_t off = (size_t)(mBase + row) * K + col;
                uint4 vh = *(const uint4*)(Ahi + off);
                uint4 vl = *(const uint4*)(Alo + off);
                uint32_t sw = SW128(row * 128 + seg * 16);
                *(uint4*)(stg + sw) = vh;
                *(uint4*)(stg + 16384 + sw) = vl;
            }
        }
        // ---- B planes (nValid x 64) ----
#pragma unroll
        for (int i = 0; i < 8; i++) {
            int idx = i * 256 + tid;
            int row = idx >> 3, seg = idx & 7;
            int col = k0 + seg * 8;
            if (row < nValid && col < K) {
                size_t off = (size_t)(nBase + row) * K + col;
                uint4 vh = *(const uint4*)(Bhi + off);
                uint4 vl = *(const uint4*)(Blo + off);
                uint32_t sw = SW128(row * 128 + seg * 16);
                *(uint4*)(stg + 32768 + sw) = vh;
                *(uint4*)(stg + 65536 + sw) = vl;
            }
        }
        asm volatile("fence.proxy.async.shared::cta;" ::: "memory");
        __syncthreads();
        if (wid == 0 && elect1()) {
            uint32_t sg = sb + HDR_BYTES + s * STAGE_BYTES;
            uint64_t dAh = mk_desc(sg);
            uint64_t dAl = mk_desc(sg + 16384);
            uint64_t dBh = mk_desc(sg + 32768);
            uint64_t dBl = mk_desc(sg + 65536);
            int ksteps = min(4, (K - k0 + 15) >> 4);
            for (int ks = 0; ks < ksteps; ks++) {
                uint64_t o = (uint64_t)(ks * 2);
                mma_bf16_ss(tmem, dAh + o, dBh + o, idesc, (c | ks) ? 1u : 0u);
                mma_bf16_ss(tmem, dAh + o, dBl + o, idesc, 1u);
                mma_bf16_ss(tmem, dAl + o, dBh + o, idesc, 1u);
            }
            TCGEN05_COMMIT(sb + 16 + s * 8);
        }
    }
    {
        int lc = NC - 1;
        MBARRIER_WAIT_PARITY(sb + 16 + (lc & 1) * 8, (lc >> 1) & 1);
    }
    TCGEN05_FENCE_AFTER();

    // ---- epilogue ----
    {
        int sub = wid & 3, cg = wid >> 2;
        int lane = tid & 31;
        float* cst = (float*)(dsm + HDR_BYTES);
        for (int cb0 = 0; cb0 < nValid; cb0 += 64) {
            int cb = cb0 + cg * 32;
            if (cb < nValid) {
                uint32_t regs[32];
                TCGEN05_LD_32X32B_X32(regs, tmem + cb);
                TCGEN05_WAIT_LD();
                int r = sub * 32 + lane;
#pragma unroll
                for (int j = 0; j < 32; j++) {
                    int col = cb + j;
                    if (col < nValid) {
                        float v = __uint_as_float(regs[j]);
                        if (BIAS) v += bias[nBase + col];
                        if (GELU_) v = gelu_tanh(v);
                        cst[r * CPITCH + (cg * 32 + j)] = v;
                    }
                }
            }
            __syncthreads();
            int cw = min(64, nValid - cb0);
            for (int i = tid; i < 128 * cw; i += 256) {
                int row = i / cw, col = i - row * cw;
                float v = cst[row * CPITCH + col];
                size_t gr = (size_t)(mBase + row);
                int gc = nBase + cb0 + col;
                if (WF32) Cf[gr * N + gc] = v;
                if (WHILO) {
                    bf16 h = __float2bfloat16(v);
                    Chi[gr * N + gc] = h;
                    Clo[gr * N + gc] = __float2bfloat16(v - __bfloat162float(h));
                }
            }
            __syncthreads();
        }
    }
    __syncthreads();
    if (wid == 0) TCGEN05_DEALLOC(tmem, 256);

#else // !HAS_TC — naive correct fallback (compile-only for non-'a' PTX pass)
    const int tid = threadIdx.x;
    const int mBase = blockIdx.y * 128;
    const int nBase = blockIdx.x * 256;
    const int nValid = min(256, N - nBase);
    if (tid >= 128) return;
    int row = mBase + tid;
    for (int col = 0; col < nValid; col++) {
        int gc = nBase + col;
        float acc = 0.f;
        for (int k = 0; k < K; k++) {
            size_t off = (size_t)row * K + k;
            float a = __bfloat162float(Ahi[off]) + __bfloat162float(Alo[off]);
            size_t bo = (size_t)gc * K + k;
            float bb = __bfloat162float(Bhi[bo]) + __bfloat162float(Blo[bo]);
            acc += a * bb;
        }
        if (BIAS) acc += bias[gc];
        if (GELU_) acc = gelu_tanh(acc);
        if (WF32) Cf[(size_t)row * N + gc] = acc;
        if (WHILO) {
            bf16 h = __float2bfloat16(acc);
            Chi[(size_t)row * N + gc] = h;
            Clo[(size_t)row * N + gc] = __float2bfloat16(acc - __bfloat162float(h));
        }
    }
#endif
}

// ---------------- fused head2 (BK=32, SW64, cp.async pipelined) ----------------
// A row r = gelu(U[sn]+V[dn]+b1), K=800, 25 chunks of 32.
// 4 A-stages (16KB, manual STS gen), 3 B-stages (51.2KB, cp.async depth-2).
// Two TMEM accumulators (N=200 each). Commit mbar[c&3]; A reuse waits
// commit(c-4), B reuse waits commit(c-3). Epilogue: gelu(.+b2) dot W3 -> pred.
#define H2_HDR   12288
#define H2_ASTG  16384
#define H2_BSTG  51200
#define H2_ABASE H2_HDR
#define H2_BBASE (H2_HDR + 4 * H2_ASTG)
#define H2_SMEM  (H2_BBASE + 3 * H2_BSTG)    // 231424

__global__ __launch_bounds__(256, 1) void head2_kernel(
    const float* __restrict__ U, const float* __restrict__ V,
    const bf16* __restrict__ Bhi, const bf16* __restrict__ Blo,   // h2t [400][800]
    const float* __restrict__ b1, const float* __restrict__ b2,
    const float* __restrict__ w3, const float* __restrict__ b3,
    const int* __restrict__ src0, const int* __restrict__ dst0,
    float* __restrict__ pred)
{
#if HAS_TC
    extern __shared__ char dsm[];
    const int tid = threadIdx.x;
    const int wid = tid >> 5;
    const uint32_t sb = smem_u32(dsm);
    const int mBase = blockIdx.x * 128;
    const int NC = 25;
    int* sSrc = (int*)(dsm + 64);
    int* sDst = (int*)(dsm + 576);
    float* sw3 = (float*)(dsm + 1152);    // 1200 floats
    float* b1s = (float*)(dsm + 5952);    // 800 floats
    float* b2s = (float*)(dsm + 9152);    // 400 floats

    if (tid == 0) {
        for (int i = 0; i < 4; i++) MBARRIER_INIT(sb + 16 + i * 8, 1);
    }
    if (wid == 0) TCGEN05_ALLOC(sb, 512);
    if (tid < 128) {
        int r = mBase + tid;
        int e = r & (EE - 1), b = r >> 14;
        sSrc[tid] = (b << 10) + src0[e];
        sDst[tid] = (b << 10) + dst0[e];
    }
    for (int i = tid; i < 1200; i += 256) sw3[i] = w3[i];
    for (int i = tid; i < 800; i += 256) b1s[i] = b1[i];
    for (int i = tid; i < 400; i += 256) b2s[i] = b2[i];
    __syncthreads();
    uint32_t tmem;
    asm volatile("ld.shared.b32 %0, [%1];" : "=r"(tmem) : "r"(sb));

    const uint32_t idesc = (1u << 4) | (1u << 7) | (1u << 10) | (25u << 17) | (8u << 24); // N=200

    auto wait_commit = [&](int j) {
        MBARRIER_WAIT_PARITY(sb + 16 + (j & 3) * 8, (j >> 2) & 1);
    };
    auto prep = [&](int cc) {
        int k0 = cc * 32;
        // A stage (cc&3): reused from chunk cc-4
        if (cc >= 4) wait_commit(cc - 4);
        char* astg = dsm + H2_ABASE + (cc & 3) * H2_ASTG;
#pragma unroll
        for (int i = 0; i < 2; i++) {
            int idx = i * 256 + tid;
            int row = idx >> 2, seg = idx & 3;
            int col = k0 + seg * 8;
            int sn = sSrc[row], dn = sDst[row];
            const float* up = U + (size_t)sn * PAIRD + col;
            const float* vp = V + (size_t)dn * PAIRD + col;
            float4 u0 = *(const float4*)up, u1 = *(const float4*)(up + 4);
            float4 v0 = *(const float4*)vp, v1 = *(const float4*)(vp + 4);
            float4 c0 = *(const float4*)(b1s + col);
            float4 c1 = *(const float4*)(b1s + col + 4);
            float r8[8];
            r8[0] = gelu_tanh(u0.x + v0.x + c0.x);
            r8[1] = gelu_tanh(u0.y + v0.y + c0.y);
            r8[2] = gelu_tanh(u0.z + v0.z + c0.z);
            r8[3] = gelu_tanh(u0.w + v0.w + c0.w);
            r8[4] = gelu_tanh(u1.x + v1.x + c1.x);
            r8[5] = gelu_tanh(u1.y + v1.y + c1.y);
            r8[6] = gelu_tanh(u1.z + v1.z + c1.z);
            r8[7] = gelu_tanh(u1.w + v1.w + c1.w);
            uint32_t hw[4], lw[4];
#pragma unroll
            for (int q = 0; q < 4; q++) {
                bf16 h0 = __float2bfloat16(r8[q*2+0]);
                bf16 h1 = __float2bfloat16(r8[q*2+1]);
                bf16 l0 = __float2bfloat16(r8[q*2+0] - __bfloat162float(h0));
                bf16 l1 = __float2bfloat16(r8[q*2+1] - __bfloat162float(h1));
                hw[q] = ((uint32_t)__bfloat16_as_ushort(h1) << 16) | __bfloat16_as_ushort(h0);
                lw[q] = ((uint32_t)__bfloat16_as_ushort(l1) << 16) | __bfloat16_as_ushort(l0);
            }
            uint32_t sw = SW64(row * 64 + seg * 16);
            *(uint4*)(astg + sw) = make_uint4(hw[0], hw[1], hw[2], hw[3]);
            *(uint4*)(astg + 8192 + sw) = make_uint4(lw[0], lw[1], lw[2], lw[3]);
        }
        // B stage (cc%3): reused from chunk cc-3
        if (cc >= 3) wait_commit(cc - 3);
        uint32_t bstg = sb + H2_BBASE + (cc % 3) * H2_BSTG;
#pragma unroll 1
        for (int i = 0; i < 13; i++) {
            int idx = i * 256 + tid;
            if (idx < 3200) {
                int plane = idx >= 1600;
                int j = idx - plane * 1600;
                int row = j >> 2, seg = j & 3;
                const bf16* g = (plane ? Blo : Bhi) + (size_t)row * PAIRD + k0 + seg * 8;
                cp16(bstg + plane * 25600 + SW64(row * 64 + seg * 16), g);
            }
        }
        CP_COMMIT();
    };

    prep(0);
    prep(1);
    for (int c = 0; c < NC; c++) {
        if (c + 2 < NC) prep(c + 2);
        if (c + 2 < NC) { CP_WAIT(2); }
        else if (c + 1 < NC) { CP_WAIT(1); }
        else { CP_WAIT(0); }
        asm volatile("fence.proxy.async.shared::cta;" ::: "memory");
        __syncthreads();
        if (wid == 0 && elect1()) {
            uint32_t ag = sb + H2_ABASE + (c & 3) * H2_ASTG;
            uint64_t dAh = mk_desc64(ag);
            uint64_t dAl = mk_desc64(ag + 8192);
            uint32_t bg = sb + H2_BBASE + (c % 3) * H2_BSTG;
#pragma unroll
            for (int half = 0; half < 2; half++) {
                uint64_t dBh = mk_desc64(bg + half * 12800);
                uint64_t dBl = mk_desc64(bg + 25600 + half * 12800);
                uint32_t d = tmem + half * 200;
#pragma unroll
                for (int ks = 0; ks < 2; ks++) {
                    uint64_t o = (uint64_t)(ks * 2);
                    mma_bf16_ss(d, dAh + o, dBh + o, idesc, (c | ks) ? 1u : 0u);
                    mma_bf16_ss(d, dAh + o, dBl + o, idesc, 1u);
                    mma_bf16_ss(d, dAl + o, dBh + o, idesc, 1u);
                }
            }
            TCGEN05_COMMIT(sb + 16 + (c & 3) * 8);
        }
    }
    wait_commit(NC - 1);
    TCGEN05_FENCE_AFTER();

    // ---- epilogue: gelu(.+b2) dot W3 -> pred ----
    {
        int sub = wid & 3, cg = wid >> 2;
        int lane = tid & 31;
        float* cst = (float*)(dsm + H2_HDR);
        float d0 = 0.f, d1 = 0.f, d2 = 0.f;
        for (int cb0 = 0; cb0 < 400; cb0 += 64) {
            int cb = cb0 + cg * 32;
            if (cb < 400) {
                uint32_t regs[32];
                TCGEN05_LD_32X32B_X32(regs, tmem + cb);
                TCGEN05_WAIT_LD();
                int r = sub * 32 + lane;
#pragma unroll
                for (int j = 0; j < 32; j++) {
                    int col = cb + j;
                    if (col < 400) {
                        float v = __uint_as_float(regs[j]) + b2s[col];
                        v = gelu_tanh(v);
                        cst[r * CPITCH + (cg * 32 + j)] = v;
                    }
                }
            }
            __syncthreads();
            int cw = min(64, 400 - cb0);
            if (tid < 128) {
                for (int col = 0; col < cw; col++) {
                    float v = cst[tid * CPITCH + col];
                    int wc = (cb0 + col) * 3;
                    d0 += v * sw3[wc + 0];
                    d1 += v * sw3[wc + 1];
                    d2 += v * sw3[wc + 2];
                }
            }
            __syncthreads();
        }
        if (tid < 128) {
            size_t r = (size_t)(mBase + tid);
            pred[r * 3 + 0] = d0 + b3[0];
            pred[r * 3 + 1] = d1 + b3[1];
            pred[r * 3 + 2] = d2 + b3[2];
        }
    }
    __syncthreads();
    if (wid == 0) TCGEN05_DEALLOC(tmem, 512);

#else // !HAS_TC — naive correct fallback (compile-only)
    const int tid = threadIdx.x;
    const int mBase = blockIdx.x * 128;
    if (tid >= 128) return;
    int row = mBase + tid;
    int e = row & (EE - 1), b = row >> 14;
    int sn = (b << 10) + src0[e];
    int dn = (b << 10) + dst0[e];
    float d0 = 0.f, d1 = 0.f, d2 = 0.f;
    for (int col = 0; col < 400; col++) {
        float acc = 0.f;
        for (int k = 0; k < PAIRD; k++) {
            float a = gelu_tanh(U[(size_t)sn * PAIRD + k] + V[(size_t)dn * PAIRD + k] + b1[k]);
            size_t bo = (size_t)col * PAIRD + k;
            float bb = __bfloat162float(Bhi[bo]) + __bfloat162float(Blo[bo]);
            acc += a * bb;
        }
        acc = gelu_tanh(acc + b2[col]);
        d0 += acc * w3[col * 3 + 0];
        d1 += acc * w3[col * 3 + 1];
        d2 += acc * w3[col * 3 + 2];
    }
    pred[(size_t)row * 3 + 0] = d0 + b3[0];
    pred[(size_t)row * 3 + 1] = d1 + b3[1];
    pred[(size_t)row * 3 + 2] = d2 + b3[2];
#endif
}

// ---------------- attention scores ----------------
__global__ void attn_score_kernel(const float* __restrict__ wh,
                                  const float* __restrict__ att_src,
                                  const float* __restrict__ att_dst,
                                  float* __restrict__ as_, float* __restrict__ ad_)
{
    int bn = blockIdx.x;
    int h = threadIdx.x >> 5, lane = threadIdx.x & 31;
    const float* w = wh + (size_t)bn * OUTD + h * 200;
    float s = 0.f, d = 0.f;
    for (int f = lane; f < 200; f += 32) {
        float v = w[f];
        s += v * att_src[h * 200 + f];
        d += v * att_dst[h * 200 + f];
    }
#pragma unroll
    for (int o = 16; o; o >>= 1) {
        s += __shfl_down_sync(0xffffffffu, s, o);
        d += __shfl_down_sync(0xffffffffu, d, o);
    }
    if (lane == 0) { as_[bn * 2 + h] = s; ad_[bn * 2 + h] = d; }
}

// ---------------- CSR build ----------------
__global__ void zero_counts_kernel(int* counts) { counts[threadIdx.x] = 0; }

__global__ void count_kernel(const int* __restrict__ edges, int* __restrict__ counts) {
    int et = blockIdx.x * 256 + threadIdx.x;
    if (et >= ETOT) return;
    int dst = (et < EE) ? edges[EE + et] : (et - EE);
    atomicAdd(&counts[dst], 1);
}

__global__ void scan_kernel(const int* __restrict__ counts, int* __restrict__ rowstart,
                            int* __restrict__ fill) {
    __shared__ int s[NN];
    int t = threadIdx.x;
    int c = counts[t];
    s[t] = c;
    __syncthreads();
    for (int o = 1; o < NN; o <<= 1) {
        int v = (t >= o) ? s[t - o] : 0;
        __syncthreads();
        s[t] += v;
        __syncthreads();
    }
    rowstart[t + 1] = s[t];
    if (t == 0) rowstart[0] = 0;
    fill[t] = s[t] - c;
}

__global__ void scatter_kernel(const int* __restrict__ edges, int* __restrict__ fill,
                               int* __restrict__ csrsrc) {
    int et = blockIdx.x * 256 + threadIdx.x;
    if (et >= ETOT) return;
    int src = (et < EE) ? edges[et] : (et - EE);
    int dst = (et < EE) ? edges[EE + et] : (et - EE);
    int pos = atomicAdd(&fill[dst], 1);
    csrsrc[pos] = src;
}

// ---------------- GAT softmax + aggregation + residual ----------------
#define CHUNK 256
__global__ void gat_kernel(const float* __restrict__ wh, const float* __restrict__ as_,
                           const float* __restrict__ ad_, const float* __restrict__ enc,
                           const float* __restrict__ gat_b,
                           const int* __restrict__ rowstart, const int* __restrict__ csrsrc,
                           float* __restrict__ feat, bf16* __restrict__ feat_hi,
                           bf16* __restrict__ feat_lo)
{
    __shared__ float red0[256], red1[256];
    __shared__ int   s_src[CHUNK];
    __shared__ float s_c0[CHUNK], s_c1[CHUNK];
    __shared__ float sh_m0, sh_m1, sh_z0, sh_z1;

    int bn = blockIdx.x;
    int b = bn >> 10, n = bn & 1023;
    int tid = threadIdx.x;
    int start = rowstart[n];
    int deg = rowstart[n + 1] - start;

    float ad0 = ad_[bn * 2 + 0], ad1 = ad_[bn * 2 + 1];

    float m0 = -1e30f, m1 = -1e30f;
    for (int i = tid; i < deg; i += 256) {
        int s = csrsrc[start + i];
        int sb2 = (b << 10) + s;
        float e0 = as_[sb2 * 2 + 0] + ad0; e0 = (e0 > 0.f) ? e0 : 0.2f * e0;
        float e1 = as_[sb2 * 2 + 1] + ad1; e1 = (e1 > 0.f) ? e1 : 0.2f * e1;
        m0 = fmaxf(m0, e0); m1 = fmaxf(m1, e1);
    }
    red0[tid] = m0; red1[tid] = m1;
    __syncthreads();
    for (int o = 128; o; o >>= 1) {
        if (tid < o) {
            red0[tid] = fmaxf(red0[tid], red0[tid + o]);
            red1[tid] = fmaxf(red1[tid], red1[tid + o]);
        }
        __syncthreads();
    }
    if (tid == 0) { sh_m0 = red0[0]; sh_m1 = red1[0]; }
    __syncthreads();
    m0 = sh_m0; m1 = sh_m1;
    __syncthreads();

    float z0 = 0.f, z1 = 0.f;
    for (int i = tid; i < deg; i += 256) {
        int s = csrsrc[start + i];
        int sb2 = (b << 10) + s;
        float e0 = as_[sb2 * 2 + 0] + ad0; e0 = (e0 > 0.f) ? e0 : 0.2f * e0;
        float e1 = as_[sb2 * 2 + 1] + ad1; e1 = (e1 > 0.f) ? e1 : 0.2f * e1;
        z0 += expf(e0 - m0);
        z1 += expf(e1 - m1);
    }
    red0[tid] = z0; red1[tid] = z1;
    __syncthreads();
    for (int o = 128; o; o >>= 1) {
        if (tid < o) { red0[tid] += red0[tid + o]; red1[tid] += red1[tid + o]; }
        __syncthreads();
    }
    if (tid == 0) { sh_z0 = red0[0]; sh_z1 = red1[0]; }
    __syncthreads();
    z0 = sh_z0; z1 = sh_z1;
    float inv0 = 1.f / z0, inv1 = 1.f / z1;

    float acc0 = 0.f, acc1 = 0.f;
    for (int c0 = 0; c0 < deg; c0 += CHUNK) {
        int cn = min(CHUNK, deg - c0);
        __syncthreads();
        if (tid < cn) {
            int s = csrsrc[start + c0 + tid];
            int sb2 = (b << 10) + s;
            float e0 = as_[sb2 * 2 + 0] + ad0; e0 = (e0 > 0.f) ? e0 : 0.2f * e0;
            float e1 = as_[sb2 * 2 + 1] + ad1; e1 = (e1 > 0.f) ? e1 : 0.2f * e1;
            s_src[tid] = sb2;
            s_c0[tid] = expf(e0 - m0) * inv0;
            s_c1[tid] = expf(e1 - m1) * inv1;
        }
        __syncthreads();
        for (int i = 0; i < cn; i++) {
            const float* whrow = wh + (size_t)s_src[i] * OUTD;
            float coef = (tid < 200) ? s_c0[i] : s_c1[i];
            acc0 += coef * whrow[tid];
            if (tid < OUTD - 256) acc1 += s_c1[i] * whrow[tid + 256];
        }
    }

    size_t base = (size_t)bn * OUTD;
    {
        float v = enc[base + tid] + acc0 + gat_b[tid];
        feat[base + tid] = v;
        bf16 h = __float2bfloat16(v);
        feat_hi[base + tid] = h;
        feat_lo[base + tid] = __float2bfloat16(v - __bfloat162float(h));
    }
    if (tid < OUTD - 256) {
        float v = enc[base + tid + 256] + acc1 + gat_b[tid + 256];
        feat[base + tid + 256] = v;
        bf16 h = __float2bfloat16(v);
        feat_hi[base + tid + 256] = h;
        feat_lo[base + tid + 256] = __float2bfloat16(v - __bfloat162float(h));
    }
}

// ---------------- launch ----------------
extern "C" void kernel_launch(void* const* d_in, const int* in_sizes, int n_in,
                              void* d_out, int out_size)
{
    const float* X       = (const float*)d_in[0];
    const int*   edges   = (const int*)  d_in[1];
    const float* enc_w1  = (const float*)d_in[2];
    const float* enc_b1  = (const float*)d_in[3];
    const float* enc_w2  = (const float*)d_in[4];
    const float* enc_b2  = (const float*)d_in[5];
    const float* gat_w   = (const float*)d_in[6];
    const float* att_src = (const float*)d_in[7];
    const float* att_dst = (const float*)d_in[8];
    const float* gat_b   = (const float*)d_in[9];
    const float* h_w1    = (const float*)d_in[10];
    const float* h_b1    = (const float*)d_in[11];
    const float* h_w2    = (const float*)d_in[12];
    const float* h_b2    = (const float*)d_in[13];
    const float* h_w3    = (const float*)d_in[14];
    const float* h_b3    = (const float*)d_in[15];

    float* out  = (float*)d_out;
    float* feat = out;
    float* pred = out + FEAT_ELEMS;

    bf16 *Xhi, *Xlo, *hid_hi, *hid_lo, *enc_hi, *enc_lo, *feat_hi, *feat_lo;
    bf16 *w1t_hi, *w1t_lo, *w2t_hi, *w2t_lo, *wgt_hi, *wgt_lo;
    bf16 *w1a_hi, *w1a_lo, *w1b_hi, *w1b_lo, *h2t_hi, *h2t_lo;
    float *enc, *wh, *as_, *ad_, *U, *V;
    int *counts, *rowstart, *fill, *csrsrc;
    cudaGetSymbolAddress((void**)&Xhi, g_Xhi);       cudaGetSymbolAddress((void**)&Xlo, g_Xlo);
    cudaGetSymbolAddress((void**)&hid_hi, g_hid_hi); cudaGetSymbolAddress((void**)&hid_lo, g_hid_lo);
    cudaGetSymbolAddress((void**)&enc, g_enc);
    cudaGetSymbolAddress((void**)&enc_hi, g_enc_hi); cudaGetSymbolAddress((void**)&enc_lo, g_enc_lo);
    cudaGetSymbolAddress((void**)&wh, g_wh);
    cudaGetSymbolAddress((void**)&feat_hi, g_feat_hi); cudaGetSymbolAddress((void**)&feat_lo, g_feat_lo);
    cudaGetSymbolAddress((void**)&U, g_U);           cudaGetSymbolAddress((void**)&V, g_V);
    cudaGetSymbolAddress((void**)&w1t_hi, g_w1t_hi); cudaGetSymbolAddress((void**)&w1t_lo, g_w1t_lo);
    cudaGetSymbolAddress((void**)&w2t_hi, g_w2t_hi); cudaGetSymbolAddress((void**)&w2t_lo, g_w2t_lo);
    cudaGetSymbolAddress((void**)&wgt_hi, g_wgt_hi); cudaGetSymbolAddress((void**)&wgt_lo, g_wgt_lo);
    cudaGetSymbolAddress((void**)&w1a_hi, g_w1a_hi); cudaGetSymbolAddress((void**)&w1a_lo, g_w1a_lo);
    cudaGetSymbolAddress((void**)&w1b_hi, g_w1b_hi); cudaGetSymbolAddress((void**)&w1b_lo, g_w1b_lo);
    cudaGetSymbolAddress((void**)&h2t_hi, g_h2t_hi); cudaGetSymbolAddress((void**)&h2t_lo, g_h2t_lo);
    cudaGetSymbolAddress((void**)&as_, g_as);        cudaGetSymbolAddress((void**)&ad_, g_ad);
    cudaGetSymbolAddress((void**)&counts, g_counts); cudaGetSymbolAddress((void**)&rowstart, g_rowstart);
    cudaGetSymbolAddress((void**)&fill, g_fill);     cudaGetSymbolAddress((void**)&csrsrc, g_csrsrc);

    const int* src0 = edges;
    const int* dst0 = edges + EE;

    cudaFuncSetAttribute(mm_kernel<true ,true ,false,true >, cudaFuncAttributeMaxDynamicSharedMemorySize, SMEM_TOTAL_MM);
    cudaFuncSetAttribute(mm_kernel<true ,false,true ,true >, cudaFuncAttributeMaxDynamicSharedMemorySize, SMEM_TOTAL_MM);
    cudaFuncSetAttribute(mm_kernel<false,false,true ,false>, cudaFuncAttributeMaxDynamicSharedMemorySize, SMEM_TOTAL_MM);
    cudaFuncSetAttribute(head2_kernel, cudaFuncAttributeMaxDynamicSharedMemorySize, H2_SMEM);

    // ---- prep: split X, transpose+split weights ----
    {
        size_t nX = (size_t)BNR * IND;
        split_kernel<<<(unsigned)((nX + 255) / 256), 256>>>(X, Xhi, Xlo, nX);
        tsplit_kernel<<<(IND * HIDD + 255) / 256, 256>>>(enc_w1, w1t_hi, w1t_lo, IND, HIDD, 0, HIDD);
        tsplit_kernel<<<(HIDD * OUTD + 255) / 256, 256>>>(enc_w2, w2t_hi, w2t_lo, HIDD, OUTD, 0, OUTD);
        tsplit_kernel<<<(OUTD * OUTD + 255) / 256, 256>>>(gat_w, wgt_hi, wgt_lo, OUTD, OUTD, 0, OUTD);
        tsplit_kernel<<<(OUTD * PAIRD + 255) / 256, 256>>>(h_w1, w1a_hi, w1a_lo, OUTD, PAIRD, 0, PAIRD);
        tsplit_kernel<<<(OUTD * PAIRD + 255) / 256, 256>>>(h_w1, w1b_hi, w1b_lo, OUTD, PAIRD, OUTD, PAIRD);
        tsplit_kernel<<<(PAIRD * (PAIRD/2) + 255) / 256, 256>>>(h_w2, h2t_hi, h2t_lo, PAIRD, PAIRD/2, 0, PAIRD/2);
    }

    // 1) enc1: [32768,768] -> [32768,512], GELU, write hid hi/lo
    mm_kernel<true,true,false,true><<<dim3(2, BNR/128), 256, SMEM_TOTAL_MM>>>(
        Xhi, Xlo, w1t_hi, w1t_lo, enc_b1, nullptr, hid_hi, hid_lo, HIDD, IND);
    // 2) enc2: [32768,512] -> [32768,400], write enc f32 + hi/lo
    mm_kernel<true,false,true,true><<<dim3(2, BNR/128), 256, SMEM_TOTAL_MM>>>(
        hid_hi, hid_lo, w2t_hi, w2t_lo, enc_b2, enc, enc_hi, enc_lo, OUTD, HIDD);
    // 3) wh = enc @ gat_w
    mm_kernel<false,false,true,false><<<dim3(2, BNR/128), 256, SMEM_TOTAL_MM>>>(
        enc_hi, enc_lo, wgt_hi, wgt_lo, nullptr, wh, nullptr, nullptr, OUTD, OUTD);
    // 4) attention scores
    attn_score_kernel<<<BNR, 64>>>(wh, att_src, att_dst, as_, ad_);
    // 5) CSR build
    zero_counts_kernel<<<1, NN>>>(counts);
    count_kernel<<<(ETOT + 255) / 256, 256>>>(edges, counts);
    scan_kernel<<<1, NN>>>(counts, rowstart, fill);
    scatter_kernel<<<(ETOT + 255) / 256, 256>>>(edges, fill, csrsrc);
    // 6) GAT aggregate + residual -> feat (output) + feat hi/lo
    gat_kernel<<<BNR, 256>>>(wh, as_, ad_, enc, gat_b, rowstart, csrsrc, feat, feat_hi, feat_lo);
    // 7a) U = feat @ W1top: [32768,400] x [400,800]
    mm_kernel<false,false,true,false><<<dim3(4, BNR/128), 256, SMEM_TOTAL_MM>>>(
        feat_hi, feat_lo, w1a_hi, w1a_lo, nullptr, U, nullptr, nullptr, PAIRD, OUTD);
    // 7b) V = feat @ W1bot
    mm_kernel<false,false,true,false><<<dim3(4, BNR/128), 256, SMEM_TOTAL_MM>>>(
        feat_hi, feat_lo, w1b_hi, w1b_lo, nullptr, V, nullptr, nullptr, PAIRD, OUTD);
    // 8) head2: BK=32 SW64 cp.async pipeline, pred written directly
    head2_kernel<<<BER / 128, 256, H2_SMEM>>>(
        U, V, h2t_hi, h2t_lo, h_b1, h_b2, h_w3, h_b3, src0, dst0, pred);
}

// round 12
// speedup vs baseline: 1.2209x; 1.0604x over previous
#include <cuda_runtime.h>
#include <cuda_bf16.h>
#include <math.h>
#include <stdint.h>
#include <stddef.h>

// Problem constants
#define BB 32
#define NN 1024
#define EE 16384
#define ETOT (EE + NN)
#define IND 768
#define HIDD 512
#define OUTD 400
#define PAIRD 800
#define BNR (BB * NN)          // 32768
#define BER (BB * EE)          // 524288
#define FEAT_ELEMS ((size_t)BNR * OUTD)

typedef __nv_bfloat16 bf16;

#if defined(__CUDA_ARCH_FEAT_SM103_ALL) || defined(__CUDA_ARCH_FEAT_SM100_ALL) || defined(__CUDA_ARCH_FEAT_SM101_ALL)
#define HAS_TC 1
#else
#define HAS_TC 0
#endif

// ---------------- device scratch ----------------
__device__ bf16  g_Xhi[(size_t)BNR * IND];
__device__ bf16  g_Xlo[(size_t)BNR * IND];
__device__ bf16  g_hid_hi[(size_t)BNR * HIDD];
__device__ bf16  g_hid_lo[(size_t)BNR * HIDD];
__device__ float g_enc[(size_t)BNR * OUTD];
__device__ bf16  g_enc_hi[(size_t)BNR * OUTD];
__device__ bf16  g_enc_lo[(size_t)BNR * OUTD];
__device__ float g_wh[(size_t)BNR * OUTD];
__device__ bf16  g_feat_hi[(size_t)BNR * OUTD];
__device__ bf16  g_feat_lo[(size_t)BNR * OUTD];
__device__ float g_U[(size_t)BNR * PAIRD];        // feat @ W1top [32768,800]
__device__ float g_V[(size_t)BNR * PAIRD];        // feat @ W1bot
// transposed/split weights [N][K]
__device__ bf16  g_w1t_hi[HIDD * IND],  g_w1t_lo[HIDD * IND];
__device__ bf16  g_w2t_hi[OUTD * HIDD], g_w2t_lo[OUTD * HIDD];
__device__ bf16  g_wgt_hi[OUTD * OUTD], g_wgt_lo[OUTD * OUTD];
__device__ bf16  g_w1a_hi[PAIRD * OUTD], g_w1a_lo[PAIRD * OUTD];   // W1top^T [800,400]
__device__ bf16  g_w1b_hi[PAIRD * OUTD], g_w1b_lo[PAIRD * OUTD];   // W1bot^T
__device__ bf16  g_h2t_hi[(PAIRD/2) * PAIRD], g_h2t_lo[(PAIRD/2) * PAIRD];
__device__ float g_as[BNR * 2], g_ad[BNR * 2];
__device__ int   g_counts[NN], g_rowstart[NN + 1], g_fill[NN], g_csrsrc[ETOT];

// tanhf lowers to the HW MUFU.TANH path on sm_103a (round-8 isolation test).
__device__ __forceinline__ float gelu_tanh(float x) {
    const float c = 0.7978845608028654f;
    float x3 = x * x * x;
    return 0.5f * x * (1.0f + tanhf(c * (x + 0.044715f * x3)));
}

// ---------------- PTX helpers ----------------
__device__ __forceinline__ uint32_t smem_u32(const void* p) {
    uint32_t a;
    asm("{ .reg .u64 t; cvta.to.shared.u64 t, %1; cvt.u32.u64 %0, t; }" : "=r"(a) : "l"(p));
    return a;
}
__device__ __forceinline__ uint32_t elect1() {
    uint32_t r;
    asm volatile("{\n\t.reg .pred p;\n\telect.sync _|p, 0xFFFFFFFF;\n\tselp.b32 %0, 1, 0, p;\n\t}" : "=r"(r));
    return r;
}
#define SW128(o) ((o) ^ (((o) >> 3) & 0x70))
#define SW64(o)  ((o) ^ (((o) >> 3) & 0x30))

__device__ __forceinline__ uint64_t mk_desc64(uint32_t addr) {
    const uint64_t base = (uint64_t(4) << 61) | (uint64_t(1) << 46) |
                          (uint64_t(32) << 32) | (uint64_t(1) << 16);
    return base | ((uint64_t)(addr >> 4) & 0x3FFF);
}

__device__ __forceinline__ void cp16(uint32_t saddr, const void* g) {
    asm volatile("cp.async.cg.shared.global [%0], [%1], 16;" :: "r"(saddr), "l"(g));
}
#define CP_COMMIT() asm volatile("cp.async.commit_group;" ::: "memory")
#define CP_WAIT(n)  asm volatile("cp.async.wait_group %0;" :: "n"(n) : "memory")

#define MBARRIER_INIT(addr, cnt) \
    asm volatile("mbarrier.init.shared.b64 [%0], %1;" :: "r"((uint32_t)(addr)), "r"((uint32_t)(cnt)) : "memory")

#define MBARRIER_WAIT_PARITY(addr, parity) do { \
    uint32_t _mbar = (uint32_t)(addr); \
    uint32_t _par = (uint32_t)(parity); \
    uint32_t _done; \
    asm volatile("{\n\t.reg .pred p;\n\t" \
        "mbarrier.try_wait.parity.acquire.cta.shared::cta.b64 p, [%1], %2;\n\t" \
        "selp.b32 %0, 1, 0, p;\n\t}" : "=r"(_done) : "r"(_mbar), "r"(_par) : "memory"); \
    if (!_done) { \
        asm volatile("{\n\t.reg .pred P1;\n\t" \
            "WAIT_LOOP_%=:\n\t" \
            "mbarrier.try_wait.parity.acquire.cta.shared::cta.b64 P1, [%0], %1, 0x989680;\n\t" \
            "@P1 bra.uni WAIT_DONE_%=;\n\t" \
            "bra.uni WAIT_LOOP_%=;\n\t" \
            "WAIT_DONE_%=:\n\t}" :: "r"(_mbar), "r"(_par) : "memory"); \
    } \
} while (0)

#if HAS_TC
#define TCGEN05_ALLOC(smem_addr, nCols) \
    asm volatile("tcgen05.alloc.cta_group::1.sync.aligned.shared::cta.b32 [%0], %1;" \
        :: "r"((uint32_t)(smem_addr)), "r"((uint32_t)(nCols)) : "memory")
#define TCGEN05_DEALLOC(tmem, nCols) \
    asm volatile("tcgen05.dealloc.cta_group::1.sync.aligned.b32 %0, %1;" :: "r"(tmem), "r"((uint32_t)(nCols)))
#define TCGEN05_COMMIT(mbar) \
    asm volatile("tcgen05.commit.cta_group::1.mbarrier::arrive::one.shared::cluster.b64 [%0];" \
        :: "r"((uint32_t)(mbar)) : "memory")
#define TCGEN05_FENCE_AFTER() asm volatile("tcgen05.fence::after_thread_sync;" ::: "memory")
#define TCGEN05_WAIT_LD() asm volatile("tcgen05.wait::ld.sync.aligned;" ::: "memory")

#define TCGEN05_LD_32X32B_X32(r, tmem_addr) \
    asm volatile( \
        "tcgen05.ld.sync.aligned.32x32b.x32.b32 " \
        "{%0, %1, %2, %3, %4, %5, %6, %7, " \
        " %8, %9, %10, %11, %12, %13, %14, %15, " \
        " %16, %17, %18, %19, %20, %21, %22, %23, " \
        " %24, %25, %26, %27, %28, %29, %30, %31}, [%32];" \
        : "=r"((r)[0]),  "=r"((r)[1]),  "=r"((r)[2]),  "=r"((r)[3]), \
          "=r"((r)[4]),  "=r"((r)[5]),  "=r"((r)[6]),  "=r"((r)[7]), \
          "=r"((r)[8]),  "=r"((r)[9]),  "=r"((r)[10]), "=r"((r)[11]), \
          "=r"((r)[12]), "=r"((r)[13]), "=r"((r)[14]), "=r"((r)[15]), \
          "=r"((r)[16]), "=r"((r)[17]), "=r"((r)[18]), "=r"((r)[19]), \
          "=r"((r)[20]), "=r"((r)[21]), "=r"((r)[22]), "=r"((r)[23]), \
          "=r"((r)[24]), "=r"((r)[25]), "=r"((r)[26]), "=r"((r)[27]), \
          "=r"((r)[28]), "=r"((r)[29]), "=r"((r)[30]), "=r"((r)[31]) \
        : "r"(tmem_addr))

__device__ __forceinline__ void mma_bf16_ss(uint32_t d, uint64_t ad, uint64_t bd,
                                            uint32_t idesc, uint32_t en) {
    asm volatile(
        "{\n\t.reg .pred p;\n\tsetp.ne.u32 p, %5, 0;\n\t"
        "tcgen05.mma.cta_group::1.kind::f16 [%0], %1, %2, %3, {%4, %4, %4, %4}, p;\n\t}"
        :: "r"(d), "l"(ad), "l"(bd), "r"(idesc), "r"(0u), "r"(en) : "memory");
}
#endif // HAS_TC

// ---------------- prep kernels ----------------
__global__ void split_kernel(const float* __restrict__ in, bf16* __restrict__ hi,
                             bf16* __restrict__ lo, size_t n) {
    size_t i = (size_t)blockIdx.x * 256 + threadIdx.x;
    if (i < n) {
        float v = in[i];
        bf16 h = __float2bfloat16(v);
        hi[i] = h;
        lo[i] = __float2bfloat16(v - __bfloat162float(h));
    }
}
// out[n*Kw+k] = W[(rowOff+k)*ldW + n]  (transpose + split)
__global__ void tsplit_kernel(const float* __restrict__ W, bf16* __restrict__ hi,
                              bf16* __restrict__ lo, int Kw, int Nw, int rowOff, int ldW) {
    int i = blockIdx.x * 256 + threadIdx.x;
    if (i < Kw * Nw) {
        int n = i / Kw, k = i - n * Kw;
        float v = W[(size_t)(rowOff + k) * ldW + n];
        bf16 h = __float2bfloat16(v);
        hi[i] = h;
        lo[i] = __float2bfloat16(v - __bfloat162float(h));
    }
}

// ---------------- split-bf16 tcgen05 GEMM, BM=128, BN<=256, BK=32, SW64 ----------------
// cp.async depth-2 pipelined, 4 stages.
#define MM_HDR   8192
#define MM_ASTG  16384                   // A hi 8KB + lo 8KB
#define MM_BSTG  32768                   // B hi 16KB + lo 16KB
#define MM_STG   (MM_ASTG + MM_BSTG)     // 48KB
#define MM_NSTG  4
#define SMEM_TOTAL_MM (MM_HDR + MM_NSTG * MM_STG)   // 204800
#define CPITCH 65

template<bool BIAS, bool GELU_, bool WF32, bool WHILO>
__global__ __launch_bounds__(256, 1) void mm_kernel(
    const bf16* __restrict__ Ahi, const bf16* __restrict__ Alo,
    const bf16* __restrict__ Bhi, const bf16* __restrict__ Blo,
    const float* __restrict__ bias,
    float* __restrict__ Cf, bf16* __restrict__ Chi, bf16* __restrict__ Clo,
    int N, int K)
{
#if HAS_TC
    extern __shared__ char dsm[];
    const int tid = threadIdx.x;
    const int wid = tid >> 5;
    const uint32_t sb = smem_u32(dsm);
    const int mBase = blockIdx.y * 128;
    const int nBase = blockIdx.x * 256;
    const int nValid = min(256, N - nBase);

    if (tid == 0) {
        for (int i = 0; i < 4; i++) MBARRIER_INIT(sb + 16 + i * 8, 1);
    }
    if (wid == 0) TCGEN05_ALLOC(sb, 256);
    __syncthreads();
    uint32_t tmem;
    asm volatile("ld.shared.b32 %0, [%1];" : "=r"(tmem) : "r"(sb));

    const uint32_t idesc = (1u << 4) | (1u << 7) | (1u << 10) |
                           ((uint32_t)(nValid >> 3) << 17) | (8u << 24);
    const int NC = (K + 31) >> 5;

    auto wait_commit = [&](int j) {
        MBARRIER_WAIT_PARITY(sb + 16 + (j & 3) * 8, (j >> 2) & 1);
    };
    auto prep = [&](int cc) {
        int k0 = cc << 5;
        if (cc >= MM_NSTG) wait_commit(cc - MM_NSTG);
        uint32_t stg = sb + MM_HDR + (cc & 3) * MM_STG;
        // A: 128 rows x 32 cols, hi/lo -> 1024 cp16
#pragma unroll
        for (int i = 0; i < 4; i++) {
            int idx = i * 256 + tid;
            int plane = idx >= 512;
            int j = idx - plane * 512;
            int row = j >> 2, seg = j & 3;
            int col = k0 + seg * 8;
            if (col < K) {
                const bf16* g = (plane ? Alo : Ahi) + (size_t)(mBase + row) * K + col;
                cp16(stg + plane * 8192 + SW64(row * 64 + seg * 16), g);
            }
        }
        // B: nValid rows x 32 cols, hi/lo -> up to 2048 cp16
#pragma unroll
        for (int i = 0; i < 8; i++) {
            int idx = i * 256 + tid;
            int plane = idx >= 1024;
            int j = idx - plane * 1024;
            int row = j >> 2, seg = j & 3;
            int col = k0 + seg * 8;
            if (row < nValid && col < K) {
                const bf16* g = (plane ? Blo : Bhi) + (size_t)(nBase + row) * K + col;
                cp16(stg + 16384 + plane * 16384 + SW64(row * 64 + seg * 16), g);
            }
        }
        CP_COMMIT();
    };

    prep(0);
    if (NC > 1) prep(1);
    for (int c = 0; c < NC; c++) {
        if (c + 2 < NC) prep(c + 2);
        if (c + 2 < NC) { CP_WAIT(2); }
        else if (c + 1 < NC) { CP_WAIT(1); }
        else { CP_WAIT(0); }
        asm volatile("fence.proxy.async.shared::cta;" ::: "memory");
        __syncthreads();
        if (wid == 0 && elect1()) {
            uint32_t stg = sb + MM_HDR + (c & 3) * MM_STG;
            uint64_t dAh = mk_desc64(stg);
            uint64_t dAl = mk_desc64(stg + 8192);
            uint64_t dBh = mk_desc64(stg + 16384);
            uint64_t dBl = mk_desc64(stg + 32768);
            int ksteps = min(2, (K - (c << 5)) >> 4);
            for (int ks = 0; ks < ksteps; ks++) {
                uint64_t o = (uint64_t)(ks * 2);
                mma_bf16_ss(tmem, dAh + o, dBh + o, idesc, (c | ks) ? 1u : 0u);
                mma_bf16_ss(tmem, dAh + o, dBl + o, idesc, 1u);
                mma_bf16_ss(tmem, dAl + o, dBh + o, idesc, 1u);
            }
            TCGEN05_COMMIT(sb + 16 + (c & 3) * 8);
        }
    }
    wait_commit(NC - 1);
    TCGEN05_FENCE_AFTER();

    // ---- epilogue ----
    {
        int sub = wid & 3, cg = wid >> 2;
        int lane = tid & 31;
        float* cst = (float*)(dsm + MM_HDR);
        for (int cb0 = 0; cb0 < nValid; cb0 += 64) {
            int cb = cb0 + cg * 32;
            if (cb < nValid) {
                uint32_t regs[32];
                TCGEN05_LD_32X32B_X32(regs, tmem + cb);
                TCGEN05_WAIT_LD();
                int r = sub * 32 + lane;
#pragma unroll
                for (int j = 0; j < 32; j++) {
                    int col = cb + j;
                    if (col < nValid) {
                        float v = __uint_as_float(regs[j]);
                        if (BIAS) v += bias[nBase + col];
                        if (GELU_) v = gelu_tanh(v);
                        cst[r * CPITCH + (cg * 32 + j)] = v;
                    }
                }
            }
            __syncthreads();
            int cw = min(64, nValid - cb0);
            for (int i = tid; i < 128 * cw; i += 256) {
                int row = i / cw, col = i - row * cw;
                float v = cst[row * CPITCH + col];
                size_t gr = (size_t)(mBase + row);
                int gc = nBase + cb0 + col;
                if (WF32) Cf[gr * N + gc] = v;
                if (WHILO) {
                    bf16 h = __float2bfloat16(v);
                    Chi[gr * N + gc] = h;
                    Clo[gr * N + gc] = __float2bfloat16(v - __bfloat162float(h));
                }
            }
            __syncthreads();
        }
    }
    __syncthreads();
    if (wid == 0) TCGEN05_DEALLOC(tmem, 256);

#else // !HAS_TC — naive correct fallback (compile-only for non-'a' PTX pass)
    const int tid = threadIdx.x;
    const int mBase = blockIdx.y * 128;
    const int nBase = blockIdx.x * 256;
    const int nValid = min(256, N - nBase);
    if (tid >= 128) return;
    int row = mBase + tid;
    for (int col = 0; col < nValid; col++) {
        int gc = nBase + col;
        float acc = 0.f;
        for (int k = 0; k < K; k++) {
            size_t off = (size_t)row * K + k;
            float a = __bfloat162float(Ahi[off]) + __bfloat162float(Alo[off]);
            size_t bo = (size_t)gc * K + k;
            float bb = __bfloat162float(Bhi[bo]) + __bfloat162float(Blo[bo]);
            acc += a * bb;
        }
        if (BIAS) acc += bias[gc];
        if (GELU_) acc = gelu_tanh(acc);
        if (WF32) Cf[(size_t)row * N + gc] = acc;
        if (WHILO) {
            bf16 h = __float2bfloat16(acc);
            Chi[(size_t)row * N + gc] = h;
            Clo[(size_t)row * N + gc] = __float2bfloat16(acc - __bfloat162float(h));
        }
    }
#endif
}

// ---------------- fused head2 (BK=32, SW64, cp.async pipelined) ----------------
#define H2_HDR   12288
#define H2_ASTG  16384
#define H2_BSTG  51200
#define H2_ABASE H2_HDR
#define H2_BBASE (H2_HDR + 4 * H2_ASTG)
#define H2_SMEM  (H2_BBASE + 3 * H2_BSTG)    // 231424

__global__ __launch_bounds__(256, 1) void head2_kernel(
    const float* __restrict__ U, const float* __restrict__ V,
    const bf16* __restrict__ Bhi, const bf16* __restrict__ Blo,   // h2t [400][800]
    const float* __restrict__ b1, const float* __restrict__ b2,
    const float* __restrict__ w3, const float* __restrict__ b3,
    const int* __restrict__ src0, const int* __restrict__ dst0,
    float* __restrict__ pred)
{
#if HAS_TC
    extern __shared__ char dsm[];
    const int tid = threadIdx.x;
    const int wid = tid >> 5;
    const uint32_t sb = smem_u32(dsm);
    const int mBase = blockIdx.x * 128;
    const int NC = 25;
    int* sSrc = (int*)(dsm + 64);
    int* sDst = (int*)(dsm + 576);
    float* sw3 = (float*)(dsm + 1152);    // 1200 floats
    float* b1s = (float*)(dsm + 5952);    // 800 floats
    float* b2s = (float*)(dsm + 9152);    // 400 floats

    if (tid == 0) {
        for (int i = 0; i < 4; i++) MBARRIER_INIT(sb + 16 + i * 8, 1);
    }
    if (wid == 0) TCGEN05_ALLOC(sb, 512);
    if (tid < 128) {
        int r = mBase + tid;
        int e = r & (EE - 1), b = r >> 14;
        sSrc[tid] = (b << 10) + src0[e];
        sDst[tid] = (b << 10) + dst0[e];
    }
    for (int i = tid; i < 1200; i += 256) sw3[i] = w3[i];
    for (int i = tid; i < 800; i += 256) b1s[i] = b1[i];
    for (int i = tid; i < 400; i += 256) b2s[i] = b2[i];
    __syncthreads();
    uint32_t tmem;
    asm volatile("ld.shared.b32 %0, [%1];" : "=r"(tmem) : "r"(sb));

    const uint32_t idesc = (1u << 4) | (1u << 7) | (1u << 10) | (25u << 17) | (8u << 24); // N=200

    auto wait_commit = [&](int j) {
        MBARRIER_WAIT_PARITY(sb + 16 + (j & 3) * 8, (j >> 2) & 1);
    };
    auto prep = [&](int cc) {
        int k0 = cc * 32;
        if (cc >= 4) wait_commit(cc - 4);
        char* astg = dsm + H2_ABASE + (cc & 3) * H2_ASTG;
#pragma unroll
        for (int i = 0; i < 2; i++) {
            int idx = i * 256 + tid;
            int row = idx >> 2, seg = idx & 3;
            int col = k0 + seg * 8;
            int sn = sSrc[row], dn = sDst[row];
            const float* up = U + (size_t)sn * PAIRD + col;
            const float* vp = V + (size_t)dn * PAIRD + col;
            float4 u0 = *(const float4*)up, u1 = *(const float4*)(up + 4);
            float4 v0 = *(const float4*)vp, v1 = *(const float4*)(vp + 4);
            float4 c0 = *(const float4*)(b1s + col);
            float4 c1 = *(const float4*)(b1s + col + 4);
            float r8[8];
            r8[0] = gelu_tanh(u0.x + v0.x + c0.x);
            r8[1] = gelu_tanh(u0.y + v0.y + c0.y);
            r8[2] = gelu_tanh(u0.z + v0.z + c0.z);
            r8[3] = gelu_tanh(u0.w + v0.w + c0.w);
            r8[4] = gelu_tanh(u1.x + v1.x + c1.x);
            r8[5] = gelu_tanh(u1.y + v1.y + c1.y);
            r8[6] = gelu_tanh(u1.z + v1.z + c1.z);
            r8[7] = gelu_tanh(u1.w + v1.w + c1.w);
            uint32_t hw[4], lw[4];
#pragma unroll
            for (int q = 0; q < 4; q++) {
                bf16 h0 = __float2bfloat16(r8[q*2+0]);
                bf16 h1 = __float2bfloat16(r8[q*2+1]);
                bf16 l0 = __float2bfloat16(r8[q*2+0] - __bfloat162float(h0));
                bf16 l1 = __float2bfloat16(r8[q*2+1] - __bfloat162float(h1));
                hw[q] = ((uint32_t)__bfloat16_as_ushort(h1) << 16) | __bfloat16_as_ushort(h0);
                lw[q] = ((uint32_t)__bfloat16_as_ushort(l1) << 16) | __bfloat16_as_ushort(l0);
            }
            uint32_t sw = SW64(row * 64 + seg * 16);
            *(uint4*)(astg + sw) = make_uint4(hw[0], hw[1], hw[2], hw[3]);
            *(uint4*)(astg + 8192 + sw) = make_uint4(lw[0], lw[1], lw[2], lw[3]);
        }
        if (cc >= 3) wait_commit(cc - 3);
        uint32_t bstg = sb + H2_BBASE + (cc % 3) * H2_BSTG;
#pragma unroll 1
        for (int i = 0; i < 13; i++) {
            int idx = i * 256 + tid;
            if (idx < 3200) {
                int plane = idx >= 1600;
                int j = idx - plane * 1600;
                int row = j >> 2, seg = j & 3;
                const bf16* g = (plane ? Blo : Bhi) + (size_t)row * PAIRD + k0 + seg * 8;
                cp16(bstg + plane * 25600 + SW64(row * 64 + seg * 16), g);
            }
        }
        CP_COMMIT();
    };

    prep(0);
    prep(1);
    for (int c = 0; c < NC; c++) {
        if (c + 2 < NC) prep(c + 2);
        if (c + 2 < NC) { CP_WAIT(2); }
        else if (c + 1 < NC) { CP_WAIT(1); }
        else { CP_WAIT(0); }
        asm volatile("fence.proxy.async.shared::cta;" ::: "memory");
        __syncthreads();
        if (wid == 0 && elect1()) {
            uint32_t ag = sb + H2_ABASE + (c & 3) * H2_ASTG;
            uint64_t dAh = mk_desc64(ag);
            uint64_t dAl = mk_desc64(ag + 8192);
            uint32_t bg = sb + H2_BBASE + (c % 3) * H2_BSTG;
#pragma unroll
            for (int half = 0; half < 2; half++) {
                uint64_t dBh = mk_desc64(bg + half * 12800);
                uint64_t dBl = mk_desc64(bg + 25600 + half * 12800);
                uint32_t d = tmem + half * 200;
#pragma unroll
                for (int ks = 0; ks < 2; ks++) {
                    uint64_t o = (uint64_t)(ks * 2);
                    mma_bf16_ss(d, dAh + o, dBh + o, idesc, (c | ks) ? 1u : 0u);
                    mma_bf16_ss(d, dAh + o, dBl + o, idesc, 1u);
                    mma_bf16_ss(d, dAl + o, dBh + o, idesc, 1u);
                }
            }
            TCGEN05_COMMIT(sb + 16 + (c & 3) * 8);
        }
    }
    wait_commit(NC - 1);
    TCGEN05_FENCE_AFTER();

    // ---- epilogue: gelu(.+b2) dot W3 -> pred ----
    {
        int sub = wid & 3, cg = wid >> 2;
        int lane = tid & 31;
        float* cst = (float*)(dsm + H2_HDR);
        float d0 = 0.f, d1 = 0.f, d2 = 0.f;
        for (int cb0 = 0; cb0 < 400; cb0 += 64) {
            int cb = cb0 + cg * 32;
            if (cb < 400) {
                uint32_t regs[32];
                TCGEN05_LD_32X32B_X32(regs, tmem + cb);
                TCGEN05_WAIT_LD();
                int r = sub * 32 + lane;
#pragma unroll
                for (int j = 0; j < 32; j++) {
                    int col = cb + j;
                    if (col < 400) {
                        float v = __uint_as_float(regs[j]) + b2s[col];
                        v = gelu_tanh(v);
                        cst[r * CPITCH + (cg * 32 + j)] = v;
                    }
                }
            }
            __syncthreads();
            int cw = min(64, 400 - cb0);
            if (tid < 128) {
                for (int col = 0; col < cw; col++) {
                    float v = cst[tid * CPITCH + col];
                    int wc = (cb0 + col) * 3;
                    d0 += v * sw3[wc + 0];
                    d1 += v * sw3[wc + 1];
                    d2 += v * sw3[wc + 2];
                }
            }
            __syncthreads();
        }
        if (tid < 128) {
            size_t r = (size_t)(mBase + tid);
            pred[r * 3 + 0] = d0 + b3[0];
            pred[r * 3 + 1] = d1 + b3[1];
            pred[r * 3 + 2] = d2 + b3[2];
        }
    }
    __syncthreads();
    if (wid == 0) TCGEN05_DEALLOC(tmem, 512);

#else // !HAS_TC — naive correct fallback (compile-only)
    const int tid = threadIdx.x;
    const int mBase = blockIdx.x * 128;
    if (tid >= 128) return;
    int row = mBase + tid;
    int e = row & (EE - 1), b = row >> 14;
    int sn = (b << 10) + src0[e];
    int dn = (b << 10) + dst0[e];
    float d0 = 0.f, d1 = 0.f, d2 = 0.f;
    for (int col = 0; col < 400; col++) {
        float acc = 0.f;
        for (int k = 0; k < PAIRD; k++) {
            float a = gelu_tanh(U[(size_t)sn * PAIRD + k] + V[(size_t)dn * PAIRD + k] + b1[k]);
            size_t bo = (size_t)col * PAIRD + k;
            float bb = __bfloat162float(Bhi[bo]) + __bfloat162float(Blo[bo]);
            acc += a * bb;
        }
        acc = gelu_tanh(acc + b2[col]);
        d0 += acc * w3[col * 3 + 0];
        d1 += acc * w3[col * 3 + 1];
        d2 += acc * w3[col * 3 + 2];
    }
    pred[(size_t)row * 3 + 0] = d0 + b3[0];
    pred[(size_t)row * 3 + 1] = d1 + b3[1];
    pred[(size_t)row * 3 + 2] = d2 + b3[2];
#endif
}

// ---------------- attention scores ----------------
__global__ void attn_score_kernel(const float* __restrict__ wh,
                                  const float* __restrict__ att_src,
                                  const float* __restrict__ att_dst,
                                  float* __restrict__ as_, float* __restrict__ ad_)
{
    int bn = blockIdx.x;
    int h = threadIdx.x >> 5, lane = threadIdx.x & 31;
    const float* w = wh + (size_t)bn * OUTD + h * 200;
    float s = 0.f, d = 0.f;
    for (int f = lane; f < 200; f += 32) {
        float v = w[f];
        s += v * att_src[h * 200 + f];
        d += v * att_dst[h * 200 + f];
    }
#pragma unroll
    for (int o = 16; o; o >>= 1) {
        s += __shfl_down_sync(0xffffffffu, s, o);
        d += __shfl_down_sync(0xffffffffu, d, o);
    }
    if (lane == 0) { as_[bn * 2 + h] = s; ad_[bn * 2 + h] = d; }
}

// ---------------- CSR build ----------------
__global__ void zero_counts_kernel(int* counts) { counts[threadIdx.x] = 0; }

__global__ void count_kernel(const int* __restrict__ edges, int* __restrict__ counts) {
    int et = blockIdx.x * 256 + threadIdx.x;
    if (et >= ETOT) return;
    int dst = (et < EE) ? edges[EE + et] : (et - EE);
    atomicAdd(&counts[dst], 1);
}

__global__ void scan_kernel(const int* __restrict__ counts, int* __restrict__ rowstart,
                            int* __restrict__ fill) {
    __shared__ int s[NN];
    int t = threadIdx.x;
    int c = counts[t];
    s[t] = c;
    __syncthreads();
    for (int o = 1; o < NN; o <<= 1) {
        int v = (t >= o) ? s[t - o] : 0;
        __syncthreads();
        s[t] += v;
        __syncthreads();
    }
    rowstart[t + 1] = s[t];
    if (t == 0) rowstart[0] = 0;
    fill[t] = s[t] - c;
}

__global__ void scatter_kernel(const int* __restrict__ edges, int* __restrict__ fill,
                               int* __restrict__ csrsrc) {
    int et = blockIdx.x * 256 + threadIdx.x;
    if (et >= ETOT) return;
    int src = (et < EE) ? edges[et] : (et - EE);
    int dst = (et < EE) ? edges[EE + et] : (et - EE);
    int pos = atomicAdd(&fill[dst], 1);
    csrsrc[pos] = src;
}

// ---------------- GAT softmax + aggregation + residual ----------------
#define CHUNK 256
__global__ void gat_kernel(const float* __restrict__ wh, const float* __restrict__ as_,
                           const float* __restrict__ ad_, const float* __restrict__ enc,
                           const float* __restrict__ gat_b,
                           const int* __restrict__ rowstart, const int* __restrict__ csrsrc,
                           float* __restrict__ feat, bf16* __restrict__ feat_hi,
                           bf16* __restrict__ feat_lo)
{
    __shared__ float red0[256], red1[256];
    __shared__ int   s_src[CHUNK];
    __shared__ float s_c0[CHUNK], s_c1[CHUNK];
    __shared__ float sh_m0, sh_m1, sh_z0, sh_z1;

    int bn = blockIdx.x;
    int b = bn >> 10, n = bn & 1023;
    int tid = threadIdx.x;
    int start = rowstart[n];
    int deg = rowstart[n + 1] - start;

    float ad0 = ad_[bn * 2 + 0], ad1 = ad_[bn * 2 + 1];

    float m0 = -1e30f, m1 = -1e30f;
    for (int i = tid; i < deg; i += 256) {
        int s = csrsrc[start + i];
        int sb2 = (b << 10) + s;
        float e0 = as_[sb2 * 2 + 0] + ad0; e0 = (e0 > 0.f) ? e0 : 0.2f * e0;
        float e1 = as_[sb2 * 2 + 1] + ad1; e1 = (e1 > 0.f) ? e1 : 0.2f * e1;
        m0 = fmaxf(m0, e0); m1 = fmaxf(m1, e1);
    }
    red0[tid] = m0; red1[tid] = m1;
    __syncthreads();
    for (int o = 128; o; o >>= 1) {
        if (tid < o) {
            red0[tid] = fmaxf(red0[tid], red0[tid + o]);
            red1[tid] = fmaxf(red1[tid], red1[tid + o]);
        }
        __syncthreads();
    }
    if (tid == 0) { sh_m0 = red0[0]; sh_m1 = red1[0]; }
    __syncthreads();
    m0 = sh_m0; m1 = sh_m1;
    __syncthreads();

    float z0 = 0.f, z1 = 0.f;
    for (int i = tid; i < deg; i += 256) {
        int s = csrsrc[start + i];
        int sb2 = (b << 10) + s;
        float e0 = as_[sb2 * 2 + 0] + ad0; e0 = (e0 > 0.f) ? e0 : 0.2f * e0;
        float e1 = as_[sb2 * 2 + 1] + ad1; e1 = (e1 > 0.f) ? e1 : 0.2f * e1;
        z0 += expf(e0 - m0);
        z1 += expf(e1 - m1);
    }
    red0[tid] = z0; red1[tid] = z1;
    __syncthreads();
    for (int o = 128; o; o >>= 1) {
        if (tid < o) { red0[tid] += red0[tid + o]; red1[tid] += red1[tid + o]; }
        __syncthreads();
    }
    if (tid == 0) { sh_z0 = red0[0]; sh_z1 = red1[0]; }
    __syncthreads();
    z0 = sh_z0; z1 = sh_z1;
    float inv0 = 1.f / z0, inv1 = 1.f / z1;

    float acc0 = 0.f, acc1 = 0.f;
    for (int c0 = 0; c0 < deg; c0 += CHUNK) {
        int cn = min(CHUNK, deg - c0);
        __syncthreads();
        if (tid < cn) {
            int s = csrsrc[start + c0 + tid];
            int sb2 = (b << 10) + s;
            float e0 = as_[sb2 * 2 + 0] + ad0; e0 = (e0 > 0.f) ? e0 : 0.2f * e0;
            float e1 = as_[sb2 * 2 + 1] + ad1; e1 = (e1 > 0.f) ? e1 : 0.2f * e1;
            s_src[tid] = sb2;
            s_c0[tid] = expf(e0 - m0) * inv0;
            s_c1[tid] = expf(e1 - m1) * inv1;
        }
        __syncthreads();
        for (int i = 0; i < cn; i++) {
            const float* whrow = wh + (size_t)s_src[i] * OUTD;
            float coef = (tid < 200) ? s_c0[i] : s_c1[i];
            acc0 += coef * whrow[tid];
            if (tid < OUTD - 256) acc1 += s_c1[i] * whrow[tid + 256];
        }
    }

    size_t base = (size_t)bn * OUTD;
    {
        float v = enc[base + tid] + acc0 + gat_b[tid];
        feat[base + tid] = v;
        bf16 h = __float2bfloat16(v);
        feat_hi[base + tid] = h;
        feat_lo[base + tid] = __float2bfloat16(v - __bfloat162float(h));
    }
    if (tid < OUTD - 256) {
        float v = enc[base + tid + 256] + acc1 + gat_b[tid + 256];
        feat[base + tid + 256] = v;
        bf16 h = __float2bfloat16(v);
        feat_hi[base + tid + 256] = h;
        feat_lo[base + tid + 256] = __float2bfloat16(v - __bfloat162float(h));
    }
}

// ---------------- launch ----------------
extern "C" void kernel_launch(void* const* d_in, const int* in_sizes, int n_in,
                              void* d_out, int out_size)
{
    const float* X       = (const float*)d_in[0];
    const int*   edges   = (const int*)  d_in[1];
    const float* enc_w1  = (const float*)d_in[2];
    const float* enc_b1  = (const float*)d_in[3];
    const float* enc_w2  = (const float*)d_in[4];
    const float* enc_b2  = (const float*)d_in[5];
    const float* gat_w   = (const float*)d_in[6];
    const float* att_src = (const float*)d_in[7];
    const float* att_dst = (const float*)d_in[8];
    const float* gat_b   = (const float*)d_in[9];
    const float* h_w1    = (const float*)d_in[10];
    const float* h_b1    = (const float*)d_in[11];
    const float* h_w2    = (const float*)d_in[12];
    const float* h_b2    = (const float*)d_in[13];
    const float* h_w3    = (const float*)d_in[14];
    const float* h_b3    = (const float*)d_in[15];

    float* out  = (float*)d_out;
    float* feat = out;
    float* pred = out + FEAT_ELEMS;

    bf16 *Xhi, *Xlo, *hid_hi, *hid_lo, *enc_hi, *enc_lo, *feat_hi, *feat_lo;
    bf16 *w1t_hi, *w1t_lo, *w2t_hi, *w2t_lo, *wgt_hi, *wgt_lo;
    bf16 *w1a_hi, *w1a_lo, *w1b_hi, *w1b_lo, *h2t_hi, *h2t_lo;
    float *enc, *wh, *as_, *ad_, *U, *V;
    int *counts, *rowstart, *fill, *csrsrc;
    cudaGetSymbolAddress((void**)&Xhi, g_Xhi);       cudaGetSymbolAddress((void**)&Xlo, g_Xlo);
    cudaGetSymbolAddress((void**)&hid_hi, g_hid_hi); cudaGetSymbolAddress((void**)&hid_lo, g_hid_lo);
    cudaGetSymbolAddress((void**)&enc, g_enc);
    cudaGetSymbolAddress((void**)&enc_hi, g_enc_hi); cudaGetSymbolAddress((void**)&enc_lo, g_enc_lo);
    cudaGetSymbolAddress((void**)&wh, g_wh);
    cudaGetSymbolAddress((void**)&feat_hi, g_feat_hi); cudaGetSymbolAddress((void**)&feat_lo, g_feat_lo);
    cudaGetSymbolAddress((void**)&U, g_U);           cudaGetSymbolAddress((void**)&V, g_V);
    cudaGetSymbolAddress((void**)&w1t_hi, g_w1t_hi); cudaGetSymbolAddress((void**)&w1t_lo, g_w1t_lo);
    cudaGetSymbolAddress((void**)&w2t_hi, g_w2t_hi); cudaGetSymbolAddress((void**)&w2t_lo, g_w2t_lo);
    cudaGetSymbolAddress((void**)&wgt_hi, g_wgt_hi); cudaGetSymbolAddress((void**)&wgt_lo, g_wgt_lo);
    cudaGetSymbolAddress((void**)&w1a_hi, g_w1a_hi); cudaGetSymbolAddress((void**)&w1a_lo, g_w1a_lo);
    cudaGetSymbolAddress((void**)&w1b_hi, g_w1b_hi); cudaGetSymbolAddress((void**)&w1b_lo, g_w1b_lo);
    cudaGetSymbolAddress((void**)&h2t_hi, g_h2t_hi); cudaGetSymbolAddress((void**)&h2t_lo, g_h2t_lo);
    cudaGetSymbolAddress((void**)&as_, g_as);        cudaGetSymbolAddress((void**)&ad_, g_ad);
    cudaGetSymbolAddress((void**)&counts, g_counts); cudaGetSymbolAddress((void**)&rowstart, g_rowstart);
    cudaGetSymbolAddress((void**)&fill, g_fill);     cudaGetSymbolAddress((void**)&csrsrc, g_csrsrc);

    const int* src0 = edges;
    const int* dst0 = edges + EE;

    cudaFuncSetAttribute(mm_kernel<true ,true ,false,true >, cudaFuncAttributeMaxDynamicSharedMemorySize, SMEM_TOTAL_MM);
    cudaFuncSetAttribute(mm_kernel<true ,false,true ,true >, cudaFuncAttributeMaxDynamicSharedMemorySize, SMEM_TOTAL_MM);
    cudaFuncSetAttribute(mm_kernel<false,false,true ,false>, cudaFuncAttributeMaxDynamicSharedMemorySize, SMEM_TOTAL_MM);
    cudaFuncSetAttribute(head2_kernel, cudaFuncAttributeMaxDynamicSharedMemorySize, H2_SMEM);

    // ---- prep: split X, transpose+split weights ----
    {
        size_t nX = (size_t)BNR * IND;
        split_kernel<<<(unsigned)((nX + 255) / 256), 256>>>(X, Xhi, Xlo, nX);
        tsplit_kernel<<<(IND * HIDD + 255) / 256, 256>>>(enc_w1, w1t_hi, w1t_lo, IND, HIDD, 0, HIDD);
        tsplit_kernel<<<(HIDD * OUTD + 255) / 256, 256>>>(enc_w2, w2t_hi, w2t_lo, HIDD, OUTD, 0, OUTD);
        tsplit_kernel<<<(OUTD * OUTD + 255) / 256, 256>>>(gat_w, wgt_hi, wgt_lo, OUTD, OUTD, 0, OUTD);
        tsplit_kernel<<<(OUTD * PAIRD + 255) / 256, 256>>>(h_w1, w1a_hi, w1a_lo, OUTD, PAIRD, 0, PAIRD);
        tsplit_kernel<<<(OUTD * PAIRD + 255) / 256, 256>>>(h_w1, w1b_hi, w1b_lo, OUTD, PAIRD, OUTD, PAIRD);
        tsplit_kernel<<<(PAIRD * (PAIRD/2) + 255) / 256, 256>>>(h_w2, h2t_hi, h2t_lo, PAIRD, PAIRD/2, 0, PAIRD/2);
    }

    // 1) enc1: [32768,768] -> [32768,512], GELU, write hid hi/lo
    mm_kernel<true,true,false,true><<<dim3(2, BNR/128), 256, SMEM_TOTAL_MM>>>(
        Xhi, Xlo, w1t_hi, w1t_lo, enc_b1, nullptr, hid_hi, hid_lo, HIDD, IND);
    // 2) enc2: [32768,512] -> [32768,400], write enc f32 + hi/lo
    mm_kernel<true,false,true,true><<<dim3(2, BNR/128), 256, SMEM_TOTAL_MM>>>(
        hid_hi, hid_lo, w2t_hi, w2t_lo, enc_b2, enc, enc_hi, enc_lo, OUTD, HIDD);
    // 3) wh = enc @ gat_w
    mm_kernel<false,false,true,false><<<dim3(2, BNR/128), 256, SMEM_TOTAL_MM>>>(
        enc_hi, enc_lo, wgt_hi, wgt_lo, nullptr, wh, nullptr, nullptr, OUTD, OUTD);
    // 4) attention scores
    attn_score_kernel<<<BNR, 64>>>(wh, att_src, att_dst, as_, ad_);
    // 5) CSR build
    zero_counts_kernel<<<1, NN>>>(counts);
    count_kernel<<<(ETOT + 255) / 256, 256>>>(edges, counts);
    scan_kernel<<<1, NN>>>(counts, rowstart, fill);
    scatter_kernel<<<(ETOT + 255) / 256, 256>>>(edges, fill, csrsrc);
    // 6) GAT aggregate + residual -> feat (output) + feat hi/lo
    gat_kernel<<<BNR, 256>>>(wh, as_, ad_, enc, gat_b, rowstart, csrsrc, feat, feat_hi, feat_lo);
    // 7a) U = feat @ W1top: [32768,400] x [400,800]
    mm_kernel<false,false,true,false><<<dim3(4, BNR/128), 256, SMEM_TOTAL_MM>>>(
        feat_hi, feat_lo, w1a_hi, w1a_lo, nullptr, U, nullptr, nullptr, PAIRD, OUTD);
    // 7b) V = feat @ W1bot
    mm_kernel<false,false,true,false><<<dim3(4, BNR/128), 256, SMEM_TOTAL_MM>>>(
        feat_hi, feat_lo, w1b_hi, w1b_lo, nullptr, V, nullptr, nullptr, PAIRD, OUTD);
    // 8) head2: BK=32 SW64 cp.async pipeline, pred written directly
    head2_kernel<<<BER / 128, 256, H2_SMEM>>>(
        U, V, h2t_hi, h2t_lo, h_b1, h_b2, h_w3, h_b3, src0, dst0, pred);
}

// round 13
// speedup vs baseline: 1.2706x; 1.0407x over previous
#include <cuda_runtime.h>
#include <cuda_bf16.h>
#include <math.h>
#include <stdint.h>
#include <stddef.h>

// Problem constants
#define BB 32
#define NN 1024
#define EE 16384
#define ETOT (EE + NN)
#define IND 768
#define HIDD 512
#define OUTD 400
#define PAIRD 800
#define BNR (BB * NN)          // 32768
#define BER (BB * EE)          // 524288
#define FEAT_ELEMS ((size_t)BNR * OUTD)

typedef __nv_bfloat16 bf16;

#if defined(__CUDA_ARCH_FEAT_SM103_ALL) || defined(__CUDA_ARCH_FEAT_SM100_ALL) || defined(__CUDA_ARCH_FEAT_SM101_ALL)
#define HAS_TC 1
#else
#define HAS_TC 0
#endif

// ---------------- device scratch ----------------
__device__ bf16  g_Xhi[(size_t)BNR * IND];
__device__ bf16  g_Xlo[(size_t)BNR * IND];
__device__ bf16  g_hid_hi[(size_t)BNR * HIDD];
__device__ bf16  g_hid_lo[(size_t)BNR * HIDD];
__device__ float g_enc[(size_t)BNR * OUTD];
__device__ bf16  g_enc_hi[(size_t)BNR * OUTD];
__device__ bf16  g_enc_lo[(size_t)BNR * OUTD];
__device__ float g_wh[(size_t)BNR * OUTD];
__device__ bf16  g_feat_hi[(size_t)BNR * OUTD];
__device__ bf16  g_feat_lo[(size_t)BNR * OUTD];
__device__ float g_U[(size_t)BNR * PAIRD];
__device__ float g_V[(size_t)BNR * PAIRD];
// transposed/split weights [N][K]
__device__ bf16  g_w1t_hi[HIDD * IND],  g_w1t_lo[HIDD * IND];
__device__ bf16  g_w2t_hi[OUTD * HIDD], g_w2t_lo[OUTD * HIDD];
__device__ bf16  g_wgt_hi[OUTD * OUTD], g_wgt_lo[OUTD * OUTD];
__device__ bf16  g_w1a_hi[PAIRD * OUTD], g_w1a_lo[PAIRD * OUTD];
__device__ bf16  g_w1b_hi[PAIRD * OUTD], g_w1b_lo[PAIRD * OUTD];
__device__ bf16  g_h2t_hi[(PAIRD/2) * PAIRD], g_h2t_lo[(PAIRD/2) * PAIRD];
__device__ float g_as[BNR * 2], g_ad[BNR * 2];
__device__ int   g_counts[NN], g_rowstart[NN + 1], g_fill[NN], g_csrsrc[ETOT];

// tanhf lowers to the HW MUFU.TANH path on sm_103a (round-8 isolation test).
__device__ __forceinline__ float gelu_tanh(float x) {
    const float c = 0.7978845608028654f;
    float x3 = x * x * x;
    return 0.5f * x * (1.0f + tanhf(c * (x + 0.044715f * x3)));
}

// ---------------- PTX helpers ----------------
__device__ __forceinline__ uint32_t smem_u32(const void* p) {
    uint32_t a;
    asm("{ .reg .u64 t; cvta.to.shared.u64 t, %1; cvt.u32.u64 %0, t; }" : "=r"(a) : "l"(p));
    return a;
}
__device__ __forceinline__ uint32_t elect1() {
    uint32_t r;
    asm volatile("{\n\t.reg .pred p;\n\telect.sync _|p, 0xFFFFFFFF;\n\tselp.b32 %0, 1, 0, p;\n\t}" : "=r"(r));
    return r;
}
#define SW64(o)  ((o) ^ (((o) >> 3) & 0x30))

__device__ __forceinline__ uint64_t mk_desc64(uint32_t addr) {
    const uint64_t base = (uint64_t(4) << 61) | (uint64_t(1) << 46) |
                          (uint64_t(32) << 32) | (uint64_t(1) << 16);
    return base | ((uint64_t)(addr >> 4) & 0x3FFF);
}

__device__ __forceinline__ void cp16(uint32_t saddr, const void* g) {
    asm volatile("cp.async.cg.shared.global [%0], [%1], 16;" :: "r"(saddr), "l"(g));
}
#define CP_COMMIT() asm volatile("cp.async.commit_group;" ::: "memory")
#define CP_WAIT(n)  asm volatile("cp.async.wait_group %0;" :: "n"(n) : "memory")

#define MBARRIER_INIT(addr, cnt) \
    asm volatile("mbarrier.init.shared.b64 [%0], %1;" :: "r"((uint32_t)(addr)), "r"((uint32_t)(cnt)) : "memory")

#define MBARRIER_WAIT_PARITY(addr, parity) do { \
    uint32_t _mbar = (uint32_t)(addr); \
    uint32_t _par = (uint32_t)(parity); \
    uint32_t _done; \
    asm volatile("{\n\t.reg .pred p;\n\t" \
        "mbarrier.try_wait.parity.acquire.cta.shared::cta.b64 p, [%1], %2;\n\t" \
        "selp.b32 %0, 1, 0, p;\n\t}" : "=r"(_done) : "r"(_mbar), "r"(_par) : "memory"); \
    if (!_done) { \
        asm volatile("{\n\t.reg .pred P1;\n\t" \
            "WAIT_LOOP_%=:\n\t" \
            "mbarrier.try_wait.parity.acquire.cta.shared::cta.b64 P1, [%0], %1, 0x989680;\n\t" \
            "@P1 bra.uni WAIT_DONE_%=;\n\t" \
            "bra.uni WAIT_LOOP_%=;\n\t" \
            "WAIT_DONE_%=:\n\t}" :: "r"(_mbar), "r"(_par) : "memory"); \
    } \
} while (0)

#if HAS_TC
#define TCGEN05_ALLOC(smem_addr, nCols) \
    asm volatile("tcgen05.alloc.cta_group::1.sync.aligned.shared::cta.b32 [%0], %1;" \
        :: "r"((uint32_t)(smem_addr)), "r"((uint32_t)(nCols)) : "memory")
#define TCGEN05_DEALLOC(tmem, nCols) \
    asm volatile("tcgen05.dealloc.cta_group::1.sync.aligned.b32 %0, %1;" :: "r"(tmem), "r"((uint32_t)(nCols)))
#define TCGEN05_COMMIT(mbar) \
    asm volatile("tcgen05.commit.cta_group::1.mbarrier::arrive::one.shared::cluster.b64 [%0];" \
        :: "r"((uint32_t)(mbar)) : "memory")
#define TCGEN05_FENCE_AFTER() asm volatile("tcgen05.fence::after_thread_sync;" ::: "memory")
#define TCGEN05_WAIT_LD() asm volatile("tcgen05.wait::ld.sync.aligned;" ::: "memory")

#define TCGEN05_LD_32X32B_X32(r, tmem_addr) \
    asm volatile( \
        "tcgen05.ld.sync.aligned.32x32b.x32.b32 " \
        "{%0, %1, %2, %3, %4, %5, %6, %7, " \
        " %8, %9, %10, %11, %12, %13, %14, %15, " \
        " %16, %17, %18, %19, %20, %21, %22, %23, " \
        " %24, %25, %26, %27, %28, %29, %30, %31}, [%32];" \
        : "=r"((r)[0]),  "=r"((r)[1]),  "=r"((r)[2]),  "=r"((r)[3]), \
          "=r"((r)[4]),  "=r"((r)[5]),  "=r"((r)[6]),  "=r"((r)[7]), \
          "=r"((r)[8]),  "=r"((r)[9]),  "=r"((r)[10]), "=r"((r)[11]), \
          "=r"((r)[12]), "=r"((r)[13]), "=r"((r)[14]), "=r"((r)[15]), \
          "=r"((r)[16]), "=r"((r)[17]), "=r"((r)[18]), "=r"((r)[19]), \
          "=r"((r)[20]), "=r"((r)[21]), "=r"((r)[22]), "=r"((r)[23]), \
          "=r"((r)[24]), "=r"((r)[25]), "=r"((r)[26]), "=r"((r)[27]), \
          "=r"((r)[28]), "=r"((r)[29]), "=r"((r)[30]), "=r"((r)[31]) \
        : "r"(tmem_addr))

__device__ __forceinline__ void mma_bf16_ss(uint32_t d, uint64_t ad, uint64_t bd,
                                            uint32_t idesc, uint32_t en) {
    asm volatile(
        "{\n\t.reg .pred p;\n\tsetp.ne.u32 p, %5, 0;\n\t"
        "tcgen05.mma.cta_group::1.kind::f16 [%0], %1, %2, %3, {%4, %4, %4, %4}, p;\n\t}"
        :: "r"(d), "l"(ad), "l"(bd), "r"(idesc), "r"(0u), "r"(en) : "memory");
}
#endif // HAS_TC

// ---------------- prep kernels ----------------
__global__ void split_kernel(const float* __restrict__ in, bf16* __restrict__ hi,
                             bf16* __restrict__ lo, size_t n) {
    size_t i = (size_t)blockIdx.x * 256 + threadIdx.x;
    if (i < n) {
        float v = in[i];
        bf16 h = __float2bfloat16(v);
        hi[i] = h;
        lo[i] = __float2bfloat16(v - __bfloat162float(h));
    }
}

__device__ __forceinline__ void tsplit_one(const float* W, bf16* hi, bf16* lo,
                                           int i, int Kw, int rowOff, int ldW) {
    int n = i / Kw, k = i - n * Kw;
    float v = W[(size_t)(rowOff + k) * ldW + n];
    bf16 h = __float2bfloat16(v);
    hi[i] = h;
    lo[i] = __float2bfloat16(v - __bfloat162float(h));
}

// All six weight transposes in one launch; also zeros counts.
#define TS0 (IND * HIDD)                 // 393216
#define TS1 (TS0 + HIDD * OUTD)          // 598016
#define TS2 (TS1 + OUTD * OUTD)          // 758016
#define TS3 (TS2 + OUTD * PAIRD)         // 1078016
#define TS4 (TS3 + OUTD * PAIRD)         // 1398016
#define TS5 (TS4 + PAIRD * (PAIRD/2))    // 1718016
__global__ void tsplit_all_kernel(
    const float* __restrict__ enc_w1, const float* __restrict__ enc_w2,
    const float* __restrict__ gat_w, const float* __restrict__ h_w1,
    const float* __restrict__ h_w2,
    bf16* w1t_hi, bf16* w1t_lo, bf16* w2t_hi, bf16* w2t_lo,
    bf16* wgt_hi, bf16* wgt_lo, bf16* w1a_hi, bf16* w1a_lo,
    bf16* w1b_hi, bf16* w1b_lo, bf16* h2t_hi, bf16* h2t_lo,
    int* counts)
{
    int i = blockIdx.x * 256 + threadIdx.x;
    if (i < NN) counts[i] = 0;
    if (i < TS0)      tsplit_one(enc_w1, w1t_hi, w1t_lo, i,        IND,  0,    HIDD);
    else if (i < TS1) tsplit_one(enc_w2, w2t_hi, w2t_lo, i - TS0,  HIDD, 0,    OUTD);
    else if (i < TS2) tsplit_one(gat_w,  wgt_hi, wgt_lo, i - TS1,  OUTD, 0,    OUTD);
    else if (i < TS3) tsplit_one(h_w1,   w1a_hi, w1a_lo, i - TS2,  OUTD, 0,    PAIRD);
    else if (i < TS4) tsplit_one(h_w1,   w1b_hi, w1b_lo, i - TS3,  OUTD, OUTD, PAIRD);
    else if (i < TS5) tsplit_one(h_w2,   h2t_hi, h2t_lo, i - TS4,  PAIRD,0,    PAIRD/2);
}

// ---------------- split-bf16 tcgen05 GEMM, BM=128, BN<=256, BK=32, SW64 ----------------
#define MM_HDR   8192
#define MM_ASTG  16384
#define MM_BSTG  32768
#define MM_STG   (MM_ASTG + MM_BSTG)
#define MM_NSTG  4
#define SMEM_TOTAL_MM (MM_HDR + MM_NSTG * MM_STG)   // 204800
#define CPITCH 65

template<bool BIAS, bool GELU_, bool WF32, bool WHILO>
__global__ __launch_bounds__(256, 1) void mm_kernel(
    const bf16* __restrict__ Ahi, const bf16* __restrict__ Alo,
    const bf16* __restrict__ Bhi, const bf16* __restrict__ Blo,
    const float* __restrict__ bias,
    float* __restrict__ Cf, bf16* __restrict__ Chi, bf16* __restrict__ Clo,
    int N, int K)
{
#if HAS_TC
    extern __shared__ char dsm[];
    const int tid = threadIdx.x;
    const int wid = tid >> 5;
    const uint32_t sb = smem_u32(dsm);
    const int mBase = blockIdx.y * 128;
    const int nBase = blockIdx.x * 256;
    const int nValid = min(256, N - nBase);

    if (tid == 0) {
        for (int i = 0; i < 4; i++) MBARRIER_INIT(sb + 16 + i * 8, 1);
    }
    if (wid == 0) TCGEN05_ALLOC(sb, 256);
    __syncthreads();
    uint32_t tmem;
    asm volatile("ld.shared.b32 %0, [%1];" : "=r"(tmem) : "r"(sb));

    const uint32_t idesc = (1u << 4) | (1u << 7) | (1u << 10) |
                           ((uint32_t)(nValid >> 3) << 17) | (8u << 24);
    const int NC = (K + 31) >> 5;

    auto wait_commit = [&](int j) {
        MBARRIER_WAIT_PARITY(sb + 16 + (j & 3) * 8, (j >> 2) & 1);
    };
    auto prep = [&](int cc) {
        int k0 = cc << 5;
        if (cc >= MM_NSTG) wait_commit(cc - MM_NSTG);
        uint32_t stg = sb + MM_HDR + (cc & 3) * MM_STG;
#pragma unroll
        for (int i = 0; i < 4; i++) {
            int idx = i * 256 + tid;
            int plane = idx >= 512;
            int j = idx - plane * 512;
            int row = j >> 2, seg = j & 3;
            int col = k0 + seg * 8;
            if (col < K) {
                const bf16* g = (plane ? Alo : Ahi) + (size_t)(mBase + row) * K + col;
                cp16(stg + plane * 8192 + SW64(row * 64 + seg * 16), g);
            }
        }
#pragma unroll
        for (int i = 0; i < 8; i++) {
            int idx = i * 256 + tid;
            int plane = idx >= 1024;
            int j = idx - plane * 1024;
            int row = j >> 2, seg = j & 3;
            int col = k0 + seg * 8;
            if (row < nValid && col < K) {
                const bf16* g = (plane ? Blo : Bhi) + (size_t)(nBase + row) * K + col;
                cp16(stg + 16384 + plane * 16384 + SW64(row * 64 + seg * 16), g);
            }
        }
        CP_COMMIT();
    };

    prep(0);
    if (NC > 1) prep(1);
    for (int c = 0; c < NC; c++) {
        if (c + 2 < NC) prep(c + 2);
        if (c + 2 < NC) { CP_WAIT(2); }
        else if (c + 1 < NC) { CP_WAIT(1); }
        else { CP_WAIT(0); }
        asm volatile("fence.proxy.async.shared::cta;" ::: "memory");
        __syncthreads();
        if (wid == 0 && elect1()) {
            uint32_t stg = sb + MM_HDR + (c & 3) * MM_STG;
            uint64_t dAh = mk_desc64(stg);
            uint64_t dAl = mk_desc64(stg + 8192);
            uint64_t dBh = mk_desc64(stg + 16384);
            uint64_t dBl = mk_desc64(stg + 32768);
            int ksteps = min(2, (K - (c << 5)) >> 4);
            for (int ks = 0; ks < ksteps; ks++) {
                uint64_t o = (uint64_t)(ks * 2);
                mma_bf16_ss(tmem, dAh + o, dBh + o, idesc, (c | ks) ? 1u : 0u);
                mma_bf16_ss(tmem, dAh + o, dBl + o, idesc, 1u);
                mma_bf16_ss(tmem, dAl + o, dBh + o, idesc, 1u);
            }
            TCGEN05_COMMIT(sb + 16 + (c & 3) * 8);
        }
    }
    wait_commit(NC - 1);
    TCGEN05_FENCE_AFTER();

    // ---- epilogue ----
    {
        int sub = wid & 3, cg = wid >> 2;
        int lane = tid & 31;
        float* cst = (float*)(dsm + MM_HDR);
        for (int cb0 = 0; cb0 < nValid; cb0 += 64) {
            int cb = cb0 + cg * 32;
            if (cb < nValid) {
                uint32_t regs[32];
                TCGEN05_LD_32X32B_X32(regs, tmem + cb);
                TCGEN05_WAIT_LD();
                int r = sub * 32 + lane;
#pragma unroll
                for (int j = 0; j < 32; j++) {
                    int col = cb + j;
                    if (col < nValid) {
                        float v = __uint_as_float(regs[j]);
                        if (BIAS) v += bias[nBase + col];
                        if (GELU_) v = gelu_tanh(v);
                        cst[r * CPITCH + (cg * 32 + j)] = v;
                    }
                }
            }
            __syncthreads();
            int cw = min(64, nValid - cb0);
            for (int i = tid; i < 128 * cw; i += 256) {
                int row = i / cw, col = i - row * cw;
                float v = cst[row * CPITCH + col];
                size_t gr = (size_t)(mBase + row);
                int gc = nBase + cb0 + col;
                if (WF32) Cf[gr * N + gc] = v;
                if (WHILO) {
                    bf16 h = __float2bfloat16(v);
                    Chi[gr * N + gc] = h;
                    Clo[gr * N + gc] = __float2bfloat16(v - __bfloat162float(h));
                }
            }
            __syncthreads();
        }
    }
    __syncthreads();
    if (wid == 0) TCGEN05_DEALLOC(tmem, 256);

#else // !HAS_TC — naive correct fallback
    const int tid = threadIdx.x;
    const int mBase = blockIdx.y * 128;
    const int nBase = blockIdx.x * 256;
    const int nValid = min(256, N - nBase);
    if (tid >= 128) return;
    int row = mBase + tid;
    for (int col = 0; col < nValid; col++) {
        int gc = nBase + col;
        float acc = 0.f;
        for (int k = 0; k < K; k++) {
            size_t off = (size_t)row * K + k;
            float a = __bfloat162float(Ahi[off]) + __bfloat162float(Alo[off]);
            size_t bo = (size_t)gc * K + k;
            float bb = __bfloat162float(Bhi[bo]) + __bfloat162float(Blo[bo]);
            acc += a * bb;
        }
        if (BIAS) acc += bias[gc];
        if (GELU_) acc = gelu_tanh(acc);
        if (WF32) Cf[(size_t)row * N + gc] = acc;
        if (WHILO) {
            bf16 h = __float2bfloat16(acc);
            Chi[(size_t)row * N + gc] = h;
            Clo[(size_t)row * N + gc] = __float2bfloat16(acc - __bfloat162float(h));
        }
    }
#endif
}

// ---------------- fused head2 (BK=32, SW64, cp.async pipelined) ----------------
#define H2_HDR   12288
#define H2_ASTG  16384
#define H2_BSTG  51200
#define H2_ABASE H2_HDR
#define H2_BBASE (H2_HDR + 4 * H2_ASTG)
#define H2_SMEM  (H2_BBASE + 3 * H2_BSTG)    // 231424

__global__ __launch_bounds__(256, 1) void head2_kernel(
    const float* __restrict__ U, const float* __restrict__ V,
    const bf16* __restrict__ Bhi, const bf16* __restrict__ Blo,
    const float* __restrict__ b1, const float* __restrict__ b2,
    const float* __restrict__ w3, const float* __restrict__ b3,
    const int* __restrict__ src0, const int* __restrict__ dst0,
    float* __restrict__ pred)
{
#if HAS_TC
    extern __shared__ char dsm[];
    const int tid = threadIdx.x;
    const int wid = tid >> 5;
    const uint32_t sb = smem_u32(dsm);
    const int mBase = blockIdx.x * 128;
    const int NC = 25;
    int* sSrc = (int*)(dsm + 64);
    int* sDst = (int*)(dsm + 576);
    float* sw3 = (float*)(dsm + 1152);
    float* b1s = (float*)(dsm + 5952);
    float* b2s = (float*)(dsm + 9152);

    if (tid == 0) {
        for (int i = 0; i < 4; i++) MBARRIER_INIT(sb + 16 + i * 8, 1);
    }
    if (wid == 0) TCGEN05_ALLOC(sb, 512);
    if (tid < 128) {
        int r = mBase + tid;
        int e = r & (EE - 1), b = r >> 14;
        sSrc[tid] = (b << 10) + src0[e];
        sDst[tid] = (b << 10) + dst0[e];
    }
    for (int i = tid; i < 1200; i += 256) sw3[i] = w3[i];
    for (int i = tid; i < 800; i += 256) b1s[i] = b1[i];
    for (int i = tid; i < 400; i += 256) b2s[i] = b2[i];
    __syncthreads();
    uint32_t tmem;
    asm volatile("ld.shared.b32 %0, [%1];" : "=r"(tmem) : "r"(sb));

    const uint32_t idesc = (1u << 4) | (1u << 7) | (1u << 10) | (25u << 17) | (8u << 24);

    auto wait_commit = [&](int j) {
        MBARRIER_WAIT_PARITY(sb + 16 + (j & 3) * 8, (j >> 2) & 1);
    };
    auto prep = [&](int cc) {
        int k0 = cc * 32;
        if (cc >= 4) wait_commit(cc - 4);
        char* astg = dsm + H2_ABASE + (cc & 3) * H2_ASTG;
#pragma unroll
        for (int i = 0; i < 2; i++) {
            int idx = i * 256 + tid;
            int row = idx >> 2, seg = idx & 3;
            int col = k0 + seg * 8;
            int sn = sSrc[row], dn = sDst[row];
            const float* up = U + (size_t)sn * PAIRD + col;
            const float* vp = V + (size_t)dn * PAIRD + col;
            float4 u0 = *(const float4*)up, u1 = *(const float4*)(up + 4);
            float4 v0 = *(const float4*)vp, v1 = *(const float4*)(vp + 4);
            float4 c0 = *(const float4*)(b1s + col);
            float4 c1 = *(const float4*)(b1s + col + 4);
            float r8[8];
            r8[0] = gelu_tanh(u0.x + v0.x + c0.x);
            r8[1] = gelu_tanh(u0.y + v0.y + c0.y);
            r8[2] = gelu_tanh(u0.z + v0.z + c0.z);
            r8[3] = gelu_tanh(u0.w + v0.w + c0.w);
            r8[4] = gelu_tanh(u1.x + v1.x + c1.x);
            r8[5] = gelu_tanh(u1.y + v1.y + c1.y);
            r8[6] = gelu_tanh(u1.z + v1.z + c1.z);
            r8[7] = gelu_tanh(u1.w + v1.w + c1.w);
            uint32_t hw[4], lw[4];
#pragma unroll
            for (int q = 0; q < 4; q++) {
                bf16 h0 = __float2bfloat16(r8[q*2+0]);
                bf16 h1 = __float2bfloat16(r8[q*2+1]);
                bf16 l0 = __float2bfloat16(r8[q*2+0] - __bfloat162float(h0));
                bf16 l1 = __float2bfloat16(r8[q*2+1] - __bfloat162float(h1));
                hw[q] = ((uint32_t)__bfloat16_as_ushort(h1) << 16) | __bfloat16_as_ushort(h0);
                lw[q] = ((uint32_t)__bfloat16_as_ushort(l1) << 16) | __bfloat16_as_ushort(l0);
            }
            uint32_t sw = SW64(row * 64 + seg * 16);
            *(uint4*)(astg + sw) = make_uint4(hw[0], hw[1], hw[2], hw[3]);
            *(uint4*)(astg + 8192 + sw) = make_uint4(lw[0], lw[1], lw[2], lw[3]);
        }
        if (cc >= 3) wait_commit(cc - 3);
        uint32_t bstg = sb + H2_BBASE + (cc % 3) * H2_BSTG;
#pragma unroll 1
        for (int i = 0; i < 13; i++) {
            int idx = i * 256 + tid;
            if (idx < 3200) {
                int plane = idx >= 1600;
                int j = idx - plane * 1600;
                int row = j >> 2, seg = j & 3;
                const bf16* g = (plane ? Blo : Bhi) + (size_t)row * PAIRD + k0 + seg * 8;
                cp16(bstg + plane * 25600 + SW64(row * 64 + seg * 16), g);
            }
        }
        CP_COMMIT();
    };

    prep(0);
    prep(1);
    for (int c = 0; c < NC; c++) {
        if (c + 2 < NC) prep(c + 2);
        if (c + 2 < NC) { CP_WAIT(2); }
        else if (c + 1 < NC) { CP_WAIT(1); }
        else { CP_WAIT(0); }
        asm volatile("fence.proxy.async.shared::cta;" ::: "memory");
        __syncthreads();
        if (wid == 0 && elect1()) {
            uint32_t ag = sb + H2_ABASE + (c & 3) * H2_ASTG;
            uint64_t dAh = mk_desc64(ag);
            uint64_t dAl = mk_desc64(ag + 8192);
            uint32_t bg = sb + H2_BBASE + (c % 3) * H2_BSTG;
#pragma unroll
            for (int half = 0; half < 2; half++) {
                uint64_t dBh = mk_desc64(bg + half * 12800);
                uint64_t dBl = mk_desc64(bg + 25600 + half * 12800);
                uint32_t d = tmem + half * 200;
#pragma unroll
                for (int ks = 0; ks < 2; ks++) {
                    uint64_t o = (uint64_t)(ks * 2);
                    mma_bf16_ss(d, dAh + o, dBh + o, idesc, (c | ks) ? 1u : 0u);
                    mma_bf16_ss(d, dAh + o, dBl + o, idesc, 1u);
                    mma_bf16_ss(d, dAl + o, dBh + o, idesc, 1u);
                }
            }
            TCGEN05_COMMIT(sb + 16 + (c & 3) * 8);
        }
    }
    wait_commit(NC - 1);
    TCGEN05_FENCE_AFTER();

    // ---- epilogue: gelu(.+b2) dot W3 -> pred ----
    {
        int sub = wid & 3, cg = wid >> 2;
        int lane = tid & 31;
        float* cst = (float*)(dsm + H2_HDR);
        float d0 = 0.f, d1 = 0.f, d2 = 0.f;
        for (int cb0 = 0; cb0 < 400; cb0 += 64) {
            int cb = cb0 + cg * 32;
            if (cb < 400) {
                uint32_t regs[32];
                TCGEN05_LD_32X32B_X32(regs, tmem + cb);
                TCGEN05_WAIT_LD();
                int r = sub * 32 + lane;
#pragma unroll
                for (int j = 0; j < 32; j++) {
                    int col = cb + j;
                    if (col < 400) {
                        float v = __uint_as_float(regs[j]) + b2s[col];
                        v = gelu_tanh(v);
                        cst[r * CPITCH + (cg * 32 + j)] = v;
                    }
                }
            }
            __syncthreads();
            int cw = min(64, 400 - cb0);
            if (tid < 128) {
                for (int col = 0; col < cw; col++) {
                    float v = cst[tid * CPITCH + col];
                    int wc = (cb0 + col) * 3;
                    d0 += v * sw3[wc + 0];
                    d1 += v * sw3[wc + 1];
                    d2 += v * sw3[wc + 2];
                }
            }
            __syncthreads();
        }
        if (tid < 128) {
            size_t r = (size_t)(mBase + tid);
            pred[r * 3 + 0] = d0 + b3[0];
            pred[r * 3 + 1] = d1 + b3[1];
            pred[r * 3 + 2] = d2 + b3[2];
        }
    }
    __syncthreads();
    if (wid == 0) TCGEN05_DEALLOC(tmem, 512);

#else // !HAS_TC — naive correct fallback
    const int tid = threadIdx.x;
    const int mBase = blockIdx.x * 128;
    if (tid >= 128) return;
    int row = mBase + tid;
    int e = row & (EE - 1), b = row >> 14;
    int sn = (b << 10) + src0[e];
    int dn = (b << 10) + dst0[e];
    float d0 = 0.f, d1 = 0.f, d2 = 0.f;
    for (int col = 0; col < 400; col++) {
        float acc = 0.f;
        for (int k = 0; k < PAIRD; k++) {
            float a = gelu_tanh(U[(size_t)sn * PAIRD + k] + V[(size_t)dn * PAIRD + k] + b1[k]);
            size_t bo = (size_t)col * PAIRD + k;
            float bb = __bfloat162float(Bhi[bo]) + __bfloat162float(Blo[bo]);
            acc += a * bb;
        }
        acc = gelu_tanh(acc + b2[col]);
        d0 += acc * w3[col * 3 + 0];
        d1 += acc * w3[col * 3 + 1];
        d2 += acc * w3[col * 3 + 2];
    }
    pred[(size_t)row * 3 + 0] = d0 + b3[0];
    pred[(size_t)row * 3 + 1] = d1 + b3[1];
    pred[(size_t)row * 3 + 2] = d2 + b3[2];
#endif
}

// ---------------- attention scores ----------------
__global__ void attn_score_kernel(const float* __restrict__ wh,
                                  const float* __restrict__ att_src,
                                  const float* __restrict__ att_dst,
                                  float* __restrict__ as_, float* __restrict__ ad_)
{
    int bn = blockIdx.x;
    int h = threadIdx.x >> 5, lane = threadIdx.x & 31;
    const float* w = wh + (size_t)bn * OUTD + h * 200;
    float s = 0.f, d = 0.f;
    for (int f = lane; f < 200; f += 32) {
        float v = w[f];
        s += v * att_src[h * 200 + f];
        d += v * att_dst[h * 200 + f];
    }
#pragma unroll
    for (int o = 16; o; o >>= 1) {
        s += __shfl_down_sync(0xffffffffu, s, o);
        d += __shfl_down_sync(0xffffffffu, d, o);
    }
    if (lane == 0) { as_[bn * 2 + h] = s; ad_[bn * 2 + h] = d; }
}

// ---------------- CSR build ----------------
__global__ void count_kernel(const int* __restrict__ edges, int* __restrict__ counts) {
    int et = blockIdx.x * 256 + threadIdx.x;
    if (et >= ETOT) return;
    int dst = (et < EE) ? edges[EE + et] : (et - EE);
    atomicAdd(&counts[dst], 1);
}

__global__ void scan_kernel(const int* __restrict__ counts, int* __restrict__ rowstart,
                            int* __restrict__ fill) {
    __shared__ int s[NN];
    int t = threadIdx.x;
    int c = counts[t];
    s[t] = c;
    __syncthreads();
    for (int o = 1; o < NN; o <<= 1) {
        int v = (t >= o) ? s[t - o] : 0;
        __syncthreads();
        s[t] += v;
        __syncthreads();
    }
    rowstart[t + 1] = s[t];
    if (t == 0) rowstart[0] = 0;
    fill[t] = s[t] - c;
}

__global__ void scatter_kernel(const int* __restrict__ edges, int* __restrict__ fill,
                               int* __restrict__ csrsrc) {
    int et = blockIdx.x * 256 + threadIdx.x;
    if (et >= ETOT) return;
    int src = (et < EE) ? edges[et] : (et - EE);
    int dst = (et < EE) ? edges[EE + et] : (et - EE);
    int pos = atomicAdd(&fill[dst], 1);
    csrsrc[pos] = src;
}

// ---------------- GAT: warp-per-node, shuffle-only (no block barriers) ----------------
__global__ void gat_kernel(const float* __restrict__ wh, const float* __restrict__ as_,
                           const float* __restrict__ ad_, const float* __restrict__ enc,
                           const float* __restrict__ gat_b,
                           const int* __restrict__ rowstart, const int* __restrict__ csrsrc,
                           float* __restrict__ feat, bf16* __restrict__ feat_hi,
                           bf16* __restrict__ feat_lo)
{
    int w = threadIdx.x >> 5, lane = threadIdx.x & 31;
    int bn = blockIdx.x * 8 + w;            // 32768 nodes, 8 warps/block
    int b = bn >> 10, n = bn & 1023;
    int start = rowstart[n];
    int deg = rowstart[n + 1] - start;
    float ad0 = ad_[bn * 2 + 0], ad1 = ad_[bn * 2 + 1];

    // pass 1: per-head max (lanes stride edges, shuffle-combine)
    float m0 = -1e30f, m1 = -1e30f;
    for (int i = lane; i < deg; i += 32) {
        int sb2 = (b << 10) + csrsrc[start + i];
        float e0 = as_[sb2 * 2 + 0] + ad0; e0 = (e0 > 0.f) ? e0 : 0.2f * e0;
        float e1 = as_[sb2 * 2 + 1] + ad1; e1 = (e1 > 0.f) ? e1 : 0.2f * e1;
        m0 = fmaxf(m0, e0); m1 = fmaxf(m1, e1);
    }
#pragma unroll
    for (int o = 16; o; o >>= 1) {
        m0 = fmaxf(m0, __shfl_xor_sync(0xffffffffu, m0, o));
        m1 = fmaxf(m1, __shfl_xor_sync(0xffffffffu, m1, o));
    }
    // pass 2: per-head sum of exp
    float z0 = 0.f, z1 = 0.f;
    for (int i = lane; i < deg; i += 32) {
        int sb2 = (b << 10) + csrsrc[start + i];
        float e0 = as_[sb2 * 2 + 0] + ad0; e0 = (e0 > 0.f) ? e0 : 0.2f * e0;
        float e1 = as_[sb2 * 2 + 1] + ad1; e1 = (e1 > 0.f) ? e1 : 0.2f * e1;
        z0 += expf(e0 - m0);
        z1 += expf(e1 - m1);
    }
#pragma unroll
    for (int o = 16; o; o >>= 1) {
        z0 += __shfl_xor_sync(0xffffffffu, z0, o);
        z1 += __shfl_xor_sync(0xffffffffu, z1, o);
    }
    float inv0 = 1.f / z0, inv1 = 1.f / z1;

    // pass 3: aggregation; lane owns cols lane + 32j (j<13)
    float acc[13];
#pragma unroll
    for (int j = 0; j < 13; j++) acc[j] = 0.f;
    for (int i = 0; i < deg; i++) {
        int sb2 = (b << 10) + csrsrc[start + i];       // broadcast load
        float e0 = as_[sb2 * 2 + 0] + ad0; e0 = (e0 > 0.f) ? e0 : 0.2f * e0;
        float e1 = as_[sb2 * 2 + 1] + ad1; e1 = (e1 > 0.f) ? e1 : 0.2f * e1;
        float c0 = expf(e0 - m0) * inv0;
        float c1 = expf(e1 - m1) * inv1;
        const float* row = wh + (size_t)sb2 * OUTD;
#pragma unroll
        for (int j = 0; j < 13; j++) {
            int col = lane + 32 * j;
            if (col < OUTD) acc[j] += ((col < 200) ? c0 : c1) * row[col];
        }
    }
    size_t base = (size_t)bn * OUTD;
#pragma unroll
    for (int j = 0; j < 13; j++) {
        int col = lane + 32 * j;
        if (col < OUTD) {
            float v = enc[base + col] + acc[j] + gat_b[col];
            feat[base + col] = v;
            bf16 h = __float2bfloat16(v);
            feat_hi[base + col] = h;
            feat_lo[base + col] = __float2bfloat16(v - __bfloat162float(h));
        }
    }
}

// ---------------- launch ----------------
extern "C" void kernel_launch(void* const* d_in, const int* in_sizes, int n_in,
                              void* d_out, int out_size)
{
    const float* X       = (const float*)d_in[0];
    const int*   edges   = (const int*)  d_in[1];
    const float* enc_w1  = (const float*)d_in[2];
    const float* enc_b1  = (const float*)d_in[3];
    const float* enc_w2  = (const float*)d_in[4];
    const float* enc_b2  = (const float*)d_in[5];
    const float* gat_w   = (const float*)d_in[6];
    const float* att_src = (const float*)d_in[7];
    const float* att_dst = (const float*)d_in[8];
    const float* gat_b   = (const float*)d_in[9];
    const float* h_w1    = (const float*)d_in[10];
    const float* h_b1    = (const float*)d_in[11];
    const float* h_w2    = (const float*)d_in[12];
    const float* h_b2    = (const float*)d_in[13];
    const float* h_w3    = (const float*)d_in[14];
    const float* h_b3    = (const float*)d_in[15];

    float* out  = (float*)d_out;
    float* feat = out;
    float* pred = out + FEAT_ELEMS;

    bf16 *Xhi, *Xlo, *hid_hi, *hid_lo, *enc_hi, *enc_lo, *feat_hi, *feat_lo;
    bf16 *w1t_hi, *w1t_lo, *w2t_hi, *w2t_lo, *wgt_hi, *wgt_lo;
    bf16 *w1a_hi, *w1a_lo, *w1b_hi, *w1b_lo, *h2t_hi, *h2t_lo;
    float *enc, *wh, *as_, *ad_, *U, *V;
    int *counts, *rowstart, *fill, *csrsrc;
    cudaGetSymbolAddress((void**)&Xhi, g_Xhi);       cudaGetSymbolAddress((void**)&Xlo, g_Xlo);
    cudaGetSymbolAddress((void**)&hid_hi, g_hid_hi); cudaGetSymbolAddress((void**)&hid_lo, g_hid_lo);
    cudaGetSymbolAddress((void**)&enc, g_enc);
    cudaGetSymbolAddress((void**)&enc_hi, g_enc_hi); cudaGetSymbolAddress((void**)&enc_lo, g_enc_lo);
    cudaGetSymbolAddress((void**)&wh, g_wh);
    cudaGetSymbolAddress((void**)&feat_hi, g_feat_hi); cudaGetSymbolAddress((void**)&feat_lo, g_feat_lo);
    cudaGetSymbolAddress((void**)&U, g_U);           cudaGetSymbolAddress((void**)&V, g_V);
    cudaGetSymbolAddress((void**)&w1t_hi, g_w1t_hi); cudaGetSymbolAddress((void**)&w1t_lo, g_w1t_lo);
    cudaGetSymbolAddress((void**)&w2t_hi, g_w2t_hi); cudaGetSymbolAddress((void**)&w2t_lo, g_w2t_lo);
    cudaGetSymbolAddress((void**)&wgt_hi, g_wgt_hi); cudaGetSymbolAddress((void**)&wgt_lo, g_wgt_lo);
    cudaGetSymbolAddress((void**)&w1a_hi, g_w1a_hi); cudaGetSymbolAddress((void**)&w1a_lo, g_w1a_lo);
    cudaGetSymbolAddress((void**)&w1b_hi, g_w1b_hi); cudaGetSymbolAddress((void**)&w1b_lo, g_w1b_lo);
    cudaGetSymbolAddress((void**)&h2t_hi, g_h2t_hi); cudaGetSymbolAddress((void**)&h2t_lo, g_h2t_lo);
    cudaGetSymbolAddress((void**)&as_, g_as);        cudaGetSymbolAddress((void**)&ad_, g_ad);
    cudaGetSymbolAddress((void**)&counts, g_counts); cudaGetSymbolAddress((void**)&rowstart, g_rowstart);
    cudaGetSymbolAddress((void**)&fill, g_fill);     cudaGetSymbolAddress((void**)&csrsrc, g_csrsrc);

    const int* src0 = edges;
    const int* dst0 = edges + EE;

    cudaFuncSetAttribute(mm_kernel<true ,true ,false,true >, cudaFuncAttributeMaxDynamicSharedMemorySize, SMEM_TOTAL_MM);
    cudaFuncSetAttribute(mm_kernel<true ,false,true ,true >, cudaFuncAttributeMaxDynamicSharedMemorySize, SMEM_TOTAL_MM);
    cudaFuncSetAttribute(mm_kernel<false,false,true ,false>, cudaFuncAttributeMaxDynamicSharedMemorySize, SMEM_TOTAL_MM);
    cudaFuncSetAttribute(head2_kernel, cudaFuncAttributeMaxDynamicSharedMemorySize, H2_SMEM);

    // Launch order chosen so the 6th launch (ncu -s 5 -c 1) is enc1's mm_kernel.
    // 1) all weight transposes + zero counts
    tsplit_all_kernel<<<(TS5 + 255) / 256, 256>>>(
        enc_w1, enc_w2, gat_w, h_w1, h_w2,
        w1t_hi, w1t_lo, w2t_hi, w2t_lo, wgt_hi, wgt_lo,
        w1a_hi, w1a_lo, w1b_hi, w1b_lo, h2t_hi, h2t_lo, counts);
    // 2-4) CSR build (depends only on edges)
    count_kernel<<<(ETOT + 255) / 256, 256>>>(edges, counts);
    scan_kernel<<<1, NN>>>(counts, rowstart, fill);
    scatter_kernel<<<(ETOT + 255) / 256, 256>>>(edges, fill, csrsrc);
    // 5) split X
    {
        size_t nX = (size_t)BNR * IND;
        split_kernel<<<(unsigned)((nX + 255) / 256), 256>>>(X, Xhi, Xlo, nX);
    }
    // 6) enc1  <-- profiled launch
    mm_kernel<true,true,false,true><<<dim3(2, BNR/128), 256, SMEM_TOTAL_MM>>>(
        Xhi, Xlo, w1t_hi, w1t_lo, enc_b1, nullptr, hid_hi, hid_lo, HIDD, IND);
    // 7) enc2
    mm_kernel<true,false,true,true><<<dim3(2, BNR/128), 256, SMEM_TOTAL_MM>>>(
        hid_hi, hid_lo, w2t_hi, w2t_lo, enc_b2, enc, enc_hi, enc_lo, OUTD, HIDD);
    // 8) wh = enc @ gat_w
    mm_kernel<false,false,true,false><<<dim3(2, BNR/128), 256, SMEM_TOTAL_MM>>>(
        enc_hi, enc_lo, wgt_hi, wgt_lo, nullptr, wh, nullptr, nullptr, OUTD, OUTD);
    // 9) attention scores
    attn_score_kernel<<<BNR, 64>>>(wh, att_src, att_dst, as_, ad_);
    // 10) GAT aggregate + residual (warp-per-node)
    gat_kernel<<<BNR / 8, 256>>>(wh, as_, ad_, enc, gat_b, rowstart, csrsrc, feat, feat_hi, feat_lo);
    // 11) U = feat @ W1top
    mm_kernel<false,false,true,false><<<dim3(4, BNR/128), 256, SMEM_TOTAL_MM>>>(
        feat_hi, feat_lo, w1a_hi, w1a_lo, nullptr, U, nullptr, nullptr, PAIRD, OUTD);
    // 12) V = feat @ W1bot
    mm_kernel<false,false,true,false><<<dim3(4, BNR/128), 256, SMEM_TOTAL_MM>>>(
        feat_hi, feat_lo, w1b_hi, w1b_lo, nullptr, V, nullptr, nullptr, PAIRD, OUTD);
    // 13) head2 fused -> pred
    head2_kernel<<<BER / 128, 256, H2_SMEM>>>(
        U, V, h2t_hi, h2t_lo, h_b1, h_b2, h_w3, h_b3, src0, dst0, pred);
}

// round 14
// speedup vs baseline: 1.5573x; 1.2257x over previous
#include <cuda_runtime.h>
#include <cuda_bf16.h>
#include <math.h>
#include <stdint.h>
#include <stddef.h>

// Problem constants
#define BB 32
#define NN 1024
#define EE 16384
#define ETOT (EE + NN)
#define IND 768
#define HIDD 512
#define OUTD 400
#define PAIRD 800
#define BNR (BB * NN)          // 32768
#define BER (BB * EE)          // 524288
#define FEAT_ELEMS ((size_t)BNR * OUTD)

typedef __nv_bfloat16 bf16;

#if defined(__CUDA_ARCH_FEAT_SM103_ALL) || defined(__CUDA_ARCH_FEAT_SM100_ALL) || defined(__CUDA_ARCH_FEAT_SM101_ALL)
#define HAS_TC 1
#else
#define HAS_TC 0
#endif

// ---------------- device scratch ----------------
__device__ bf16  g_Xhi[(size_t)BNR * IND];
__device__ bf16  g_Xlo[(size_t)BNR * IND];
__device__ bf16  g_hid_hi[(size_t)BNR * HIDD];
__device__ bf16  g_hid_lo[(size_t)BNR * HIDD];
__device__ float g_enc[(size_t)BNR * OUTD];
__device__ bf16  g_enc_hi[(size_t)BNR * OUTD];
__device__ bf16  g_enc_lo[(size_t)BNR * OUTD];
__device__ float g_wh[(size_t)BNR * OUTD];
__device__ bf16  g_feat_hi[(size_t)BNR * OUTD];
__device__ bf16  g_feat_lo[(size_t)BNR * OUTD];
__device__ float g_U[(size_t)BNR * PAIRD];
__device__ float g_V[(size_t)BNR * PAIRD];
// PRE-SWIZZLED staged weights: [ntile][chunk][hi 16KB | lo 16KB] (SW64 baked in)
__device__ uint4 g_w1tS[(size_t)2 * 24 * 32768 / 16];   // enc1 B: N=512,K=768
__device__ uint4 g_w2tS[(size_t)2 * 16 * 32768 / 16];   // enc2 B: N=400,K=512
__device__ uint4 g_wgtS[(size_t)2 * 13 * 32768 / 16];   // wh   B: N=400,K=400
__device__ uint4 g_w1aS[(size_t)4 * 13 * 32768 / 16];   // U    B: N=800,K=400
__device__ uint4 g_w1bS[(size_t)4 * 13 * 32768 / 16];   // V    B: N=800,K=400
__device__ uint4 g_h2BS[(size_t)25 * 51200 / 16];       // head2 B: [chunk][hi 25.6K|lo 25.6K]
__device__ float g_as[BNR * 2], g_ad[BNR * 2];
__device__ int   g_counts[NN], g_rowstart[NN + 1], g_fill[NN], g_csrsrc[ETOT];

// tanhf lowers to the HW MUFU.TANH path on sm_103a (round-8 isolation test).
__device__ __forceinline__ float gelu_tanh(float x) {
    const float c = 0.7978845608028654f;
    float x3 = x * x * x;
    return 0.5f * x * (1.0f + tanhf(c * (x + 0.044715f * x3)));
}

// ---------------- PTX helpers ----------------
__device__ __forceinline__ uint32_t smem_u32(const void* p) {
    uint32_t a;
    asm("{ .reg .u64 t; cvta.to.shared.u64 t, %1; cvt.u32.u64 %0, t; }" : "=r"(a) : "l"(p));
    return a;
}
__device__ __forceinline__ uint32_t elect1() {
    uint32_t r;
    asm volatile("{\n\t.reg .pred p;\n\telect.sync _|p, 0xFFFFFFFF;\n\tselp.b32 %0, 1, 0, p;\n\t}" : "=r"(r));
    return r;
}
#define SW64(o)  ((o) ^ (((o) >> 3) & 0x30))

__device__ __forceinline__ uint64_t mk_desc64(uint32_t addr) {
    const uint64_t base = (uint64_t(4) << 61) | (uint64_t(1) << 46) |
                          (uint64_t(32) << 32) | (uint64_t(1) << 16);
    return base | ((uint64_t)(addr >> 4) & 0x3FFF);
}

__device__ __forceinline__ void cp16(uint32_t saddr, const void* g) {
    asm volatile("cp.async.cg.shared.global [%0], [%1], 16;" :: "r"(saddr), "l"(g));
}
#define CP_COMMIT() asm volatile("cp.async.commit_group;" ::: "memory")
#define CP_WAIT(n)  asm volatile("cp.async.wait_group %0;" :: "n"(n) : "memory")

// one-shot bulk copy (UBLKCP): single instruction, mbarrier tx completion
__device__ __forceinline__ void bulk_cp(uint32_t dst, const void* src, uint32_t bytes, uint32_t mbar) {
    asm volatile("cp.async.bulk.shared::cluster.global.mbarrier::complete_tx::bytes [%0], [%1], %2, [%3];"
        :: "r"(dst), "l"(src), "r"(bytes), "r"(mbar) : "memory");
}

#define MBARRIER_INIT(addr, cnt) \
    asm volatile("mbarrier.init.shared.b64 [%0], %1;" :: "r"((uint32_t)(addr)), "r"((uint32_t)(cnt)) : "memory")
#define MBARRIER_EXPECT_TX(addr, bytes) \
    asm volatile("mbarrier.arrive.expect_tx.shared.b64 _, [%0], %1;" :: "r"((uint32_t)(addr)), "r"((uint32_t)(bytes)) : "memory")

#define MBARRIER_WAIT_PARITY(addr, parity) do { \
    uint32_t _mbar = (uint32_t)(addr); \
    uint32_t _par = (uint32_t)(parity); \
    uint32_t _done; \
    asm volatile("{\n\t.reg .pred p;\n\t" \
        "mbarrier.try_wait.parity.acquire.cta.shared::cta.b64 p, [%1], %2;\n\t" \
        "selp.b32 %0, 1, 0, p;\n\t}" : "=r"(_done) : "r"(_mbar), "r"(_par) : "memory"); \
    if (!_done) { \
        asm volatile("{\n\t.reg .pred P1;\n\t" \
            "WAIT_LOOP_%=:\n\t" \
            "mbarrier.try_wait.parity.acquire.cta.shared::cta.b64 P1, [%0], %1, 0x989680;\n\t" \
            "@P1 bra.uni WAIT_DONE_%=;\n\t" \
            "bra.uni WAIT_LOOP_%=;\n\t" \
            "WAIT_DONE_%=:\n\t}" :: "r"(_mbar), "r"(_par) : "memory"); \
    } \
} while (0)

#if HAS_TC
#define TCGEN05_ALLOC(smem_addr, nCols) \
    asm volatile("tcgen05.alloc.cta_group::1.sync.aligned.shared::cta.b32 [%0], %1;" \
        :: "r"((uint32_t)(smem_addr)), "r"((uint32_t)(nCols)) : "memory")
#define TCGEN05_DEALLOC(tmem, nCols) \
    asm volatile("tcgen05.dealloc.cta_group::1.sync.aligned.b32 %0, %1;" :: "r"(tmem), "r"((uint32_t)(nCols)))
#define TCGEN05_COMMIT(mbar) \
    asm volatile("tcgen05.commit.cta_group::1.mbarrier::arrive::one.shared::cluster.b64 [%0];" \
        :: "r"((uint32_t)(mbar)) : "memory")
#define TCGEN05_FENCE_AFTER() asm volatile("tcgen05.fence::after_thread_sync;" ::: "memory")
#define TCGEN05_WAIT_LD() asm volatile("tcgen05.wait::ld.sync.aligned;" ::: "memory")

#define TCGEN05_LD_32X32B_X32(r, tmem_addr) \
    asm volatile( \
        "tcgen05.ld.sync.aligned.32x32b.x32.b32 " \
        "{%0, %1, %2, %3, %4, %5, %6, %7, " \
        " %8, %9, %10, %11, %12, %13, %14, %15, " \
        " %16, %17, %18, %19, %20, %21, %22, %23, " \
        " %24, %25, %26, %27, %28, %29, %30, %31}, [%32];" \
        : "=r"((r)[0]),  "=r"((r)[1]),  "=r"((r)[2]),  "=r"((r)[3]), \
          "=r"((r)[4]),  "=r"((r)[5]),  "=r"((r)[6]),  "=r"((r)[7]), \
          "=r"((r)[8]),  "=r"((r)[9]),  "=r"((r)[10]), "=r"((r)[11]), \
          "=r"((r)[12]), "=r"((r)[13]), "=r"((r)[14]), "=r"((r)[15]), \
          "=r"((r)[16]), "=r"((r)[17]), "=r"((r)[18]), "=r"((r)[19]), \
          "=r"((r)[20]), "=r"((r)[21]), "=r"((r)[22]), "=r"((r)[23]), \
          "=r"((r)[24]), "=r"((r)[25]), "=r"((r)[26]), "=r"((r)[27]), \
          "=r"((r)[28]), "=r"((r)[29]), "=r"((r)[30]), "=r"((r)[31]) \
        : "r"(tmem_addr))

__device__ __forceinline__ void mma_bf16_ss(uint32_t d, uint64_t ad, uint64_t bd,
                                            uint32_t idesc, uint32_t en) {
    asm volatile(
        "{\n\t.reg .pred p;\n\tsetp.ne.u32 p, %5, 0;\n\t"
        "tcgen05.mma.cta_group::1.kind::f16 [%0], %1, %2, %3, {%4, %4, %4, %4}, p;\n\t}"
        :: "r"(d), "l"(ad), "l"(bd), "r"(idesc), "r"(0u), "r"(en) : "memory");
}
#endif // HAS_TC

// ---------------- prep kernels ----------------
__global__ void split_kernel(const float* __restrict__ in, bf16* __restrict__ hi,
                             bf16* __restrict__ lo, size_t n) {
    size_t i = (size_t)blockIdx.x * 256 + threadIdx.x;
    if (i < n) {
        float v = in[i];
        bf16 h = __float2bfloat16(v);
        hi[i] = h;
        lo[i] = __float2bfloat16(v - __bfloat162float(h));
    }
}

// staged write: B[n][k] (transposed from W[(rowOff+k)*ldW + n]), SW64 pre-applied
__device__ __forceinline__ void tstage_one(const float* W, char* S, int i,
                                           int Kw, int NC, int rowOff, int ldW) {
    int n = i / Kw, k = i - n * Kw;
    float v = W[(size_t)(rowOff + k) * ldW + n];
    bf16 h = __float2bfloat16(v);
    bf16 l = __float2bfloat16(v - __bfloat162float(h));
    int ntile = n >> 8, lrow = n & 255;
    int chunk = k >> 5, kin = k & 31;
    uint32_t o = SW64((uint32_t)(lrow * 64 + kin * 2));
    size_t blk = (size_t)(ntile * NC + chunk) * 32768;
    *(bf16*)(S + blk + o) = h;
    *(bf16*)(S + blk + 16384 + o) = l;
}
// head2 B staging: h2t[n=0..399][k=0..799] from h_w2[k][n]; [chunk][hi 25600|lo 25600]
__device__ __forceinline__ void h2stage_one(const float* W, char* S, int i) {
    int n = i / PAIRD, k = i - n * PAIRD;
    float v = W[(size_t)k * (PAIRD / 2) + n];
    bf16 h = __float2bfloat16(v);
    bf16 l = __float2bfloat16(v - __bfloat162float(h));
    int chunk = k >> 5, kin = k & 31;
    uint32_t o = SW64((uint32_t)(n * 64 + kin * 2));
    size_t blk = (size_t)chunk * 51200;
    *(bf16*)(S + blk + o) = h;
    *(bf16*)(S + blk + 25600 + o) = l;
}

#define TS0 (IND * HIDD)
#define TS1 (TS0 + HIDD * OUTD)
#define TS2 (TS1 + OUTD * OUTD)
#define TS3 (TS2 + OUTD * PAIRD)
#define TS4 (TS3 + OUTD * PAIRD)
#define TS5 (TS4 + PAIRD * (PAIRD/2))
__global__ void tsplit_all_kernel(
    const float* __restrict__ enc_w1, const float* __restrict__ enc_w2,
    const float* __restrict__ gat_w, const float* __restrict__ h_w1,
    const float* __restrict__ h_w2,
    char* w1tS, char* w2tS, char* wgtS, char* w1aS, char* w1bS, char* h2BS,
    int* counts)
{
    int i = blockIdx.x * 256 + threadIdx.x;
    if (i < NN) counts[i] = 0;
    if (i < TS0)      tstage_one(enc_w1, w1tS, i,        IND,  24, 0,    HIDD);
    else if (i < TS1) tstage_one(enc_w2, w2tS, i - TS0,  HIDD, 16, 0,    OUTD);
    else if (i < TS2) tstage_one(gat_w,  wgtS, i - TS1,  OUTD, 13, 0,    OUTD);
    else if (i < TS3) tstage_one(h_w1,   w1aS, i - TS2,  OUTD, 13, 0,    PAIRD);
    else if (i < TS4) tstage_one(h_w1,   w1bS, i - TS3,  OUTD, 13, OUTD, PAIRD);
    else if (i < TS5) h2stage_one(h_w2,  h2BS, i - TS4);
}

// fallback reader for staged weights (compile-only path)
__device__ __forceinline__ float staged_read(const char* S, int NC, int n, int k) {
    int ntile = n >> 8, lrow = n & 255, chunk = k >> 5, kin = k & 31;
    size_t blk = (size_t)(ntile * NC + chunk) * 32768;
    uint32_t o = SW64((uint32_t)(lrow * 64 + kin * 2));
    return __bfloat162float(*(const bf16*)(S + blk + o)) +
           __bfloat162float(*(const bf16*)(S + blk + 16384 + o));
}

// ---------------- split-bf16 tcgen05 GEMM, BM=128, BN<=256, BK=32, SW64 ----------------
// A: cp.async depth-2; B: pre-swizzled staged + single bulk copy per chunk.
#define MM_HDR   8192
#define MM_ASTG  16384
#define MM_BSTG  32768
#define MM_STG   (MM_ASTG + MM_BSTG)
#define MM_NSTG  4
#define SMEM_TOTAL_MM (MM_HDR + MM_NSTG * MM_STG)   // 204800
#define CPITCH 65

template<bool BIAS, bool GELU_, bool WF32, bool WHILO>
__global__ __launch_bounds__(256, 1) void mm_kernel(
    const bf16* __restrict__ Ahi, const bf16* __restrict__ Alo,
    const char* __restrict__ Bstg,
    const float* __restrict__ bias,
    float* __restrict__ Cf, bf16* __restrict__ Chi, bf16* __restrict__ Clo,
    int N, int K)
{
#if HAS_TC
    extern __shared__ char dsm[];
    const int tid = threadIdx.x;
    const int wid = tid >> 5;
    const uint32_t sb = smem_u32(dsm);
    const int mBase = blockIdx.y * 128;
    const int nBase = blockIdx.x * 256;
    const int nValid = min(256, N - nBase);
    const int NC = (K + 31) >> 5;

    if (tid == 0) {
        for (int i = 0; i < 4; i++) { MBARRIER_INIT(sb + 16 + i * 8, 1); MBARRIER_INIT(sb + 48 + i * 8, 1); }
    }
    if (wid == 0) TCGEN05_ALLOC(sb, 256);
    __syncthreads();
    uint32_t tmem;
    asm volatile("ld.shared.b32 %0, [%1];" : "=r"(tmem) : "r"(sb));

    const uint32_t idesc = (1u << 4) | (1u << 7) | (1u << 10) |
                           ((uint32_t)(nValid >> 3) << 17) | (8u << 24);

    auto wait_commit = [&](int j) {
        MBARRIER_WAIT_PARITY(sb + 16 + (j & 3) * 8, (j >> 2) & 1);
    };
    auto prep = [&](int cc) {
        int k0 = cc << 5;
        if (cc >= MM_NSTG) wait_commit(cc - MM_NSTG);
        uint32_t stg = sb + MM_HDR + (cc & 3) * MM_STG;
        // B: single bulk copy (both planes, 32KB) from pre-swizzled staging
        if (tid == 0) {
            uint32_t fb = sb + 48 + (cc & 3) * 8;
            MBARRIER_EXPECT_TX(fb, 32768u);
            bulk_cp(stg + 16384, Bstg + ((size_t)(blockIdx.x * NC + cc)) * 32768, 32768u, fb);
        }
        // A: 128 rows x 32 cols, hi/lo -> 1024 cp16
#pragma unroll
        for (int i = 0; i < 4; i++) {
            int idx = i * 256 + tid;
            int plane = idx >= 512;
            int j = idx - plane * 512;
            int row = j >> 2, seg = j & 3;
            int col = k0 + seg * 8;
            if (col < K) {
                const bf16* g = (plane ? Alo : Ahi) + (size_t)(mBase + row) * K + col;
                cp16(stg + plane * 8192 + SW64(row * 64 + seg * 16), g);
            }
        }
        CP_COMMIT();
    };

    prep(0);
    if (NC > 1) prep(1);
    for (int c = 0; c < NC; c++) {
        if (c + 2 < NC) prep(c + 2);
        if (c + 2 < NC) { CP_WAIT(2); }
        else if (c + 1 < NC) { CP_WAIT(1); }
        else { CP_WAIT(0); }
        asm volatile("fence.proxy.async.shared::cta;" ::: "memory");
        __syncthreads();
        if (wid == 0 && elect1()) {
            MBARRIER_WAIT_PARITY(sb + 48 + (c & 3) * 8, (c >> 2) & 1);  // B full
            uint32_t stg = sb + MM_HDR + (c & 3) * MM_STG;
            uint64_t dAh = mk_desc64(stg);
            uint64_t dAl = mk_desc64(stg + 8192);
            uint64_t dBh = mk_desc64(stg + 16384);
            uint64_t dBl = mk_desc64(stg + 32768);
            int ksteps = min(2, (K - (c << 5)) >> 4);
            for (int ks = 0; ks < ksteps; ks++) {
                uint64_t o = (uint64_t)(ks * 2);
                mma_bf16_ss(tmem, dAh + o, dBh + o, idesc, (c | ks) ? 1u : 0u);
                mma_bf16_ss(tmem, dAh + o, dBl + o, idesc, 1u);
                mma_bf16_ss(tmem, dAl + o, dBh + o, idesc, 1u);
            }
            TCGEN05_COMMIT(sb + 16 + (c & 3) * 8);
        }
    }
    wait_commit(NC - 1);
    TCGEN05_FENCE_AFTER();

    // ---- epilogue ----
    {
        int sub = wid & 3, cg = wid >> 2;
        int lane = tid & 31;
        float* cst = (float*)(dsm + MM_HDR);
        for (int cb0 = 0; cb0 < nValid; cb0 += 64) {
            int cb = cb0 + cg * 32;
            if (cb < nValid) {
                uint32_t regs[32];
                TCGEN05_LD_32X32B_X32(regs, tmem + cb);
                TCGEN05_WAIT_LD();
                int r = sub * 32 + lane;
#pragma unroll
                for (int j = 0; j < 32; j++) {
                    int col = cb + j;
                    if (col < nValid) {
                        float v = __uint_as_float(regs[j]);
                        if (BIAS) v += bias[nBase + col];
                        if (GELU_) v = gelu_tanh(v);
                        cst[r * CPITCH + (cg * 32 + j)] = v;
                    }
                }
            }
            __syncthreads();
            int cw = min(64, nValid - cb0);
            for (int i = tid; i < 128 * cw; i += 256) {
                int row = i / cw, col = i - row * cw;
                float v = cst[row * CPITCH + col];
                size_t gr = (size_t)(mBase + row);
                int gc = nBase + cb0 + col;
                if (WF32) Cf[gr * N + gc] = v;
                if (WHILO) {
                    bf16 h = __float2bfloat16(v);
                    Chi[gr * N + gc] = h;
                    Clo[gr * N + gc] = __float2bfloat16(v - __bfloat162float(h));
                }
            }
            __syncthreads();
        }
    }
    __syncthreads();
    if (wid == 0) TCGEN05_DEALLOC(tmem, 256);

#else // !HAS_TC — naive correct fallback
    const int tid = threadIdx.x;
    const int mBase = blockIdx.y * 128;
    const int nBase = blockIdx.x * 256;
    const int nValid = min(256, N - nBase);
    const int NC = (K + 31) >> 5;
    if (tid >= 128) return;
    int row = mBase + tid;
    for (int col = 0; col < nValid; col++) {
        int gc = nBase + col;
        float acc = 0.f;
        for (int k = 0; k < K; k++) {
            size_t off = (size_t)row * K + k;
            float a = __bfloat162float(Ahi[off]) + __bfloat162float(Alo[off]);
            // B tile ntile = blockIdx.x, local row = col
            int ntile = blockIdx.x, lrow = col;
            size_t blk = (size_t)(ntile * NC + (k >> 5)) * 32768;
            uint32_t o = SW64((uint32_t)(lrow * 64 + (k & 31) * 2));
            float bb = __bfloat162float(*(const bf16*)(Bstg + blk + o)) +
                       __bfloat162float(*(const bf16*)(Bstg + blk + 16384 + o));
            acc += a * bb;
        }
        if (BIAS) acc += bias[gc];
        if (GELU_) acc = gelu_tanh(acc);
        if (WF32) Cf[(size_t)row * N + gc] = acc;
        if (WHILO) {
            bf16 h = __float2bfloat16(acc);
            Chi[(size_t)row * N + gc] = h;
            Clo[(size_t)row * N + gc] = __float2bfloat16(acc - __bfloat162float(h));
        }
    }
#endif
}

// ---------------- fused head2 (BK=32, SW64, bulk-B pipelined) ----------------
#define H2_HDR   12288
#define H2_ASTG  16384
#define H2_BSTG  51200
#define H2_ABASE H2_HDR
#define H2_BBASE (H2_HDR + 4 * H2_ASTG)
#define H2_SMEM  (H2_BBASE + 3 * H2_BSTG)    // 231424
#define H2_MB_FULL 10752                      // B-full mbarriers (4x8B) inside HDR

__global__ __launch_bounds__(256, 1) void head2_kernel(
    const float* __restrict__ U, const float* __restrict__ V,
    const char* __restrict__ BS,
    const float* __restrict__ b1, const float* __restrict__ b2,
    const float* __restrict__ w3, const float* __restrict__ b3,
    const int* __restrict__ src0, const int* __restrict__ dst0,
    float* __restrict__ pred)
{
#if HAS_TC
    extern __shared__ char dsm[];
    const int tid = threadIdx.x;
    const int wid = tid >> 5;
    const uint32_t sb = smem_u32(dsm);
    const int mBase = blockIdx.x * 128;
    const int NC = 25;
    int* sSrc = (int*)(dsm + 64);
    int* sDst = (int*)(dsm + 576);
    float* sw3 = (float*)(dsm + 1152);
    float* b1s = (float*)(dsm + 5952);
    float* b2s = (float*)(dsm + 9152);

    if (tid == 0) {
        for (int i = 0; i < 4; i++) {
            MBARRIER_INIT(sb + 16 + i * 8, 1);
            MBARRIER_INIT(sb + H2_MB_FULL + i * 8, 1);
        }
    }
    if (wid == 0) TCGEN05_ALLOC(sb, 512);
    if (tid < 128) {
        int r = mBase + tid;
        int e = r & (EE - 1), b = r >> 14;
        sSrc[tid] = (b << 10) + src0[e];
        sDst[tid] = (b << 10) + dst0[e];
    }
    for (int i = tid; i < 1200; i += 256) sw3[i] = w3[i];
    for (int i = tid; i < 800; i += 256) b1s[i] = b1[i];
    for (int i = tid; i < 400; i += 256) b2s[i] = b2[i];
    __syncthreads();
    uint32_t tmem;
    asm volatile("ld.shared.b32 %0, [%1];" : "=r"(tmem) : "r"(sb));

    const uint32_t idesc = (1u << 4) | (1u << 7) | (1u << 10) | (25u << 17) | (8u << 24);

    auto wait_commit = [&](int j) {
        MBARRIER_WAIT_PARITY(sb + 16 + (j & 3) * 8, (j >> 2) & 1);
    };
    auto prep = [&](int cc) {
        int k0 = cc * 32;
        if (cc >= 4) wait_commit(cc - 4);
        char* astg = dsm + H2_ABASE + (cc & 3) * H2_ASTG;
#pragma unroll
        for (int i = 0; i < 2; i++) {
            int idx = i * 256 + tid;
            int row = idx >> 2, seg = idx & 3;
            int col = k0 + seg * 8;
            int sn = sSrc[row], dn = sDst[row];
            const float* up = U + (size_t)sn * PAIRD + col;
            const float* vp = V + (size_t)dn * PAIRD + col;
            float4 u0 = *(const float4*)up, u1 = *(const float4*)(up + 4);
            float4 v0 = *(const float4*)vp, v1 = *(const float4*)(vp + 4);
            float4 c0 = *(const float4*)(b1s + col);
            float4 c1 = *(const float4*)(b1s + col + 4);
            float r8[8];
            r8[0] = gelu_tanh(u0.x + v0.x + c0.x);
            r8[1] = gelu_tanh(u0.y + v0.y + c0.y);
            r8[2] = gelu_tanh(u0.z + v0.z + c0.z);
            r8[3] = gelu_tanh(u0.w + v0.w + c0.w);
            r8[4] = gelu_tanh(u1.x + v1.x + c1.x);
            r8[5] = gelu_tanh(u1.y + v1.y + c1.y);
            r8[6] = gelu_tanh(u1.z + v1.z + c1.z);
            r8[7] = gelu_tanh(u1.w + v1.w + c1.w);
            uint32_t hw[4], lw[4];
#pragma unroll
            for (int q = 0; q < 4; q++) {
                bf16 h0 = __float2bfloat16(r8[q*2+0]);
                bf16 h1 = __float2bfloat16(r8[q*2+1]);
                bf16 l0 = __float2bfloat16(r8[q*2+0] - __bfloat162float(h0));
                bf16 l1 = __float2bfloat16(r8[q*2+1] - __bfloat162float(h1));
                hw[q] = ((uint32_t)__bfloat16_as_ushort(h1) << 16) | __bfloat16_as_ushort(h0);
                lw[q] = ((uint32_t)__bfloat16_as_ushort(l1) << 16) | __bfloat16_as_ushort(l0);
            }
            uint32_t sw = SW64(row * 64 + seg * 16);
            *(uint4*)(astg + sw) = make_uint4(hw[0], hw[1], hw[2], hw[3]);
            *(uint4*)(astg + 8192 + sw) = make_uint4(lw[0], lw[1], lw[2], lw[3]);
        }
        if (cc >= 3) wait_commit(cc - 3);
        if (tid == 0) {
            uint32_t fb = sb + H2_MB_FULL + (cc & 3) * 8;
            MBARRIER_EXPECT_TX(fb, 51200u);
            bulk_cp(sb + H2_BBASE + (cc % 3) * H2_BSTG, BS + (size_t)cc * 51200, 51200u, fb);
        }
    };

    prep(0);
    prep(1);
    for (int c = 0; c < NC; c++) {
        if (c + 2 < NC) prep(c + 2);
        asm volatile("fence.proxy.async.shared::cta;" ::: "memory");
        __syncthreads();
        if (wid == 0 && elect1()) {
            MBARRIER_WAIT_PARITY(sb + H2_MB_FULL + (c & 3) * 8, (c >> 2) & 1);  // B full
            uint32_t ag = sb + H2_ABASE + (c & 3) * H2_ASTG;
            uint64_t dAh = mk_desc64(ag);
            uint64_t dAl = mk_desc64(ag + 8192);
            uint32_t bg = sb + H2_BBASE + (c % 3) * H2_BSTG;
#pragma unroll
            for (int half = 0; half < 2; half++) {
                uint64_t dBh = mk_desc64(bg + half * 12800);
                uint64_t dBl = mk_desc64(bg + 25600 + half * 12800);
                uint32_t d = tmem + half * 200;
#pragma unroll
                for (int ks = 0; ks < 2; ks++) {
                    uint64_t o = (uint64_t)(ks * 2);
                    mma_bf16_ss(d, dAh + o, dBh + o, idesc, (c | ks) ? 1u : 0u);
                    mma_bf16_ss(d, dAh + o, dBl + o, idesc, 1u);
                    mma_bf16_ss(d, dAl + o, dBh + o, idesc, 1u);
                }
            }
            TCGEN05_COMMIT(sb + 16 + (c & 3) * 8);
        }
    }
    wait_commit(NC - 1);
    TCGEN05_FENCE_AFTER();

    // ---- epilogue: gelu(.+b2) dot W3 -> pred ----
    {
        int sub = wid & 3, cg = wid >> 2;
        int lane = tid & 31;
        float* cst = (float*)(dsm + H2_HDR);
        float d0 = 0.f, d1 = 0.f, d2 = 0.f;
        for (int cb0 = 0; cb0 < 400; cb0 += 64) {
            int cb = cb0 + cg * 32;
            if (cb < 400) {
                uint32_t regs[32];
                TCGEN05_LD_32X32B_X32(regs, tmem + cb);
                TCGEN05_WAIT_LD();
                int r = sub * 32 + lane;
#pragma unroll
                for (int j = 0; j < 32; j++) {
                    int col = cb + j;
                    if (col < 400) {
                        float v = __uint_as_float(regs[j]) + b2s[col];
                        v = gelu_tanh(v);
                        cst[r * CPITCH + (cg * 32 + j)] = v;
                    }
                }
            }
            __syncthreads();
            int cw = min(64, 400 - cb0);
            if (tid < 128) {
                for (int col = 0; col < cw; col++) {
                    float v = cst[tid * CPITCH + col];
                    int wc = (cb0 + col) * 3;
                    d0 += v * sw3[wc + 0];
                    d1 += v * sw3[wc + 1];
                    d2 += v * sw3[wc + 2];
                }
            }
            __syncthreads();
        }
        if (tid < 128) {
            size_t r = (size_t)(mBase + tid);
            pred[r * 3 + 0] = d0 + b3[0];
            pred[r * 3 + 1] = d1 + b3[1];
            pred[r * 3 + 2] = d2 + b3[2];
        }
    }
    __syncthreads();
    if (wid == 0) TCGEN05_DEALLOC(tmem, 512);

#else // !HAS_TC — naive correct fallback
    const int tid = threadIdx.x;
    const int mBase = blockIdx.x * 128;
    if (tid >= 128) return;
    int row = mBase + tid;
    int e = row & (EE - 1), b = row >> 14;
    int sn = (b << 10) + src0[e];
    int dn = (b << 10) + dst0[e];
    float d0 = 0.f, d1 = 0.f, d2 = 0.f;
    for (int col = 0; col < 400; col++) {
        float acc = 0.f;
        for (int k = 0; k < PAIRD; k++) {
            float a = gelu_tanh(U[(size_t)sn * PAIRD + k] + V[(size_t)dn * PAIRD + k] + b1[k]);
            size_t blk = (size_t)(k >> 5) * 51200;
            uint32_t o = SW64((uint32_t)(col * 64 + (k & 31) * 2));
            float bb = __bfloat162float(*(const bf16*)(BS + blk + o)) +
                       __bfloat162float(*(const bf16*)(BS + blk + 25600 + o));
            acc += a * bb;
        }
        acc = gelu_tanh(acc + b2[col]);
        d0 += acc * w3[col * 3 + 0];
        d1 += acc * w3[col * 3 + 1];
        d2 += acc * w3[col * 3 + 2];
    }
    pred[(size_t)row * 3 + 0] = d0 + b3[0];
    pred[(size_t)row * 3 + 1] = d1 + b3[1];
    pred[(size_t)row * 3 + 2] = d2 + b3[2];
#endif
}

// ---------------- attention scores ----------------
__global__ void attn_score_kernel(const float* __restrict__ wh,
                                  const float* __restrict__ att_src,
                                  const float* __restrict__ att_dst,
                                  float* __restrict__ as_, float* __restrict__ ad_)
{
    int bn = blockIdx.x;
    int h = threadIdx.x >> 5, lane = threadIdx.x & 31;
    const float* w = wh + (size_t)bn * OUTD + h * 200;
    float s = 0.f, d = 0.f;
    for (int f = lane; f < 200; f += 32) {
        float v = w[f];
        s += v * att_src[h * 200 + f];
        d += v * att_dst[h * 200 + f];
    }
#pragma unroll
    for (int o = 16; o; o >>= 1) {
        s += __shfl_down_sync(0xffffffffu, s, o);
        d += __shfl_down_sync(0xffffffffu, d, o);
    }
    if (lane == 0) { as_[bn * 2 + h] = s; ad_[bn * 2 + h] = d; }
}

// ---------------- CSR build ----------------
__global__ void count_kernel(const int* __restrict__ edges, int* __restrict__ counts) {
    int et = blockIdx.x * 256 + threadIdx.x;
    if (et >= ETOT) return;
    int dst = (et < EE) ? edges[EE + et] : (et - EE);
    atomicAdd(&counts[dst], 1);
}

__global__ void scan_kernel(const int* __restrict__ counts, int* __restrict__ rowstart,
                            int* __restrict__ fill) {
    __shared__ int s[NN];
    int t = threadIdx.x;
    int c = counts[t];
    s[t] = c;
    __syncthreads();
    for (int o = 1; o < NN; o <<= 1) {
        int v = (t >= o) ? s[t - o] : 0;
        __syncthreads();
        s[t] += v;
        __syncthreads();
    }
    rowstart[t + 1] = s[t];
    if (t == 0) rowstart[0] = 0;
    fill[t] = s[t] - c;
}

__global__ void scatter_kernel(const int* __restrict__ edges, int* __restrict__ fill,
                               int* __restrict__ csrsrc) {
    int et = blockIdx.x * 256 + threadIdx.x;
    if (et >= ETOT) return;
    int src = (et < EE) ? edges[et] : (et - EE);
    int dst = (et < EE) ? edges[EE + et] : (et - EE);
    int pos = atomicAdd(&fill[dst], 1);
    csrsrc[pos] = src;
}

// ---------------- GAT: warp-per-node, shuffle-only ----------------
__global__ void gat_kernel(const float* __restrict__ wh, const float* __restrict__ as_,
                           const float* __restrict__ ad_, const float* __restrict__ enc,
                           const float* __restrict__ gat_b,
                           const int* __restrict__ rowstart, const int* __restrict__ csrsrc,
                           float* __restrict__ feat, bf16* __restrict__ feat_hi,
                           bf16* __restrict__ feat_lo)
{
    int w = threadIdx.x >> 5, lane = threadIdx.x & 31;
    int bn = blockIdx.x * 8 + w;
    int b = bn >> 10, n = bn & 1023;
    int start = rowstart[n];
    int deg = rowstart[n + 1] - start;
    float ad0 = ad_[bn * 2 + 0], ad1 = ad_[bn * 2 + 1];

    float m0 = -1e30f, m1 = -1e30f;
    for (int i = lane; i < deg; i += 32) {
        int sb2 = (b << 10) + csrsrc[start + i];
        float e0 = as_[sb2 * 2 + 0] + ad0; e0 = (e0 > 0.f) ? e0 : 0.2f * e0;
        float e1 = as_[sb2 * 2 + 1] + ad1; e1 = (e1 > 0.f) ? e1 : 0.2f * e1;
        m0 = fmaxf(m0, e0); m1 = fmaxf(m1, e1);
    }
#pragma unroll
    for (int o = 16; o; o >>= 1) {
        m0 = fmaxf(m0, __shfl_xor_sync(0xffffffffu, m0, o));
        m1 = fmaxf(m1, __shfl_xor_sync(0xffffffffu, m1, o));
    }
    float z0 = 0.f, z1 = 0.f;
    for (int i = lane; i < deg; i += 32) {
        int sb2 = (b << 10) + csrsrc[start + i];
        float e0 = as_[sb2 * 2 + 0] + ad0; e0 = (e0 > 0.f) ? e0 : 0.2f * e0;
        float e1 = as_[sb2 * 2 + 1] + ad1; e1 = (e1 > 0.f) ? e1 : 0.2f * e1;
        z0 += expf(e0 - m0);
        z1 += expf(e1 - m1);
    }
#pragma unroll
    for (int o = 16; o; o >>= 1) {
        z0 += __shfl_xor_sync(0xffffffffu, z0, o);
        z1 += __shfl_xor_sync(0xffffffffu, z1, o);
    }
    float inv0 = 1.f / z0, inv1 = 1.f / z1;

    float acc[13];
#pragma unroll
    for (int j = 0; j < 13; j++) acc[j] = 0.f;
    for (int i = 0; i < deg; i++) {
        int sb2 = (b << 10) + csrsrc[start + i];
        float e0 = as_[sb2 * 2 + 0] + ad0; e0 = (e0 > 0.f) ? e0 : 0.2f * e0;
        float e1 = as_[sb2 * 2 + 1] + ad1; e1 = (e1 > 0.f) ? e1 : 0.2f * e1;
        float c0 = expf(e0 - m0) * inv0;
        float c1 = expf(e1 - m1) * inv1;
        const float* row = wh + (size_t)sb2 * OUTD;
#pragma unroll
        for (int j = 0; j < 13; j++) {
            int col = lane + 32 * j;
            if (col < OUTD) acc[j] += ((col < 200) ? c0 : c1) * row[col];
        }
    }
    size_t base = (size_t)bn * OUTD;
#pragma unroll
    for (int j = 0; j < 13; j++) {
        int col = lane + 32 * j;
        if (col < OUTD) {
            float v = enc[base + col] + acc[j] + gat_b[col];
            feat[base + col] = v;
            bf16 h = __float2bfloat16(v);
            feat_hi[base + col] = h;
            feat_lo[base + col] = __float2bfloat16(v - __bfloat162float(h));
        }
    }
}

// ---------------- launch ----------------
extern "C" void kernel_launch(void* const* d_in, const int* in_sizes, int n_in,
                              void* d_out, int out_size)
{
    const float* X       = (const float*)d_in[0];
    const int*   edges   = (const int*)  d_in[1];
    const float* enc_w1  = (const float*)d_in[2];
    const float* enc_b1  = (const float*)d_in[3];
    const float* enc_w2  = (const float*)d_in[4];
    const float* enc_b2  = (const float*)d_in[5];
    const float* gat_w   = (const float*)d_in[6];
    const float* att_src = (const float*)d_in[7];
    const float* att_dst = (const float*)d_in[8];
    const float* gat_b   = (const float*)d_in[9];
    const float* h_w1    = (const float*)d_in[10];
    const float* h_b1    = (const float*)d_in[11];
    const float* h_w2    = (const float*)d_in[12];
    const float* h_b2    = (const float*)d_in[13];
    const float* h_w3    = (const float*)d_in[14];
    const float* h_b3    = (const float*)d_in[15];

    float* out  = (float*)d_out;
    float* feat = out;
    float* pred = out + FEAT_ELEMS;

    bf16 *Xhi, *Xlo, *hid_hi, *hid_lo, *enc_hi, *enc_lo, *feat_hi, *feat_lo;
    char *w1tS, *w2tS, *wgtS, *w1aS, *w1bS, *h2BS;
    float *enc, *wh, *as_, *ad_, *U, *V;
    int *counts, *rowstart, *fill, *csrsrc;
    cudaGetSymbolAddress((void**)&Xhi, g_Xhi);       cudaGetSymbolAddress((void**)&Xlo, g_Xlo);
    cudaGetSymbolAddress((void**)&hid_hi, g_hid_hi); cudaGetSymbolAddress((void**)&hid_lo, g_hid_lo);
    cudaGetSymbolAddress((void**)&enc, g_enc);
    cudaGetSymbolAddress((void**)&enc_hi, g_enc_hi); cudaGetSymbolAddress((void**)&enc_lo, g_enc_lo);
    cudaGetSymbolAddress((void**)&wh, g_wh);
    cudaGetSymbolAddress((void**)&feat_hi, g_feat_hi); cudaGetSymbolAddress((void**)&feat_lo, g_feat_lo);
    cudaGetSymbolAddress((void**)&U, g_U);           cudaGetSymbolAddress((void**)&V, g_V);
    cudaGetSymbolAddress((void**)&w1tS, g_w1tS);     cudaGetSymbolAddress((void**)&w2tS, g_w2tS);
    cudaGetSymbolAddress((void**)&wgtS, g_wgtS);     cudaGetSymbolAddress((void**)&w1aS, g_w1aS);
    cudaGetSymbolAddress((void**)&w1bS, g_w1bS);     cudaGetSymbolAddress((void**)&h2BS, g_h2BS);
    cudaGetSymbolAddress((void**)&as_, g_as);        cudaGetSymbolAddress((void**)&ad_, g_ad);
    cudaGetSymbolAddress((void**)&counts, g_counts); cudaGetSymbolAddress((void**)&rowstart, g_rowstart);
    cudaGetSymbolAddress((void**)&fill, g_fill);     cudaGetSymbolAddress((void**)&csrsrc, g_csrsrc);

    const int* src0 = edges;
    const int* dst0 = edges + EE;

    cudaFuncSetAttribute(mm_kernel<true ,true ,false,true >, cudaFuncAttributeMaxDynamicSharedMemorySize, SMEM_TOTAL_MM);
    cudaFuncSetAttribute(mm_kernel<true ,false,true ,true >, cudaFuncAttributeMaxDynamicSharedMemorySize, SMEM_TOTAL_MM);
    cudaFuncSetAttribute(mm_kernel<false,false,true ,false>, cudaFuncAttributeMaxDynamicSharedMemorySize, SMEM_TOTAL_MM);
    cudaFuncSetAttribute(head2_kernel, cudaFuncAttributeMaxDynamicSharedMemorySize, H2_SMEM);

    // 1) stage all weights (pre-swizzled) + zero counts
    tsplit_all_kernel<<<(TS5 + 255) / 256, 256>>>(
        enc_w1, enc_w2, gat_w, h_w1, h_w2,
        w1tS, w2tS, wgtS, w1aS, w1bS, h2BS, counts);
    // 2-4) CSR build
    count_kernel<<<(ETOT + 255) / 256, 256>>>(edges, counts);
    scan_kernel<<<1, NN>>>(counts, rowstart, fill);
    scatter_kernel<<<(ETOT + 255) / 256, 256>>>(edges, fill, csrsrc);
    // 5) split X
    {
        size_t nX = (size_t)BNR * IND;
        split_kernel<<<(unsigned)((nX + 255) / 256), 256>>>(X, Xhi, Xlo, nX);
    }
    // 6) enc1  <-- profiled launch (ncu -s 5 -c 1)
    mm_kernel<true,true,false,true><<<dim3(2, BNR/128), 256, SMEM_TOTAL_MM>>>(
        Xhi, Xlo, w1tS, enc_b1, nullptr, hid_hi, hid_lo, HIDD, IND);
    // 7) enc2
    mm_kernel<true,false,true,true><<<dim3(2, BNR/128), 256, SMEM_TOTAL_MM>>>(
        hid_hi, hid_lo, w2tS, enc_b2, enc, enc_hi, enc_lo, OUTD, HIDD);
    // 8) wh
    mm_kernel<false,false,true,false><<<dim3(2, BNR/128), 256, SMEM_TOTAL_MM>>>(
        enc_hi, enc_lo, wgtS, nullptr, wh, nullptr, nullptr, OUTD, OUTD);
    // 9) attention scores
    attn_score_kernel<<<BNR, 64>>>(wh, att_src, att_dst, as_, ad_);
    // 10) GAT (warp-per-node)
    gat_kernel<<<BNR / 8, 256>>>(wh, as_, ad_, enc, gat_b, rowstart, csrsrc, feat, feat_hi, feat_lo);
    // 11) U = feat @ W1top
    mm_kernel<false,false,true,false><<<dim3(4, BNR/128), 256, SMEM_TOTAL_MM>>>(
        feat_hi, feat_lo, w1aS, nullptr, U, nullptr, nullptr, PAIRD, OUTD);
    // 12) V = feat @ W1bot
    mm_kernel<false,false,true,false><<<dim3(4, BNR/128), 256, SMEM_TOTAL_MM>>>(
        feat_hi, feat_lo, w1bS, nullptr, V, nullptr, nullptr, PAIRD, OUTD);
    // 13) head2 fused -> pred
    head2_kernel<<<BER / 128, 256, H2_SMEM>>>(
        U, V, h2BS, h_b1, h_b2, h_w3, h_b3, src0, dst0, pred);
}

// round 16
// speedup vs baseline: 1.5623x; 1.0032x over previous
#include <cuda_runtime.h>
#include <cuda_bf16.h>
#include <math.h>
#include <stdint.h>
#include <stddef.h>

// Problem constants
#define BB 32
#define NN 1024
#define EE 16384
#define ETOT (EE + NN)
#define IND 768
#define HIDD 512
#define OUTD 400
#define PAIRD 800
#define BNR (BB * NN)          // 32768
#define BER (BB * EE)          // 524288
#define FEAT_ELEMS ((size_t)BNR * OUTD)

typedef __nv_bfloat16 bf16;

#if defined(__CUDA_ARCH_FEAT_SM103_ALL) || defined(__CUDA_ARCH_FEAT_SM100_ALL) || defined(__CUDA_ARCH_FEAT_SM101_ALL)
#define HAS_TC 1
#else
#define HAS_TC 0
#endif

// ---------------- device scratch ----------------
// staged activations: [mtile(=row>>7)][chunk(=k>>5)][hi 8KB | lo 8KB], SW64 baked in
__device__ uint4 g_XS  [(size_t)256 * 24 * 16384 / 16];   // X    K=768
__device__ uint4 g_hidS[(size_t)256 * 16 * 16384 / 16];   // hid  K=512
__device__ uint4 g_encS[(size_t)256 * 13 * 16384 / 16];   // enc  K=400
__device__ uint4 g_featS[(size_t)256 * 13 * 16384 / 16];  // feat K=400
__device__ float g_enc[(size_t)BNR * OUTD];
__device__ float g_wh[(size_t)BNR * OUTD];
__device__ float g_U[(size_t)BNR * PAIRD];
__device__ float g_V[(size_t)BNR * PAIRD];
// staged weights: [ntile][chunk][hi 16KB | lo 16KB]
__device__ uint4 g_w1tS[(size_t)2 * 24 * 32768 / 16];
__device__ uint4 g_w2tS[(size_t)2 * 16 * 32768 / 16];
__device__ uint4 g_wgtS[(size_t)2 * 13 * 32768 / 16];
__device__ uint4 g_w1aS[(size_t)4 * 13 * 32768 / 16];
__device__ uint4 g_w1bS[(size_t)4 * 13 * 32768 / 16];
__device__ uint4 g_h2BS[(size_t)25 * 51200 / 16];
__device__ float g_as[BNR * 2], g_ad[BNR * 2];
__device__ int   g_counts[NN], g_rowstart[NN + 1], g_fill[NN], g_csrsrc[ETOT];

// tanhf lowers to the HW MUFU.TANH path on sm_103a (round-8 isolation test).
__device__ __forceinline__ float gelu_tanh(float x) {
    const float c = 0.7978845608028654f;
    float x3 = x * x * x;
    return 0.5f * x * (1.0f + tanhf(c * (x + 0.044715f * x3)));
}

// ---------------- PTX helpers ----------------
__device__ __forceinline__ uint32_t smem_u32(const void* p) {
    uint32_t a;
    asm("{ .reg .u64 t; cvta.to.shared.u64 t, %1; cvt.u32.u64 %0, t; }" : "=r"(a) : "l"(p));
    return a;
}
#define SW64(o)  ((o) ^ (((o) >> 3) & 0x30))

__device__ __forceinline__ uint64_t mk_desc64(uint32_t addr) {
    const uint64_t base = (uint64_t(4) << 61) | (uint64_t(1) << 46) |
                          (uint64_t(32) << 32) | (uint64_t(1) << 16);
    return base | ((uint64_t)(addr >> 4) & 0x3FFF);
}

// one-shot bulk copy (UBLKCP)
__device__ __forceinline__ void bulk_cp(uint32_t dst, const void* src, uint32_t bytes, uint32_t mbar) {
    asm volatile("cp.async.bulk.shared::cluster.global.mbarrier::complete_tx::bytes [%0], [%1], %2, [%3];"
        :: "r"(dst), "l"(src), "r"(bytes), "r"(mbar) : "memory");
}

#define MBARRIER_INIT(addr, cnt) \
    asm volatile("mbarrier.init.shared.b64 [%0], %1;" :: "r"((uint32_t)(addr)), "r"((uint32_t)(cnt)) : "memory")
#define MBARRIER_EXPECT_TX(addr, bytes) \
    asm volatile("mbarrier.arrive.expect_tx.shared.b64 _, [%0], %1;" :: "r"((uint32_t)(addr)), "r"((uint32_t)(bytes)) : "memory")

#define MBARRIER_WAIT_PARITY(addr, parity) do { \
    uint32_t _mbar = (uint32_t)(addr); \
    uint32_t _par = (uint32_t)(parity); \
    uint32_t _done; \
    asm volatile("{\n\t.reg .pred p;\n\t" \
        "mbarrier.try_wait.parity.acquire.cta.shared::cta.b64 p, [%1], %2;\n\t" \
        "selp.b32 %0, 1, 0, p;\n\t}" : "=r"(_done) : "r"(_mbar), "r"(_par) : "memory"); \
    if (!_done) { \
        asm volatile("{\n\t.reg .pred P1;\n\t" \
            "WAIT_LOOP_%=:\n\t" \
            "mbarrier.try_wait.parity.acquire.cta.shared::cta.b64 P1, [%0], %1, 0x989680;\n\t" \
            "@P1 bra.uni WAIT_DONE_%=;\n\t" \
            "bra.uni WAIT_LOOP_%=;\n\t" \
            "WAIT_DONE_%=:\n\t}" :: "r"(_mbar), "r"(_par) : "memory"); \
    } \
} while (0)

#if HAS_TC
#define TCGEN05_ALLOC(smem_addr, nCols) \
    asm volatile("tcgen05.alloc.cta_group::1.sync.aligned.shared::cta.b32 [%0], %1;" \
        :: "r"((uint32_t)(smem_addr)), "r"((uint32_t)(nCols)) : "memory")
#define TCGEN05_DEALLOC(tmem, nCols) \
    asm volatile("tcgen05.dealloc.cta_group::1.sync.aligned.b32 %0, %1;" :: "r"(tmem), "r"((uint32_t)(nCols)))
#define TCGEN05_COMMIT(mbar) \
    asm volatile("tcgen05.commit.cta_group::1.mbarrier::arrive::one.shared::cluster.b64 [%0];" \
        :: "r"((uint32_t)(mbar)) : "memory")
#define TCGEN05_FENCE_AFTER() asm volatile("tcgen05.fence::after_thread_sync;" ::: "memory")
#define TCGEN05_WAIT_LD() asm volatile("tcgen05.wait::ld.sync.aligned;" ::: "memory")

#define TCGEN05_LD_32X32B_X32(r, tmem_addr) \
    asm volatile( \
        "tcgen05.ld.sync.aligned.32x32b.x32.b32 " \
        "{%0, %1, %2, %3, %4, %5, %6, %7, " \
        " %8, %9, %10, %11, %12, %13, %14, %15, " \
        " %16, %17, %18, %19, %20, %21, %22, %23, " \
        " %24, %25, %26, %27, %28, %29, %30, %31}, [%32];" \
        : "=r"((r)[0]),  "=r"((r)[1]),  "=r"((r)[2]),  "=r"((r)[3]), \
          "=r"((r)[4]),  "=r"((r)[5]),  "=r"((r)[6]),  "=r"((r)[7]), \
          "=r"((r)[8]),  "=r"((r)[9]),  "=r"((r)[10]), "=r"((r)[11]), \
          "=r"((r)[12]), "=r"((r)[13]), "=r"((r)[14]), "=r"((r)[15]), \
          "=r"((r)[16]), "=r"((r)[17]), "=r"((r)[18]), "=r"((r)[19]), \
          "=r"((r)[20]), "=r"((r)[21]), "=r"((r)[22]), "=r"((r)[23]), \
          "=r"((r)[24]), "=r"((r)[25]), "=r"((r)[26]), "=r"((r)[27]), \
          "=r"((r)[28]), "=r"((r)[29]), "=r"((r)[30]), "=r"((r)[31]) \
        : "r"(tmem_addr))

__device__ __forceinline__ void mma_bf16_ss(uint32_t d, uint64_t ad, uint64_t bd,
                                            uint32_t idesc, uint32_t en) {
    asm volatile(
        "{\n\t.reg .pred p;\n\tsetp.ne.u32 p, %5, 0;\n\t"
        "tcgen05.mma.cta_group::1.kind::f16 [%0], %1, %2, %3, {%4, %4, %4, %4}, p;\n\t}"
        :: "r"(d), "l"(ad), "l"(bd), "r"(idesc), "r"(0u), "r"(en) : "memory");
}
__device__ __forceinline__ uint32_t elect1() {
    uint32_t r;
    asm volatile("{\n\t.reg .pred p;\n\telect.sync _|p, 0xFFFFFFFF;\n\tselp.b32 %0, 1, 0, p;\n\t}" : "=r"(r));
    return r;
}
#endif // HAS_TC

// staged-activation addressing
__device__ __forceinline__ void stageA_write(char* S, int NCc, int row, int col, float v) {
    bf16 h = __float2bfloat16(v);
    bf16 l = __float2bfloat16(v - __bfloat162float(h));
    size_t blk = (size_t)((row >> 7) * NCc + (col >> 5)) * 16384;
    uint32_t o = SW64((uint32_t)((row & 127) * 64 + (col & 31) * 2));
    *(bf16*)(S + blk + o) = h;
    *(bf16*)(S + blk + 8192 + o) = l;
}
__device__ __forceinline__ float stageA_read(const char* S, int NCc, int row, int col) {
    size_t blk = (size_t)((row >> 7) * NCc + (col >> 5)) * 16384;
    uint32_t o = SW64((uint32_t)((row & 127) * 64 + (col & 31) * 2));
    return __bfloat162float(*(const bf16*)(S + blk + o)) +
           __bfloat162float(*(const bf16*)(S + blk + 8192 + o));
}

// ---------------- prep kernels ----------------
__global__ void splitX_kernel(const float* __restrict__ X, char* __restrict__ XS) {
    size_t i = (size_t)blockIdx.x * 256 + threadIdx.x;
    if (i < (size_t)BNR * IND) {
        int row = (int)(i / IND), k = (int)(i - (size_t)row * IND);
        stageA_write(XS, 24, row, k, X[i]);
    }
}

__device__ __forceinline__ void tstage_one(const float* W, char* S, int i,
                                           int Kw, int NC, int rowOff, int ldW) {
    int n = i / Kw, k = i - n * Kw;
    float v = W[(size_t)(rowOff + k) * ldW + n];
    bf16 h = __float2bfloat16(v);
    bf16 l = __float2bfloat16(v - __bfloat162float(h));
    int ntile = n >> 8, lrow = n & 255;
    int chunk = k >> 5, kin = k & 31;
    uint32_t o = SW64((uint32_t)(lrow * 64 + kin * 2));
    size_t blk = (size_t)(ntile * NC + chunk) * 32768;
    *(bf16*)(S + blk + o) = h;
    *(bf16*)(S + blk + 16384 + o) = l;
}
__device__ __forceinline__ void h2stage_one(const float* W, char* S, int i) {
    int n = i / PAIRD, k = i - n * PAIRD;
    float v = W[(size_t)k * (PAIRD / 2) + n];
    bf16 h = __float2bfloat16(v);
    bf16 l = __float2bfloat16(v - __bfloat162float(h));
    int chunk = k >> 5, kin = k & 31;
    uint32_t o = SW64((uint32_t)(n * 64 + kin * 2));
    size_t blk = (size_t)chunk * 51200;
    *(bf16*)(S + blk + o) = h;
    *(bf16*)(S + blk + 25600 + o) = l;
}

#define TS0 (IND * HIDD)
#define TS1 (TS0 + HIDD * OUTD)
#define TS2 (TS1 + OUTD * OUTD)
#define TS3 (TS2 + OUTD * PAIRD)
#define TS4 (TS3 + OUTD * PAIRD)
#define TS5 (TS4 + PAIRD * (PAIRD/2))
__global__ void tsplit_all_kernel(
    const float* __restrict__ enc_w1, const float* __restrict__ enc_w2,
    const float* __restrict__ gat_w, const float* __restrict__ h_w1,
    const float* __restrict__ h_w2,
    char* w1tS, char* w2tS, char* wgtS, char* w1aS, char* w1bS, char* h2BS,
    int* counts)
{
    int i = blockIdx.x * 256 + threadIdx.x;
    if (i < NN) counts[i] = 0;
    if (i < TS0)      tstage_one(enc_w1, w1tS, i,        IND,  24, 0,    HIDD);
    else if (i < TS1) tstage_one(enc_w2, w2tS, i - TS0,  HIDD, 16, 0,    OUTD);
    else if (i < TS2) tstage_one(gat_w,  wgtS, i - TS1,  OUTD, 13, 0,    OUTD);
    else if (i < TS3) tstage_one(h_w1,   w1aS, i - TS2,  OUTD, 13, 0,    PAIRD);
    else if (i < TS4) tstage_one(h_w1,   w1bS, i - TS3,  OUTD, 13, OUTD, PAIRD);
    else if (i < TS5) h2stage_one(h_w2,  h2BS, i - TS4);
}

// ---------------- split-bf16 tcgen05 GEMM, BM=128, BN<=256, BK=32, SW64 ----------------
// Both A and B staged pre-swizzled in gmem -> per chunk: 2 bulk copies, zero per-thread issue.
#define MM_HDR   8192
#define MM_ASTG  16384
#define MM_BSTG  32768
#define MM_STG   (MM_ASTG + MM_BSTG)
#define MM_NSTG  4
#define SMEM_TOTAL_MM (MM_HDR + MM_NSTG * MM_STG)   // 204800
#define CPITCH 65

template<bool BIAS, bool GELU_, bool WF32, bool WHILO>
__global__ __launch_bounds__(256, 1) void mm_kernel(
    const char* __restrict__ Astg,
    const char* __restrict__ Bstg,
    const float* __restrict__ bias,
    float* __restrict__ Cf, char* __restrict__ Cstg,
    int N, int K, int NCc)
{
#if HAS_TC
    extern __shared__ char dsm[];
    const int tid = threadIdx.x;
    const int wid = tid >> 5;
    const uint32_t sb = smem_u32(dsm);
    const int mBase = blockIdx.y * 128;
    const int nBase = blockIdx.x * 256;
    const int nValid = min(256, N - nBase);
    const int NC = (K + 31) >> 5;

    if (tid == 0) {
        for (int i = 0; i < 4; i++) { MBARRIER_INIT(sb + 16 + i * 8, 1); MBARRIER_INIT(sb + 48 + i * 8, 1); }
    }
    if (wid == 0) TCGEN05_ALLOC(sb, 256);
    __syncthreads();
    uint32_t tmem;
    asm volatile("ld.shared.b32 %0, [%1];" : "=r"(tmem) : "r"(sb));

    const uint32_t idesc = (1u << 4) | (1u << 7) | (1u << 10) |
                           ((uint32_t)(nValid >> 3) << 17) | (8u << 24);

    // single-thread producer/MMA pipeline; tid0 alone waits the final commit
    if (tid == 0) {
        auto prep = [&](int cc) {
            if (cc >= MM_NSTG)
                MBARRIER_WAIT_PARITY(sb + 16 + (cc & 3) * 8, ((cc - MM_NSTG) >> 2) & 1);
            uint32_t stg = sb + MM_HDR + (cc & 3) * MM_STG;
            uint32_t fb = sb + 48 + (cc & 3) * 8;
            MBARRIER_EXPECT_TX(fb, 49152u);
            bulk_cp(stg, Astg + ((size_t)(blockIdx.y * NC + cc)) * 16384, 16384u, fb);
            bulk_cp(stg + 16384, Bstg + ((size_t)(blockIdx.x * NC + cc)) * 32768, 32768u, fb);
        };
        prep(0);
        if (NC > 1) prep(1);
        for (int c = 0; c < NC; c++) {
            if (c + 2 < NC) prep(c + 2);
            MBARRIER_WAIT_PARITY(sb + 48 + (c & 3) * 8, (c >> 2) & 1);   // A+B full
            uint32_t stg = sb + MM_HDR + (c & 3) * MM_STG;
            uint64_t dAh = mk_desc64(stg);
            uint64_t dAl = mk_desc64(stg + 8192);
            uint64_t dBh = mk_desc64(stg + 16384);
            uint64_t dBl = mk_desc64(stg + 32768);
            int ksteps = min(2, (K - (c << 5)) >> 4);
            for (int ks = 0; ks < ksteps; ks++) {
                uint64_t o = (uint64_t)(ks * 2);
                mma_bf16_ss(tmem, dAh + o, dBh + o, idesc, (c | ks) ? 1u : 0u);
                mma_bf16_ss(tmem, dAh + o, dBl + o, idesc, 1u);
                mma_bf16_ss(tmem, dAl + o, dBh + o, idesc, 1u);
            }
            TCGEN05_COMMIT(sb + 16 + (c & 3) * 8);
        }
        // FIX (round-15 NaN): only tid0 may parity-wait here. Its program order
        // guarantees the barrier sits at the opposite parity until the true
        // final commit completes. Other threads are released by __syncthreads.
        MBARRIER_WAIT_PARITY(sb + 16 + ((NC - 1) & 3) * 8, ((NC - 1) >> 2) & 1);
    }
    __syncthreads();
    TCGEN05_FENCE_AFTER();

    // ---- epilogue ----
    {
        int sub = wid & 3, cg = wid >> 2;
        int lane = tid & 31;
        float* cst = (float*)(dsm + MM_HDR);
        for (int cb0 = 0; cb0 < nValid; cb0 += 64) {
            int cb = cb0 + cg * 32;
            if (cb < nValid) {
                uint32_t regs[32];
                TCGEN05_LD_32X32B_X32(regs, tmem + cb);
                TCGEN05_WAIT_LD();
                int r = sub * 32 + lane;
#pragma unroll
                for (int j = 0; j < 32; j++) {
                    int col = cb + j;
                    if (col < nValid) {
                        float v = __uint_as_float(regs[j]);
                        if (BIAS) v += bias[nBase + col];
                        if (GELU_) v = gelu_tanh(v);
                        cst[r * CPITCH + (cg * 32 + j)] = v;
                    }
                }
            }
            __syncthreads();
            int cw = min(64, nValid - cb0);
            for (int i = tid; i < 128 * cw; i += 256) {
                int row = i / cw, col = i - row * cw;
                float v = cst[row * CPITCH + col];
                int gr = mBase + row;
                int gc = nBase + cb0 + col;
                if (WF32) Cf[(size_t)gr * N + gc] = v;
                if (WHILO) stageA_write(Cstg, NCc, gr, gc, v);
            }
            __syncthreads();
        }
    }
    __syncthreads();
    if (wid == 0) TCGEN05_DEALLOC(tmem, 256);

#else // !HAS_TC — naive correct fallback
    const int tid = threadIdx.x;
    const int mBase = blockIdx.y * 128;
    const int nBase = blockIdx.x * 256;
    const int nValid = min(256, N - nBase);
    const int NC = (K + 31) >> 5;
    if (tid >= 128) return;
    int row = mBase + tid;
    for (int col = 0; col < nValid; col++) {
        int gc = nBase + col;
        float acc = 0.f;
        for (int k = 0; k < K; k++) {
            float a = stageA_read(Astg, NC, row, k);
            int ntile = blockIdx.x, lrow = col;
            size_t blk = (size_t)(ntile * NC + (k >> 5)) * 32768;
            uint32_t o = SW64((uint32_t)(lrow * 64 + (k & 31) * 2));
            float bb = __bfloat162float(*(const bf16*)(Bstg + blk + o)) +
                       __bfloat162float(*(const bf16*)(Bstg + blk + 16384 + o));
            acc += a * bb;
        }
        if (BIAS) acc += bias[gc];
        if (GELU_) acc = gelu_tanh(acc);
        if (WF32) Cf[(size_t)row * N + gc] = acc;
        if (WHILO) stageA_write(Cstg, NCc, row, gc, acc);
    }
#endif
}

// ---------------- fused head2 (BK=32, SW64, bulk-B pipelined) ----------------
#define H2_HDR   12288
#define H2_ASTG  16384
#define H2_BSTG  51200
#define H2_ABASE H2_HDR
#define H2_BBASE (H2_HDR + 4 * H2_ASTG)
#define H2_SMEM  (H2_BBASE + 3 * H2_BSTG)    // 231424
#define H2_MB_FULL 10752

__global__ __launch_bounds__(256, 1) void head2_kernel(
    const float* __restrict__ U, const float* __restrict__ V,
    const char* __restrict__ BS,
    const float* __restrict__ b1, const float* __restrict__ b2,
    const float* __restrict__ w3, const float* __restrict__ b3,
    const int* __restrict__ src0, const int* __restrict__ dst0,
    float* __restrict__ pred)
{
#if HAS_TC
    extern __shared__ char dsm[];
    const int tid = threadIdx.x;
    const int wid = tid >> 5;
    const uint32_t sb = smem_u32(dsm);
    const int mBase = blockIdx.x * 128;
    const int NC = 25;
    int* sSrc = (int*)(dsm + 64);
    int* sDst = (int*)(dsm + 576);
    float* sw3 = (float*)(dsm + 1152);
    float* b1s = (float*)(dsm + 5952);
    float* b2s = (float*)(dsm + 9152);

    if (tid == 0) {
        for (int i = 0; i < 4; i++) {
            MBARRIER_INIT(sb + 16 + i * 8, 1);
            MBARRIER_INIT(sb + H2_MB_FULL + i * 8, 1);
        }
    }
    if (wid == 0) TCGEN05_ALLOC(sb, 512);
    if (tid < 128) {
        int r = mBase + tid;
        int e = r & (EE - 1), b = r >> 14;
        sSrc[tid] = (b << 10) + src0[e];
        sDst[tid] = (b << 10) + dst0[e];
    }
    for (int i = tid; i < 1200; i += 256) sw3[i] = w3[i];
    for (int i = tid; i < 800; i += 256) b1s[i] = b1[i];
    for (int i = tid; i < 400; i += 256) b2s[i] = b2[i];
    __syncthreads();
    uint32_t tmem;
    asm volatile("ld.shared.b32 %0, [%1];" : "=r"(tmem) : "r"(sb));

    const uint32_t idesc = (1u << 4) | (1u << 7) | (1u << 10) | (25u << 17) | (8u << 24);

    auto wait_commit = [&](int j) {
        MBARRIER_WAIT_PARITY(sb + 16 + (j & 3) * 8, (j >> 2) & 1);
    };
    auto prep = [&](int cc) {
        int k0 = cc * 32;
        if (cc >= 4) wait_commit(cc - 4);
        char* astg = dsm + H2_ABASE + (cc & 3) * H2_ASTG;
#pragma unroll
        for (int i = 0; i < 2; i++) {
            int idx = i * 256 + tid;
            int row = idx >> 2, seg = idx & 3;
            int col = k0 + seg * 8;
            int sn = sSrc[row], dn = sDst[row];
            const float* up = U + (size_t)sn * PAIRD + col;
            const float* vp = V + (size_t)dn * PAIRD + col;
            float4 u0 = *(const float4*)up, u1 = *(const float4*)(up + 4);
            float4 v0 = *(const float4*)vp, v1 = *(const float4*)(vp + 4);
            float4 c0 = *(const float4*)(b1s + col);
            float4 c1 = *(const float4*)(b1s + col + 4);
            float r8[8];
            r8[0] = gelu_tanh(u0.x + v0.x + c0.x);
            r8[1] = gelu_tanh(u0.y + v0.y + c0.y);
            r8[2] = gelu_tanh(u0.z + v0.z + c0.z);
            r8[3] = gelu_tanh(u0.w + v0.w + c0.w);
            r8[4] = gelu_tanh(u1.x + v1.x + c1.x);
            r8[5] = gelu_tanh(u1.y + v1.y + c1.y);
            r8[6] = gelu_tanh(u1.z + v1.z + c1.z);
            r8[7] = gelu_tanh(u1.w + v1.w + c1.w);
            uint32_t hw[4], lw[4];
#pragma unroll
            for (int q = 0; q < 4; q++) {
                bf16 h0 = __float2bfloat16(r8[q*2+0]);
                bf16 h1 = __float2bfloat16(r8[q*2+1]);
                bf16 l0 = __float2bfloat16(r8[q*2+0] - __bfloat162float(h0));
                bf16 l1 = __float2bfloat16(r8[q*2+1] - __bfloat162float(h1));
                hw[q] = ((uint32_t)__bfloat16_as_ushort(h1) << 16) | __bfloat16_as_ushort(h0);
                lw[q] = ((uint32_t)__bfloat16_as_ushort(l1) << 16) | __bfloat16_as_ushort(l0);
            }
            uint32_t sw = SW64(row * 64 + seg * 16);
            *(uint4*)(astg + sw) = make_uint4(hw[0], hw[1], hw[2], hw[3]);
            *(uint4*)(astg + 8192 + sw) = make_uint4(lw[0], lw[1], lw[2], lw[3]);
        }
        if (cc >= 3) wait_commit(cc - 3);
        if (tid == 0) {
            uint32_t fb = sb + H2_MB_FULL + (cc & 3) * 8;
            MBARRIER_EXPECT_TX(fb, 51200u);
            bulk_cp(sb + H2_BBASE + (cc % 3) * H2_BSTG, BS + (size_t)cc * 51200, 51200u, fb);
        }
    };

    prep(0);
    prep(1);
    for (int c = 0; c < NC; c++) {
        if (c + 2 < NC) prep(c + 2);
        asm volatile("fence.proxy.async.shared::cta;" ::: "memory");
        __syncthreads();
        if (wid == 0 && elect1()) {
            MBARRIER_WAIT_PARITY(sb + H2_MB_FULL + (c & 3) * 8, (c >> 2) & 1);
            uint32_t ag = sb + H2_ABASE + (c & 3) * H2_ASTG;
            uint64_t dAh = mk_desc64(ag);
            uint64_t dAl = mk_desc64(ag + 8192);
            uint32_t bg = sb + H2_BBASE + (c % 3) * H2_BSTG;
#pragma unroll
            for (int half = 0; half < 2; half++) {
                uint64_t dBh = mk_desc64(bg + half * 12800);
                uint64_t dBl = mk_desc64(bg + 25600 + half * 12800);
                uint32_t d = tmem + half * 200;
#pragma unroll
                for (int ks = 0; ks < 2; ks++) {
                    uint64_t o = (uint64_t)(ks * 2);
                    mma_bf16_ss(d, dAh + o, dBh + o, idesc, (c | ks) ? 1u : 0u);
                    mma_bf16_ss(d, dAh + o, dBl + o, idesc, 1u);
                    mma_bf16_ss(d, dAl + o, dBh + o, idesc, 1u);
                }
            }
            TCGEN05_COMMIT(sb + 16 + (c & 3) * 8);
        }
    }
    wait_commit(NC - 1);
    TCGEN05_FENCE_AFTER();

    // ---- epilogue: gelu(.+b2) dot W3 -> pred ----
    {
        int sub = wid & 3, cg = wid >> 2;
        int lane = tid & 31;
        float* cst = (float*)(dsm + H2_HDR);
        float d0 = 0.f, d1 = 0.f, d2 = 0.f;
        for (int cb0 = 0; cb0 < 400; cb0 += 64) {
            int cb = cb0 + cg * 32;
            if (cb < 400) {
                uint32_t regs[32];
                TCGEN05_LD_32X32B_X32(regs, tmem + cb);
                TCGEN05_WAIT_LD();
                int r = sub * 32 + lane;
#pragma unroll
                for (int j = 0; j < 32; j++) {
                    int col = cb + j;
                    if (col < 400) {
                        float v = __uint_as_float(regs[j]) + b2s[col];
                        v = gelu_tanh(v);
                        cst[r * CPITCH + (cg * 32 + j)] = v;
                    }
                }
            }
            __syncthreads();
            int cw = min(64, 400 - cb0);
            if (tid < 128) {
                for (int col = 0; col < cw; col++) {
                    float v = cst[tid * CPITCH + col];
                    int wc = (cb0 + col) * 3;
                    d0 += v * sw3[wc + 0];
                    d1 += v * sw3[wc + 1];
                    d2 += v * sw3[wc + 2];
                }
            }
            __syncthreads();
        }
        if (tid < 128) {
            size_t r = (size_t)(mBase + tid);
            pred[r * 3 + 0] = d0 + b3[0];
            pred[r * 3 + 1] = d1 + b3[1];
            pred[r * 3 + 2] = d2 + b3[2];
        }
    }
    __syncthreads();
    if (wid == 0) TCGEN05_DEALLOC(tmem, 512);

#else // !HAS_TC — naive correct fallback
    const int tid = threadIdx.x;
    const int mBase = blockIdx.x * 128;
    if (tid >= 128) return;
    int row = mBase + tid;
    int e = row & (EE - 1), b = row >> 14;
    int sn = (b << 10) + src0[e];
    int dn = (b << 10) + dst0[e];
    float d0 = 0.f, d1 = 0.f, d2 = 0.f;
    for (int col = 0; col < 400; col++) {
        float acc = 0.f;
        for (int k = 0; k < PAIRD; k++) {
            float a = gelu_tanh(U[(size_t)sn * PAIRD + k] + V[(size_t)dn * PAIRD + k] + b1[k]);
            size_t blk = (size_t)(k >> 5) * 51200;
            uint32_t o = SW64((uint32_t)(col * 64 + (k & 31) * 2));
            float bb = __bfloat162float(*(const bf16*)(BS + blk + o)) +
                       __bfloat162float(*(const bf16*)(BS + blk + 25600 + o));
            acc += a * bb;
        }
        acc = gelu_tanh(acc + b2[col]);
        d0 += acc * w3[col * 3 + 0];
        d1 += acc * w3[col * 3 + 1];
        d2 += acc * w3[col * 3 + 2];
    }
    pred[(size_t)row * 3 + 0] = d0 + b3[0];
    pred[(size_t)row * 3 + 1] = d1 + b3[1];
    pred[(size_t)row * 3 + 2] = d2 + b3[2];
#endif
}

// ---------------- attention scores ----------------
__global__ void attn_score_kernel(const float* __restrict__ wh,
                                  const float* __restrict__ att_src,
                                  const float* __restrict__ att_dst,
                                  float* __restrict__ as_, float* __restrict__ ad_)
{
    int bn = blockIdx.x;
    int h = threadIdx.x >> 5, lane = threadIdx.x & 31;
    const float* w = wh + (size_t)bn * OUTD + h * 200;
    float s = 0.f, d = 0.f;
    for (int f = lane; f < 200; f += 32) {
        float v = w[f];
        s += v * att_src[h * 200 + f];
        d += v * att_dst[h * 200 + f];
    }
#pragma unroll
    for (int o = 16; o; o >>= 1) {
        s += __shfl_down_sync(0xffffffffu, s, o);
        d += __shfl_down_sync(0xffffffffu, d, o);
    }
    if (lane == 0) { as_[bn * 2 + h] = s; ad_[bn * 2 + h] = d; }
}

// ---------------- CSR build ----------------
__global__ void count_kernel(const int* __restrict__ edges, int* __restrict__ counts) {
    int et = blockIdx.x * 256 + threadIdx.x;
    if (et >= ETOT) return;
    int dst = (et < EE) ? edges[EE + et] : (et - EE);
    atomicAdd(&counts[dst], 1);
}

__global__ void scan_kernel(const int* __restrict__ counts, int* __restrict__ rowstart,
                            int* __restrict__ fill) {
    __shared__ int s[NN];
    int t = threadIdx.x;
    int c = counts[t];
    s[t] = c;
    __syncthreads();
    for (int o = 1; o < NN; o <<= 1) {
        int v = (t >= o) ? s[t - o] : 0;
        __syncthreads();
        s[t] += v;
        __syncthreads();
    }
    rowstart[t + 1] = s[t];
    if (t == 0) rowstart[0] = 0;
    fill[t] = s[t] - c;
}

__global__ void scatter_kernel(const int* __restrict__ edges, int* __restrict__ fill,
                               int* __restrict__ csrsrc) {
    int et = blockIdx.x * 256 + threadIdx.x;
    if (et >= ETOT) return;
    int src = (et < EE) ? edges[et] : (et - EE);
    int dst = (et < EE) ? edges[EE + et] : (et - EE);
    int pos = atomicAdd(&fill[dst], 1);
    csrsrc[pos] = src;
}

// ---------------- GAT: warp-per-node, shuffle-only ----------------
__global__ void gat_kernel(const float* __restrict__ wh, const float* __restrict__ as_,
                           const float* __restrict__ ad_, const float* __restrict__ enc,
                           const float* __restrict__ gat_b,
                           const int* __restrict__ rowstart, const int* __restrict__ csrsrc,
                           float* __restrict__ feat, char* __restrict__ featS)
{
    int w = threadIdx.x >> 5, lane = threadIdx.x & 31;
    int bn = blockIdx.x * 8 + w;
    int b = bn >> 10, n = bn & 1023;
    int start = rowstart[n];
    int deg = rowstart[n + 1] - start;
    float ad0 = ad_[bn * 2 + 0], ad1 = ad_[bn * 2 + 1];

    float m0 = -1e30f, m1 = -1e30f;
    for (int i = lane; i < deg; i += 32) {
        int sb2 = (b << 10) + csrsrc[start + i];
        float e0 = as_[sb2 * 2 + 0] + ad0; e0 = (e0 > 0.f) ? e0 : 0.2f * e0;
        float e1 = as_[sb2 * 2 + 1] + ad1; e1 = (e1 > 0.f) ? e1 : 0.2f * e1;
        m0 = fmaxf(m0, e0); m1 = fmaxf(m1, e1);
    }
#pragma unroll
    for (int o = 16; o; o >>= 1) {
        m0 = fmaxf(m0, __shfl_xor_sync(0xffffffffu, m0, o));
        m1 = fmaxf(m1, __shfl_xor_sync(0xffffffffu, m1, o));
    }
    float z0 = 0.f, z1 = 0.f;
    for (int i = lane; i < deg; i += 32) {
        int sb2 = (b << 10) + csrsrc[start + i];
        float e0 = as_[sb2 * 2 + 0] + ad0; e0 = (e0 > 0.f) ? e0 : 0.2f * e0;
        float e1 = as_[sb2 * 2 + 1] + ad1; e1 = (e1 > 0.f) ? e1 : 0.2f * e1;
        z0 += expf(e0 - m0);
        z1 += expf(e1 - m1);
    }
#pragma unroll
    for (int o = 16; o; o >>= 1) {
        z0 += __shfl_xor_sync(0xffffffffu, z0, o);
        z1 += __shfl_xor_sync(0xffffffffu, z1, o);
    }
    float inv0 = 1.f / z0, inv1 = 1.f / z1;

    float acc[13];
#pragma unroll
    for (int j = 0; j < 13; j++) acc[j] = 0.f;
    for (int i = 0; i < deg; i++) {
        int sb2 = (b << 10) + csrsrc[start + i];
        float e0 = as_[sb2 * 2 + 0] + ad0; e0 = (e0 > 0.f) ? e0 : 0.2f * e0;
        float e1 = as_[sb2 * 2 + 1] + ad1; e1 = (e1 > 0.f) ? e1 : 0.2f * e1;
        float c0 = expf(e0 - m0) * inv0;
        float c1 = expf(e1 - m1) * inv1;
        const float* row = wh + (size_t)sb2 * OUTD;
#pragma unroll
        for (int j = 0; j < 13; j++) {
            int col = lane + 32 * j;
            if (col < OUTD) acc[j] += ((col < 200) ? c0 : c1) * row[col];
        }
    }
    size_t base = (size_t)bn * OUTD;
#pragma unroll
    for (int j = 0; j < 13; j++) {
        int col = lane + 32 * j;
        if (col < OUTD) {
            float v = enc[base + col] + acc[j] + gat_b[col];
            feat[base + col] = v;
            stageA_write(featS, 13, bn, col, v);
        }
    }
}

// ---------------- launch ----------------
extern "C" void kernel_launch(void* const* d_in, const int* in_sizes, int n_in,
                              void* d_out, int out_size)
{
    const float* X       = (const float*)d_in[0];
    const int*   edges   = (const int*)  d_in[1];
    const float* enc_w1  = (const float*)d_in[2];
    const float* enc_b1  = (const float*)d_in[3];
    const float* enc_w2  = (const float*)d_in[4];
    const float* enc_b2  = (const float*)d_in[5];
    const float* gat_w   = (const float*)d_in[6];
    const float* att_src = (const float*)d_in[7];
    const float* att_dst = (const float*)d_in[8];
    const float* gat_b   = (const float*)d_in[9];
    const float* h_w1    = (const float*)d_in[10];
    const float* h_b1    = (const float*)d_in[11];
    const float* h_w2    = (const float*)d_in[12];
    const float* h_b2    = (const float*)d_in[13];
    const float* h_w3    = (const float*)d_in[14];
    const float* h_b3    = (const float*)d_in[15];

    float* out  = (float*)d_out;
    float* feat = out;
    float* pred = out + FEAT_ELEMS;

    char *XS, *hidS, *encS, *featS;
    char *w1tS, *w2tS, *wgtS, *w1aS, *w1bS, *h2BS;
    float *enc, *wh, *as_, *ad_, *U, *V;
    int *counts, *rowstart, *fill, *csrsrc;
    cudaGetSymbolAddress((void**)&XS, g_XS);         cudaGetSymbolAddress((void**)&hidS, g_hidS);
    cudaGetSymbolAddress((void**)&encS, g_encS);     cudaGetSymbolAddress((void**)&featS, g_featS);
    cudaGetSymbolAddress((void**)&enc, g_enc);       cudaGetSymbolAddress((void**)&wh, g_wh);
    cudaGetSymbolAddress((void**)&U, g_U);           cudaGetSymbolAddress((void**)&V, g_V);
    cudaGetSymbolAddress((void**)&w1tS, g_w1tS);     cudaGetSymbolAddress((void**)&w2tS, g_w2tS);
    cudaGetSymbolAddress((void**)&wgtS, g_wgtS);     cudaGetSymbolAddress((void**)&w1aS, g_w1aS);
    cudaGetSymbolAddress((void**)&w1bS, g_w1bS);     cudaGetSymbolAddress((void**)&h2BS, g_h2BS);
    cudaGetSymbolAddress((void**)&as_, g_as);        cudaGetSymbolAddress((void**)&ad_, g_ad);
    cudaGetSymbolAddress((void**)&counts, g_counts); cudaGetSymbolAddress((void**)&rowstart, g_rowstart);
    cudaGetSymbolAddress((void**)&fill, g_fill);     cudaGetSymbolAddress((void**)&csrsrc, g_csrsrc);

    const int* src0 = edges;
    const int* dst0 = edges + EE;

    cudaFuncSetAttribute(mm_kernel<true ,true ,false,true >, cudaFuncAttributeMaxDynamicSharedMemorySize, SMEM_TOTAL_MM);
    cudaFuncSetAttribute(mm_kernel<true ,false,true ,true >, cudaFuncAttributeMaxDynamicSharedMemorySize, SMEM_TOTAL_MM);
    cudaFuncSetAttribute(mm_kernel<false,false,true ,false>, cudaFuncAttributeMaxDynamicSharedMemorySize, SMEM_TOTAL_MM);
    cudaFuncSetAttribute(head2_kernel, cudaFuncAttributeMaxDynamicSharedMemorySize, H2_SMEM);

    // 1) stage all weights + zero counts
    tsplit_all_kernel<<<(TS5 + 255) / 256, 256>>>(
        enc_w1, enc_w2, gat_w, h_w1, h_w2,
        w1tS, w2tS, wgtS, w1aS, w1bS, h2BS, counts);
    // 2) stage X
    {
        size_t nX = (size_t)BNR * IND;
        splitX_kernel<<<(unsigned)((nX + 255) / 256), 256>>>(X, XS);
    }
    // 3) CSR count
    count_kernel<<<(ETOT + 255) / 256, 256>>>(edges, counts);
    // 4) enc1  <-- profiled launch (ncu 6th launch == our 4th)
    mm_kernel<true,true,false,true><<<dim3(2, BNR/128), 256, SMEM_TOTAL_MM>>>(
        XS, w1tS, enc_b1, nullptr, hidS, HIDD, IND, 16);
    // 5-6) CSR scan + scatter
    scan_kernel<<<1, NN>>>(counts, rowstart, fill);
    scatter_kernel<<<(ETOT + 255) / 256, 256>>>(edges, fill, csrsrc);
    // 7) enc2
    mm_kernel<true,false,true,true><<<dim3(2, BNR/128), 256, SMEM_TOTAL_MM>>>(
        hidS, w2tS, enc_b2, enc, encS, OUTD, HIDD, 13);
    // 8) wh
    mm_kernel<false,false,true,false><<<dim3(2, BNR/128), 256, SMEM_TOTAL_MM>>>(
        encS, wgtS, nullptr, wh, nullptr, OUTD, OUTD, 0);
    // 9) attention scores
    attn_score_kernel<<<BNR, 64>>>(wh, att_src, att_dst, as_, ad_);
    // 10) GAT (warp-per-node) -> feat f32 (output) + featS
    gat_kernel<<<BNR / 8, 256>>>(wh, as_, ad_, enc, gat_b, rowstart, csrsrc, feat, featS);
    // 11) U = feat @ W1top
    mm_kernel<false,false,true,false><<<dim3(4, BNR/128), 256, SMEM_TOTAL_MM>>>(
        featS, w1aS, nullptr, U, nullptr, PAIRD, OUTD, 0);
    // 12) V = feat @ W1bot
    mm_kernel<false,false,true,false><<<dim3(4, BNR/128), 256, SMEM_TOTAL_MM>>>(
        featS, w1bS, nullptr, V, nullptr, PAIRD, OUTD, 0);
    // 13) head2 fused -> pred
    head2_kernel<<<BER / 128, 256, H2_SMEM>>>(
        U, V, h2BS, h_b1, h_b2, h_w3, h_b3, src0, dst0, pred);
}

// round 17
// speedup vs baseline: 1.5909x; 1.0183x over previous
#include <cuda_runtime.h>
#include <cuda_bf16.h>
#include <math.h>
#include <stdint.h>
#include <stddef.h>

// Problem constants
#define BB 32
#define NN 1024
#define EE 16384
#define ETOT (EE + NN)
#define IND 768
#define HIDD 512
#define OUTD 400
#define PAIRD 800
#define BNR (BB * NN)          // 32768
#define BER (BB * EE)          // 524288
#define FEAT_ELEMS ((size_t)BNR * OUTD)

typedef __nv_bfloat16 bf16;

#if defined(__CUDA_ARCH_FEAT_SM103_ALL) || defined(__CUDA_ARCH_FEAT_SM100_ALL) || defined(__CUDA_ARCH_FEAT_SM101_ALL)
#define HAS_TC 1
#else
#define HAS_TC 0
#endif

// ---------------- device scratch ----------------
// staged activations: [mtile(=row>>7)][chunk(=k>>5)][hi 8KB | lo 8KB], SW64 baked in
__device__ uint4 g_XS  [(size_t)256 * 24 * 16384 / 16];   // X    K=768
__device__ uint4 g_hidS[(size_t)256 * 16 * 16384 / 16];   // hid  K=512
__device__ uint4 g_encS[(size_t)256 * 13 * 16384 / 16];   // enc  K=400
__device__ uint4 g_featS[(size_t)256 * 13 * 16384 / 16];  // feat K=400
__device__ float g_enc[(size_t)BNR * OUTD];
__device__ float g_wh[(size_t)BNR * OUTD];
__device__ float g_U[(size_t)BNR * PAIRD];
__device__ float g_V[(size_t)BNR * PAIRD];
// staged weights: [ntile][chunk][hi 16KB | lo 16KB]
__device__ uint4 g_w1tS[(size_t)2 * 24 * 32768 / 16];
__device__ uint4 g_w2tS[(size_t)2 * 16 * 32768 / 16];
__device__ uint4 g_wgtS[(size_t)2 * 13 * 32768 / 16];
__device__ uint4 g_w1aS[(size_t)4 * 13 * 32768 / 16];
__device__ uint4 g_w1bS[(size_t)4 * 13 * 32768 / 16];
__device__ uint4 g_h2BS[(size_t)25 * 51200 / 16];
__device__ float g_as[BNR * 2], g_ad[BNR * 2];
__device__ int   g_counts[NN], g_rowstart[NN + 1], g_fill[NN], g_csrsrc[ETOT];

// tanhf lowers to the HW MUFU.TANH path on sm_103a (round-8 isolation test).
__device__ __forceinline__ float gelu_tanh(float x) {
    const float c = 0.7978845608028654f;
    float x3 = x * x * x;
    return 0.5f * x * (1.0f + tanhf(c * (x + 0.044715f * x3)));
}

// ---------------- PTX helpers ----------------
__device__ __forceinline__ uint32_t smem_u32(const void* p) {
    uint32_t a;
    asm("{ .reg .u64 t; cvta.to.shared.u64 t, %1; cvt.u32.u64 %0, t; }" : "=r"(a) : "l"(p));
    return a;
}
#define SW64(o)  ((o) ^ (((o) >> 3) & 0x30))

__device__ __forceinline__ uint64_t mk_desc64(uint32_t addr) {
    const uint64_t base = (uint64_t(4) << 61) | (uint64_t(1) << 46) |
                          (uint64_t(32) << 32) | (uint64_t(1) << 16);
    return base | ((uint64_t)(addr >> 4) & 0x3FFF);
}

// one-shot bulk copy (UBLKCP)
__device__ __forceinline__ void bulk_cp(uint32_t dst, const void* src, uint32_t bytes, uint32_t mbar) {
    asm volatile("cp.async.bulk.shared::cluster.global.mbarrier::complete_tx::bytes [%0], [%1], %2, [%3];"
        :: "r"(dst), "l"(src), "r"(bytes), "r"(mbar) : "memory");
}

#define MBARRIER_INIT(addr, cnt) \
    asm volatile("mbarrier.init.shared.b64 [%0], %1;" :: "r"((uint32_t)(addr)), "r"((uint32_t)(cnt)) : "memory")
#define MBARRIER_EXPECT_TX(addr, bytes) \
    asm volatile("mbarrier.arrive.expect_tx.shared.b64 _, [%0], %1;" :: "r"((uint32_t)(addr)), "r"((uint32_t)(bytes)) : "memory")

#define MBARRIER_WAIT_PARITY(addr, parity) do { \
    uint32_t _mbar = (uint32_t)(addr); \
    uint32_t _par = (uint32_t)(parity); \
    uint32_t _done; \
    asm volatile("{\n\t.reg .pred p;\n\t" \
        "mbarrier.try_wait.parity.acquire.cta.shared::cta.b64 p, [%1], %2;\n\t" \
        "selp.b32 %0, 1, 0, p;\n\t}" : "=r"(_done) : "r"(_mbar), "r"(_par) : "memory"); \
    if (!_done) { \
        asm volatile("{\n\t.reg .pred P1;\n\t" \
            "WAIT_LOOP_%=:\n\t" \
            "mbarrier.try_wait.parity.acquire.cta.shared::cta.b64 P1, [%0], %1, 0x989680;\n\t" \
            "@P1 bra.uni WAIT_DONE_%=;\n\t" \
            "bra.uni WAIT_LOOP_%=;\n\t" \
            "WAIT_DONE_%=:\n\t}" :: "r"(_mbar), "r"(_par) : "memory"); \
    } \
} while (0)

#if HAS_TC
#define TCGEN05_ALLOC(smem_addr, nCols) \
    asm volatile("tcgen05.alloc.cta_group::1.sync.aligned.shared::cta.b32 [%0], %1;" \
        :: "r"((uint32_t)(smem_addr)), "r"((uint32_t)(nCols)) : "memory")
#define TCGEN05_DEALLOC(tmem, nCols) \
    asm volatile("tcgen05.dealloc.cta_group::1.sync.aligned.b32 %0, %1;" :: "r"(tmem), "r"((uint32_t)(nCols)))
#define TCGEN05_COMMIT(mbar) \
    asm volatile("tcgen05.commit.cta_group::1.mbarrier::arrive::one.shared::cluster.b64 [%0];" \
        :: "r"((uint32_t)(mbar)) : "memory")
#define TCGEN05_FENCE_AFTER() asm volatile("tcgen05.fence::after_thread_sync;" ::: "memory")
#define TCGEN05_WAIT_LD() asm volatile("tcgen05.wait::ld.sync.aligned;" ::: "memory")

#define TCGEN05_LD_32X32B_X32(r, tmem_addr) \
    asm volatile( \
        "tcgen05.ld.sync.aligned.32x32b.x32.b32 " \
        "{%0, %1, %2, %3, %4, %5, %6, %7, " \
        " %8, %9, %10, %11, %12, %13, %14, %15, " \
        " %16, %17, %18, %19, %20, %21, %22, %23, " \
        " %24, %25, %26, %27, %28, %29, %30, %31}, [%32];" \
        : "=r"((r)[0]),  "=r"((r)[1]),  "=r"((r)[2]),  "=r"((r)[3]), \
          "=r"((r)[4]),  "=r"((r)[5]),  "=r"((r)[6]),  "=r"((r)[7]), \
          "=r"((r)[8]),  "=r"((r)[9]),  "=r"((r)[10]), "=r"((r)[11]), \
          "=r"((r)[12]), "=r"((r)[13]), "=r"((r)[14]), "=r"((r)[15]), \
          "=r"((r)[16]), "=r"((r)[17]), "=r"((r)[18]), "=r"((r)[19]), \
          "=r"((r)[20]), "=r"((r)[21]), "=r"((r)[22]), "=r"((r)[23]), \
          "=r"((r)[24]), "=r"((r)[25]), "=r"((r)[26]), "=r"((r)[27]), \
          "=r"((r)[28]), "=r"((r)[29]), "=r"((r)[30]), "=r"((r)[31]) \
        : "r"(tmem_addr))

__device__ __forceinline__ void mma_bf16_ss(uint32_t d, uint64_t ad, uint64_t bd,
                                            uint32_t idesc, uint32_t en) {
    asm volatile(
        "{\n\t.reg .pred p;\n\tsetp.ne.u32 p, %5, 0;\n\t"
        "tcgen05.mma.cta_group::1.kind::f16 [%0], %1, %2, %3, {%4, %4, %4, %4}, p;\n\t}"
        :: "r"(d), "l"(ad), "l"(bd), "r"(idesc), "r"(0u), "r"(en) : "memory");
}
__device__ __forceinline__ uint32_t elect1() {
    uint32_t r;
    asm volatile("{\n\t.reg .pred p;\n\telect.sync _|p, 0xFFFFFFFF;\n\tselp.b32 %0, 1, 0, p;\n\t}" : "=r"(r));
    return r;
}
#endif // HAS_TC

// staged-activation addressing
__device__ __forceinline__ void stageA_write(char* S, int NCc, int row, int col, float v) {
    bf16 h = __float2bfloat16(v);
    bf16 l = __float2bfloat16(v - __bfloat162float(h));
    size_t blk = (size_t)((row >> 7) * NCc + (col >> 5)) * 16384;
    uint32_t o = SW64((uint32_t)((row & 127) * 64 + (col & 31) * 2));
    *(bf16*)(S + blk + o) = h;
    *(bf16*)(S + blk + 8192 + o) = l;
}
// vectorized: 8 consecutive cols (col8 multiple of 8) in one 16B unit per plane
__device__ __forceinline__ void stageA_write8(char* S, int NCc, int row, int col8,
                                              const float* v8) {
    uint32_t hw[4], lw[4];
#pragma unroll
    for (int q = 0; q < 4; q++) {
        bf16 h0 = __float2bfloat16(v8[q*2+0]);
        bf16 h1 = __float2bfloat16(v8[q*2+1]);
        bf16 l0 = __float2bfloat16(v8[q*2+0] - __bfloat162float(h0));
        bf16 l1 = __float2bfloat16(v8[q*2+1] - __bfloat162float(h1));
        hw[q] = ((uint32_t)__bfloat16_as_ushort(h1) << 16) | __bfloat16_as_ushort(h0);
        lw[q] = ((uint32_t)__bfloat16_as_ushort(l1) << 16) | __bfloat16_as_ushort(l0);
    }
    size_t blk = (size_t)((row >> 7) * NCc + (col8 >> 5)) * 16384;
    uint32_t o = SW64((uint32_t)((row & 127) * 64 + (col8 & 31) * 2));
    *(uint4*)(S + blk + o) = make_uint4(hw[0], hw[1], hw[2], hw[3]);
    *(uint4*)(S + blk + 8192 + o) = make_uint4(lw[0], lw[1], lw[2], lw[3]);
}
__device__ __forceinline__ float stageA_read(const char* S, int NCc, int row, int col) {
    size_t blk = (size_t)((row >> 7) * NCc + (col >> 5)) * 16384;
    uint32_t o = SW64((uint32_t)((row & 127) * 64 + (col & 31) * 2));
    return __bfloat162float(*(const bf16*)(S + blk + o)) +
           __bfloat162float(*(const bf16*)(S + blk + 8192 + o));
}

// ---------------- prep kernels ----------------
__global__ void splitX_kernel(const float* __restrict__ X, char* __restrict__ XS) {
    size_t u = (size_t)blockIdx.x * 256 + threadIdx.x;   // unit of 8 elements
    if (u < (size_t)BNR * IND / 8) {
        int row = (int)(u / (IND / 8));
        int col8 = (int)(u - (size_t)row * (IND / 8)) * 8;
        float v8[8];
        const float* p = X + (size_t)row * IND + col8;
#pragma unroll
        for (int q = 0; q < 8; q++) v8[q] = p[q];
        stageA_write8(XS, 24, row, col8, v8);
    }
}

__device__ __forceinline__ void tstage_one(const float* W, char* S, int i,
                                           int Kw, int NC, int rowOff, int ldW) {
    int n = i / Kw, k = i - n * Kw;
    float v = W[(size_t)(rowOff + k) * ldW + n];
    bf16 h = __float2bfloat16(v);
    bf16 l = __float2bfloat16(v - __bfloat162float(h));
    int ntile = n >> 8, lrow = n & 255;
    int chunk = k >> 5, kin = k & 31;
    uint32_t o = SW64((uint32_t)(lrow * 64 + kin * 2));
    size_t blk = (size_t)(ntile * NC + chunk) * 32768;
    *(bf16*)(S + blk + o) = h;
    *(bf16*)(S + blk + 16384 + o) = l;
}
__device__ __forceinline__ void h2stage_one(const float* W, char* S, int i) {
    int n = i / PAIRD, k = i - n * PAIRD;
    float v = W[(size_t)k * (PAIRD / 2) + n];
    bf16 h = __float2bfloat16(v);
    bf16 l = __float2bfloat16(v - __bfloat162float(h));
    int chunk = k >> 5, kin = k & 31;
    uint32_t o = SW64((uint32_t)(n * 64 + kin * 2));
    size_t blk = (size_t)chunk * 51200;
    *(bf16*)(S + blk + o) = h;
    *(bf16*)(S + blk + 25600 + o) = l;
}

#define TS0 (IND * HIDD)
#define TS1 (TS0 + HIDD * OUTD)
#define TS2 (TS1 + OUTD * OUTD)
#define TS3 (TS2 + OUTD * PAIRD)
#define TS4 (TS3 + OUTD * PAIRD)
#define TS5 (TS4 + PAIRD * (PAIRD/2))
__global__ void tsplit_all_kernel(
    const float* __restrict__ enc_w1, const float* __restrict__ enc_w2,
    const float* __restrict__ gat_w, const float* __restrict__ h_w1,
    const float* __restrict__ h_w2,
    char* w1tS, char* w2tS, char* wgtS, char* w1aS, char* w1bS, char* h2BS,
    int* counts)
{
    int i = blockIdx.x * 256 + threadIdx.x;
    if (i < NN) counts[i] = 0;
    if (i < TS0)      tstage_one(enc_w1, w1tS, i,        IND,  24, 0,    HIDD);
    else if (i < TS1) tstage_one(enc_w2, w2tS, i - TS0,  HIDD, 16, 0,    OUTD);
    else if (i < TS2) tstage_one(gat_w,  wgtS, i - TS1,  OUTD, 13, 0,    OUTD);
    else if (i < TS3) tstage_one(h_w1,   w1aS, i - TS2,  OUTD, 13, 0,    PAIRD);
    else if (i < TS4) tstage_one(h_w1,   w1bS, i - TS3,  OUTD, 13, OUTD, PAIRD);
    else if (i < TS5) h2stage_one(h_w2,  h2BS, i - TS4);
}

// ---------------- split-bf16 tcgen05 GEMM, BM=128, BN<=256, BK=32, SW64 ----------------
#define MM_HDR   8192
#define MM_ASTG  16384
#define MM_BSTG  32768
#define MM_STG   (MM_ASTG + MM_BSTG)
#define MM_NSTG  4
#define SMEM_TOTAL_MM (MM_HDR + MM_NSTG * MM_STG)   // 204800
#define CPITCH 65

template<bool BIAS, bool GELU_, bool WF32, bool WHILO>
__global__ __launch_bounds__(256, 1) void mm_kernel(
    const char* __restrict__ Astg,
    const char* __restrict__ Bstg,
    const float* __restrict__ bias,
    float* __restrict__ Cf, char* __restrict__ Cstg,
    int N, int K, int NCc)
{
#if HAS_TC
    extern __shared__ char dsm[];
    const int tid = threadIdx.x;
    const int wid = tid >> 5;
    const uint32_t sb = smem_u32(dsm);
    const int mBase = blockIdx.y * 128;
    const int nBase = blockIdx.x * 256;
    const int nValid = min(256, N - nBase);
    const int NC = (K + 31) >> 5;

    if (tid == 0) {
        for (int i = 0; i < 4; i++) { MBARRIER_INIT(sb + 16 + i * 8, 1); MBARRIER_INIT(sb + 48 + i * 8, 1); }
    }
    if (wid == 0) TCGEN05_ALLOC(sb, 256);
    __syncthreads();
    uint32_t tmem;
    asm volatile("ld.shared.b32 %0, [%1];" : "=r"(tmem) : "r"(sb));

    const uint32_t idesc = (1u << 4) | (1u << 7) | (1u << 10) |
                           ((uint32_t)(nValid >> 3) << 17) | (8u << 24);

    // single-thread producer/MMA pipeline; tid0 alone waits the final commit
    if (tid == 0) {
        auto prep = [&](int cc) {
            if (cc >= MM_NSTG)
                MBARRIER_WAIT_PARITY(sb + 16 + (cc & 3) * 8, ((cc - MM_NSTG) >> 2) & 1);
            uint32_t stg = sb + MM_HDR + (cc & 3) * MM_STG;
            uint32_t fb = sb + 48 + (cc & 3) * 8;
            MBARRIER_EXPECT_TX(fb, 49152u);
            bulk_cp(stg, Astg + ((size_t)(blockIdx.y * NC + cc)) * 16384, 16384u, fb);
            bulk_cp(stg + 16384, Bstg + ((size_t)(blockIdx.x * NC + cc)) * 32768, 32768u, fb);
        };
        prep(0);
        if (NC > 1) prep(1);
        for (int c = 0; c < NC; c++) {
            if (c + 2 < NC) prep(c + 2);
            MBARRIER_WAIT_PARITY(sb + 48 + (c & 3) * 8, (c >> 2) & 1);   // A+B full
            uint32_t stg = sb + MM_HDR + (c & 3) * MM_STG;
            uint64_t dAh = mk_desc64(stg);
            uint64_t dAl = mk_desc64(stg + 8192);
            uint64_t dBh = mk_desc64(stg + 16384);
            uint64_t dBl = mk_desc64(stg + 32768);
            int ksteps = min(2, (K - (c << 5)) >> 4);
            for (int ks = 0; ks < ksteps; ks++) {
                uint64_t o = (uint64_t)(ks * 2);
                mma_bf16_ss(tmem, dAh + o, dBh + o, idesc, (c | ks) ? 1u : 0u);
                mma_bf16_ss(tmem, dAh + o, dBl + o, idesc, 1u);
                mma_bf16_ss(tmem, dAl + o, dBh + o, idesc, 1u);
            }
            TCGEN05_COMMIT(sb + 16 + (c & 3) * 8);
        }
        // only tid0 parity-waits here (its program order makes this safe)
        MBARRIER_WAIT_PARITY(sb + 16 + ((NC - 1) & 3) * 8, ((NC - 1) >> 2) & 1);
    }
    __syncthreads();
    TCGEN05_FENCE_AFTER();

    // ---- epilogue ----
    {
        int sub = wid & 3, cg = wid >> 2;
        int lane = tid & 31;
        float* cst = (float*)(dsm + MM_HDR);
        for (int cb0 = 0; cb0 < nValid; cb0 += 64) {
            int cb = cb0 + cg * 32;
            if (cb < nValid) {
                uint32_t regs[32];
                TCGEN05_LD_32X32B_X32(regs, tmem + cb);
                TCGEN05_WAIT_LD();
                int r = sub * 32 + lane;
#pragma unroll
                for (int j = 0; j < 32; j++) {
                    int col = cb + j;
                    if (col < nValid) {
                        float v = __uint_as_float(regs[j]);
                        if (BIAS) v += bias[nBase + col];
                        if (GELU_) v = gelu_tanh(v);
                        cst[r * CPITCH + (cg * 32 + j)] = v;
                    }
                }
            }
            __syncthreads();
            int cw = min(64, nValid - cb0);
            if (WHILO) {
                // vectorized staged writes: 8-col units, 2x 16B stores each
                int uw = cw >> 3;                        // units per row (cw multiple of 8)
                for (int u = tid; u < 128 * uw; u += 256) {
                    int row = u / uw, s8 = u - row * uw;
                    int colL = s8 * 8;                   // col within 64-block
                    float v8[8];
#pragma unroll
                    for (int q = 0; q < 8; q++) v8[q] = cst[row * CPITCH + colL + q];
                    stageA_write8(Cstg, NCc, mBase + row, nBase + cb0 + colL, v8);
                }
            }
            if (WF32) {
                for (int i = tid; i < 128 * cw; i += 256) {
                    int row = i / cw, col = i - row * cw;
                    float v = cst[row * CPITCH + col];
                    Cf[(size_t)(mBase + row) * N + nBase + cb0 + col] = v;
                }
            }
            __syncthreads();
        }
    }
    __syncthreads();
    if (wid == 0) TCGEN05_DEALLOC(tmem, 256);

#else // !HAS_TC — naive correct fallback
    const int tid = threadIdx.x;
    const int mBase = blockIdx.y * 128;
    const int nBase = blockIdx.x * 256;
    const int nValid = min(256, N - nBase);
    const int NC = (K + 31) >> 5;
    if (tid >= 128) return;
    int row = mBase + tid;
    for (int col = 0; col < nValid; col++) {
        int gc = nBase + col;
        float acc = 0.f;
        for (int k = 0; k < K; k++) {
            float a = stageA_read(Astg, NC, row, k);
            int ntile = blockIdx.x, lrow = col;
            size_t blk = (size_t)(ntile * NC + (k >> 5)) * 32768;
            uint32_t o = SW64((uint32_t)(lrow * 64 + (k & 31) * 2));
            float bb = __bfloat162float(*(const bf16*)(Bstg + blk + o)) +
                       __bfloat162float(*(const bf16*)(Bstg + blk + 16384 + o));
            acc += a * bb;
        }
        if (BIAS) acc += bias[gc];
        if (GELU_) acc = gelu_tanh(acc);
        if (WF32) Cf[(size_t)row * N + gc] = acc;
        if (WHILO) stageA_write(Cstg, NCc, row, gc, acc);
    }
#endif
}

// ---------------- fused head2 (BK=32, SW64, bulk-B pipelined) ----------------
#define H2_HDR   12288
#define H2_ASTG  16384
#define H2_BSTG  51200
#define H2_ABASE H2_HDR
#define H2_BBASE (H2_HDR + 4 * H2_ASTG)
#define H2_SMEM  (H2_BBASE + 3 * H2_BSTG)    // 231424
#define H2_MB_FULL 10752

__global__ __launch_bounds__(256, 1) void head2_kernel(
    const float* __restrict__ U, const float* __restrict__ V,
    const char* __restrict__ BS,
    const float* __restrict__ b1, const float* __restrict__ b2,
    const float* __restrict__ w3, const float* __restrict__ b3,
    const int* __restrict__ src0, const int* __restrict__ dst0,
    float* __restrict__ pred)
{
#if HAS_TC
    extern __shared__ char dsm[];
    const int tid = threadIdx.x;
    const int wid = tid >> 5;
    const uint32_t sb = smem_u32(dsm);
    const int mBase = blockIdx.x * 128;
    const int NC = 25;
    int* sSrc = (int*)(dsm + 64);
    int* sDst = (int*)(dsm + 576);
    float* sw3 = (float*)(dsm + 1152);
    float* b1s = (float*)(dsm + 5952);
    float* b2s = (float*)(dsm + 9152);

    if (tid == 0) {
        for (int i = 0; i < 4; i++) {
            MBARRIER_INIT(sb + 16 + i * 8, 1);
            MBARRIER_INIT(sb + H2_MB_FULL + i * 8, 1);
        }
    }
    if (wid == 0) TCGEN05_ALLOC(sb, 512);
    if (tid < 128) {
        int r = mBase + tid;
        int e = r & (EE - 1), b = r >> 14;
        sSrc[tid] = (b << 10) + src0[e];
        sDst[tid] = (b << 10) + dst0[e];
    }
    for (int i = tid; i < 1200; i += 256) sw3[i] = w3[i];
    for (int i = tid; i < 800; i += 256) b1s[i] = b1[i];
    for (int i = tid; i < 400; i += 256) b2s[i] = b2[i];
    __syncthreads();
    uint32_t tmem;
    asm volatile("ld.shared.b32 %0, [%1];" : "=r"(tmem) : "r"(sb));

    const uint32_t idesc = (1u << 4) | (1u << 7) | (1u << 10) | (25u << 17) | (8u << 24);

    auto wait_commit = [&](int j) {
        MBARRIER_WAIT_PARITY(sb + 16 + (j & 3) * 8, (j >> 2) & 1);
    };
    auto prep = [&](int cc) {
        int k0 = cc * 32;
        if (cc >= 4) wait_commit(cc - 4);
        char* astg = dsm + H2_ABASE + (cc & 3) * H2_ASTG;
#pragma unroll
        for (int i = 0; i < 2; i++) {
            int idx = i * 256 + tid;
            int row = idx >> 2, seg = idx & 3;
            int col = k0 + seg * 8;
            int sn = sSrc[row], dn = sDst[row];
            const float* up = U + (size_t)sn * PAIRD + col;
            const float* vp = V + (size_t)dn * PAIRD + col;
            float4 u0 = *(const float4*)up, u1 = *(const float4*)(up + 4);
            float4 v0 = *(const float4*)vp, v1 = *(const float4*)(vp + 4);
            float4 c0 = *(const float4*)(b1s + col);
            float4 c1 = *(const float4*)(b1s + col + 4);
            float r8[8];
            r8[0] = gelu_tanh(u0.x + v0.x + c0.x);
            r8[1] = gelu_tanh(u0.y + v0.y + c0.y);
            r8[2] = gelu_tanh(u0.z + v0.z + c0.z);
            r8[3] = gelu_tanh(u0.w + v0.w + c0.w);
            r8[4] = gelu_tanh(u1.x + v1.x + c1.x);
            r8[5] = gelu_tanh(u1.y + v1.y + c1.y);
            r8[6] = gelu_tanh(u1.z + v1.z + c1.z);
            r8[7] = gelu_tanh(u1.w + v1.w + c1.w);
            uint32_t hw[4], lw[4];
#pragma unroll
            for (int q = 0; q < 4; q++) {
                bf16 h0 = __float2bfloat16(r8[q*2+0]);
                bf16 h1 = __float2bfloat16(r8[q*2+1]);
                bf16 l0 = __float2bfloat16(r8[q*2+0] - __bfloat162float(h0));
                bf16 l1 = __float2bfloat16(r8[q*2+1] - __bfloat162float(h1));
                hw[q] = ((uint32_t)__bfloat16_as_ushort(h1) << 16) | __bfloat16_as_ushort(h0);
                lw[q] = ((uint32_t)__bfloat16_as_ushort(l1) << 16) | __bfloat16_as_ushort(l0);
            }
            uint32_t sw = SW64(row * 64 + seg * 16);
            *(uint4*)(astg + sw) = make_uint4(hw[0], hw[1], hw[2], hw[3]);
            *(uint4*)(astg + 8192 + sw) = make_uint4(lw[0], lw[1], lw[2], lw[3]);
        }
        if (cc >= 3) wait_commit(cc - 3);
        if (tid == 0) {
            uint32_t fb = sb + H2_MB_FULL + (cc & 3) * 8;
            MBARRIER_EXPECT_TX(fb, 51200u);
            bulk_cp(sb + H2_BBASE + (cc % 3) * H2_BSTG, BS + (size_t)cc * 51200, 51200u, fb);
        }
    };

    prep(0);
    prep(1);
    for (int c = 0; c < NC; c++) {
        if (c + 2 < NC) prep(c + 2);
        asm volatile("fence.proxy.async.shared::cta;" ::: "memory");
        __syncthreads();
        if (wid == 0 && elect1()) {
            MBARRIER_WAIT_PARITY(sb + H2_MB_FULL + (c & 3) * 8, (c >> 2) & 1);
            uint32_t ag = sb + H2_ABASE + (c & 3) * H2_ASTG;
            uint64_t dAh = mk_desc64(ag);
            uint64_t dAl = mk_desc64(ag + 8192);
            uint32_t bg = sb + H2_BBASE + (c % 3) * H2_BSTG;
#pragma unroll
            for (int half = 0; half < 2; half++) {
                uint64_t dBh = mk_desc64(bg + half * 12800);
                uint64_t dBl = mk_desc64(bg + 25600 + half * 12800);
                uint32_t d = tmem + half * 200;
#pragma unroll
                for (int ks = 0; ks < 2; ks++) {
                    uint64_t o = (uint64_t)(ks * 2);
                    mma_bf16_ss(d, dAh + o, dBh + o, idesc, (c | ks) ? 1u : 0u);
                    mma_bf16_ss(d, dAh + o, dBl + o, idesc, 1u);
                    mma_bf16_ss(d, dAl + o, dBh + o, idesc, 1u);
                }
            }
            TCGEN05_COMMIT(sb + 16 + (c & 3) * 8);
        }
    }
    wait_commit(NC - 1);
    TCGEN05_FENCE_AFTER();

    // ---- epilogue: gelu(.+b2) dot W3 -> pred ----
    {
        int sub = wid & 3, cg = wid >> 2;
        int lane = tid & 31;
        float* cst = (float*)(dsm + H2_HDR);
        float d0 = 0.f, d1 = 0.f, d2 = 0.f;
        for (int cb0 = 0; cb0 < 400; cb0 += 64) {
            int cb = cb0 + cg * 32;
            if (cb < 400) {
                uint32_t regs[32];
                TCGEN05_LD_32X32B_X32(regs, tmem + cb);
                TCGEN05_WAIT_LD();
                int r = sub * 32 + lane;
#pragma unroll
                for (int j = 0; j < 32; j++) {
                    int col = cb + j;
                    if (col < 400) {
                        float v = __uint_as_float(regs[j]) + b2s[col];
                        v = gelu_tanh(v);
                        cst[r * CPITCH + (cg * 32 + j)] = v;
                    }
                }
            }
            __syncthreads();
            int cw = min(64, 400 - cb0);
            if (tid < 128) {
                for (int col = 0; col < cw; col++) {
                    float v = cst[tid * CPITCH + col];
                    int wc = (cb0 + col) * 3;
                    d0 += v * sw3[wc + 0];
                    d1 += v * sw3[wc + 1];
                    d2 += v * sw3[wc + 2];
                }
            }
            __syncthreads();
        }
        if (tid < 128) {
            size_t r = (size_t)(mBase + tid);
            pred[r * 3 + 0] = d0 + b3[0];
            pred[r * 3 + 1] = d1 + b3[1];
            pred[r * 3 + 2] = d2 + b3[2];
        }
    }
    __syncthreads();
    if (wid == 0) TCGEN05_DEALLOC(tmem, 512);

#else // !HAS_TC — naive correct fallback
    const int tid = threadIdx.x;
    const int mBase = blockIdx.x * 128;
    if (tid >= 128) return;
    int row = mBase + tid;
    int e = row & (EE - 1), b = row >> 14;
    int sn = (b << 10) + src0[e];
    int dn = (b << 10) + dst0[e];
    float d0 = 0.f, d1 = 0.f, d2 = 0.f;
    for (int col = 0; col < 400; col++) {
        float acc = 0.f;
        for (int k = 0; k < PAIRD; k++) {
            float a = gelu_tanh(U[(size_t)sn * PAIRD + k] + V[(size_t)dn * PAIRD + k] + b1[k]);
            size_t blk = (size_t)(k >> 5) * 51200;
            uint32_t o = SW64((uint32_t)(col * 64 + (k & 31) * 2));
            float bb = __bfloat162float(*(const bf16*)(BS + blk + o)) +
                       __bfloat162float(*(const bf16*)(BS + blk + 25600 + o));
            acc += a * bb;
        }
        acc = gelu_tanh(acc + b2[col]);
        d0 += acc * w3[col * 3 + 0];
        d1 += acc * w3[col * 3 + 1];
        d2 += acc * w3[col * 3 + 2];
    }
    pred[(size_t)row * 3 + 0] = d0 + b3[0];
    pred[(size_t)row * 3 + 1] = d1 + b3[1];
    pred[(size_t)row * 3 + 2] = d2 + b3[2];
#endif
}

// ---------------- attention scores ----------------
__global__ void attn_score_kernel(const float* __restrict__ wh,
                                  const float* __restrict__ att_src,
                                  const float* __restrict__ att_dst,
                                  float* __restrict__ as_, float* __restrict__ ad_)
{
    int bn = blockIdx.x;
    int h = threadIdx.x >> 5, lane = threadIdx.x & 31;
    const float* w = wh + (size_t)bn * OUTD + h * 200;
    float s = 0.f, d = 0.f;
    for (int f = lane; f < 200; f += 32) {
        float v = w[f];
        s += v * att_src[h * 200 + f];
        d += v * att_dst[h * 200 + f];
    }
#pragma unroll
    for (int o = 16; o; o >>= 1) {
        s += __shfl_down_sync(0xffffffffu, s, o);
        d += __shfl_down_sync(0xffffffffu, d, o);
    }
    if (lane == 0) { as_[bn * 2 + h] = s; ad_[bn * 2 + h] = d; }
}

// ---------------- CSR build ----------------
__global__ void count_kernel(const int* __restrict__ edges, int* __restrict__ counts) {
    int et = blockIdx.x * 256 + threadIdx.x;
    if (et >= ETOT) return;
    int dst = (et < EE) ? edges[EE + et] : (et - EE);
    atomicAdd(&counts[dst], 1);
}

__global__ void scan_kernel(const int* __restrict__ counts, int* __restrict__ rowstart,
                            int* __restrict__ fill) {
    __shared__ int s[NN];
    int t = threadIdx.x;
    int c = counts[t];
    s[t] = c;
    __syncthreads();
    for (int o = 1; o < NN; o <<= 1) {
        int v = (t >= o) ? s[t - o] : 0;
        __syncthreads();
        s[t] += v;
        __syncthreads();
    }
    rowstart[t + 1] = s[t];
    if (t == 0) rowstart[0] = 0;
    fill[t] = s[t] - c;
}

__global__ void scatter_kernel(const int* __restrict__ edges, int* __restrict__ fill,
                               int* __restrict__ csrsrc) {
    int et = blockIdx.x * 256 + threadIdx.x;
    if (et >= ETOT) return;
    int src = (et < EE) ? edges[et] : (et - EE);
    int dst = (et < EE) ? edges[EE + et] : (et - EE);
    int pos = atomicAdd(&fill[dst], 1);
    csrsrc[pos] = src;
}

// ---------------- GAT: warp-per-node, shuffle-only ----------------
__global__ void gat_kernel(const float* __restrict__ wh, const float* __restrict__ as_,
                           const float* __restrict__ ad_, const float* __restrict__ enc,
                           const float* __restrict__ gat_b,
                           const int* __restrict__ rowstart, const int* __restrict__ csrsrc,
                           float* __restrict__ feat, char* __restrict__ featS)
{
    int w = threadIdx.x >> 5, lane = threadIdx.x & 31;
    int bn = blockIdx.x * 8 + w;
    int b = bn >> 10, n = bn & 1023;
    int start = rowstart[n];
    int deg = rowstart[n + 1] - start;
    float ad0 = ad_[bn * 2 + 0], ad1 = ad_[bn * 2 + 1];

    float m0 = -1e30f, m1 = -1e30f;
    for (int i = lane; i < deg; i += 32) {
        int sb2 = (b << 10) + csrsrc[start + i];
        float e0 = as_[sb2 * 2 + 0] + ad0; e0 = (e0 > 0.f) ? e0 : 0.2f * e0;
        float e1 = as_[sb2 * 2 + 1] + ad1; e1 = (e1 > 0.f) ? e1 : 0.2f * e1;
        m0 = fmaxf(m0, e0); m1 = fmaxf(m1, e1);
    }
#pragma unroll
    for (int o = 16; o; o >>= 1) {
        m0 = fmaxf(m0, __shfl_xor_sync(0xffffffffu, m0, o));
        m1 = fmaxf(m1, __shfl_xor_sync(0xffffffffu, m1, o));
    }
    float z0 = 0.f, z1 = 0.f;
    for (int i = lane; i < deg; i += 32) {
        int sb2 = (b << 10) + csrsrc[start + i];
        float e0 = as_[sb2 * 2 + 0] + ad0; e0 = (e0 > 0.f) ? e0 : 0.2f * e0;
        float e1 = as_[sb2 * 2 + 1] + ad1; e1 = (e1 > 0.f) ? e1 : 0.2f * e1;
        z0 += expf(e0 - m0);
        z1 += expf(e1 - m1);
    }
#pragma unroll
    for (int o = 16; o; o >>= 1) {
        z0 += __shfl_xor_sync(0xffffffffu, z0, o);
        z1 += __shfl_xor_sync(0xffffffffu, z1, o);
    }
    float inv0 = 1.f / z0, inv1 = 1.f / z1;

    float acc[13];
#pragma unroll
    for (int j = 0; j < 13; j++) acc[j] = 0.f;
    for (int i = 0; i < deg; i++) {
        int sb2 = (b << 10) + csrsrc[start + i];
        float e0 = as_[sb2 * 2 + 0] + ad0; e0 = (e0 > 0.f) ? e0 : 0.2f * e0;
        float e1 = as_[sb2 * 2 + 1] + ad1; e1 = (e1 > 0.f) ? e1 : 0.2f * e1;
        float c0 = expf(e0 - m0) * inv0;
        float c1 = expf(e1 - m1) * inv1;
        const float* row = wh + (size_t)sb2 * OUTD;
#pragma unroll
        for (int j = 0; j < 13; j++) {
            int col = lane + 32 * j;
            if (col < OUTD) acc[j] += ((col < 200) ? c0 : c1) * row[col];
        }
    }
    size_t base = (size_t)bn * OUTD;
#pragma unroll
    for (int j = 0; j < 13; j++) {
        int col = lane + 32 * j;
        if (col < OUTD) {
            float v = enc[base + col] + acc[j] + gat_b[col];
            feat[base + col] = v;
            stageA_write(featS, 13, bn, col, v);
        }
    }
}

// ---------------- launch ----------------
extern "C" void kernel_launch(void* const* d_in, const int* in_sizes, int n_in,
                              void* d_out, int out_size)
{
    const float* X       = (const float*)d_in[0];
    const int*   edges   = (const int*)  d_in[1];
    const float* enc_w1  = (const float*)d_in[2];
    const float* enc_b1  = (const float*)d_in[3];
    const float* enc_w2  = (const float*)d_in[4];
    const float* enc_b2  = (const float*)d_in[5];
    const float* gat_w   = (const float*)d_in[6];
    const float* att_src = (const float*)d_in[7];
    const float* att_dst = (const float*)d_in[8];
    const float* gat_b   = (const float*)d_in[9];
    const float* h_w1    = (const float*)d_in[10];
    const float* h_b1    = (const float*)d_in[11];
    const float* h_w2    = (const float*)d_in[12];
    const float* h_b2    = (const float*)d_in[13];
    const float* h_w3    = (const float*)d_in[14];
    const float* h_b3    = (const float*)d_in[15];

    float* out  = (float*)d_out;
    float* feat = out;
    float* pred = out + FEAT_ELEMS;

    char *XS, *hidS, *encS, *featS;
    char *w1tS, *w2tS, *wgtS, *w1aS, *w1bS, *h2BS;
    float *enc, *wh, *as_, *ad_, *U, *V;
    int *counts, *rowstart, *fill, *csrsrc;
    cudaGetSymbolAddress((void**)&XS, g_XS);         cudaGetSymbolAddress((void**)&hidS, g_hidS);
    cudaGetSymbolAddress((void**)&encS, g_encS);     cudaGetSymbolAddress((void**)&featS, g_featS);
    cudaGetSymbolAddress((void**)&enc, g_enc);       cudaGetSymbolAddress((void**)&wh, g_wh);
    cudaGetSymbolAddress((void**)&U, g_U);           cudaGetSymbolAddress((void**)&V, g_V);
    cudaGetSymbolAddress((void**)&w1tS, g_w1tS);     cudaGetSymbolAddress((void**)&w2tS, g_w2tS);
    cudaGetSymbolAddress((void**)&wgtS, g_wgtS);     cudaGetSymbolAddress((void**)&w1aS, g_w1aS);
    cudaGetSymbolAddress((void**)&w1bS, g_w1bS);     cudaGetSymbolAddress((void**)&h2BS, g_h2BS);
    cudaGetSymbolAddress((void**)&as_, g_as);        cudaGetSymbolAddress((void**)&ad_, g_ad);
    cudaGetSymbolAddress((void**)&counts, g_counts); cudaGetSymbolAddress((void**)&rowstart, g_rowstart);
    cudaGetSymbolAddress((void**)&fill, g_fill);     cudaGetSymbolAddress((void**)&csrsrc, g_csrsrc);

    const int* src0 = edges;
    const int* dst0 = edges + EE;

    cudaFuncSetAttribute(mm_kernel<true ,true ,false,true >, cudaFuncAttributeMaxDynamicSharedMemorySize, SMEM_TOTAL_MM);
    cudaFuncSetAttribute(mm_kernel<true ,false,true ,true >, cudaFuncAttributeMaxDynamicSharedMemorySize, SMEM_TOTAL_MM);
    cudaFuncSetAttribute(mm_kernel<false,false,true ,false>, cudaFuncAttributeMaxDynamicSharedMemorySize, SMEM_TOTAL_MM);
    cudaFuncSetAttribute(head2_kernel, cudaFuncAttributeMaxDynamicSharedMemorySize, H2_SMEM);

    // 1) stage all weights + zero counts
    tsplit_all_kernel<<<(TS5 + 255) / 256, 256>>>(
        enc_w1, enc_w2, gat_w, h_w1, h_w2,
        w1tS, w2tS, wgtS, w1aS, w1bS, h2BS, counts);
    // 2) stage X (vectorized 8-col units)
    {
        size_t nU = (size_t)BNR * IND / 8;
        splitX_kernel<<<(unsigned)((nU + 255) / 256), 256>>>(X, XS);
    }
    // 3) CSR count
    count_kernel<<<(ETOT + 255) / 256, 256>>>(edges, counts);
    // 4) enc1  <-- profiled launch
    mm_kernel<true,true,false,true><<<dim3(2, BNR/128), 256, SMEM_TOTAL_MM>>>(
        XS, w1tS, enc_b1, nullptr, hidS, HIDD, IND, 16);
    // 5-6) CSR scan + scatter
    scan_kernel<<<1, NN>>>(counts, rowstart, fill);
    scatter_kernel<<<(ETOT + 255) / 256, 256>>>(edges, fill, csrsrc);
    // 7) enc2
    mm_kernel<true,false,true,true><<<dim3(2, BNR/128), 256, SMEM_TOTAL_MM>>>(
        hidS, w2tS, enc_b2, enc, encS, OUTD, HIDD, 13);
    // 8) wh
    mm_kernel<false,false,true,false><<<dim3(2, BNR/128), 256, SMEM_TOTAL_MM>>>(
        encS, wgtS, nullptr, wh, nullptr, OUTD, OUTD, 0);
    // 9) attention scores
    attn_score_kernel<<<BNR, 64>>>(wh, att_src, att_dst, as_, ad_);
    // 10) GAT (warp-per-node) -> feat f32 (output) + featS
    gat_kernel<<<BNR / 8, 256>>>(wh, as_, ad_, enc, gat_b, rowstart, csrsrc, feat, featS);
    // 11) U = feat @ W1top
    mm_kernel<false,false,true,false><<<dim3(4, BNR/128), 256, SMEM_TOTAL_MM>>>(
        featS, w1aS, nullptr, U, nullptr, PAIRD, OUTD, 0);
    // 12) V = feat @ W1bot
    mm_kernel<false,false,true,false><<<dim3(4, BNR/128), 256, SMEM_TOTAL_MM>>>(
        featS, w1bS, nullptr, V, nullptr, PAIRD, OUTD, 0);
    // 13) head2 fused -> pred
    head2_kernel<<<BER / 128, 256, H2_SMEM>>>(
        U, V, h2BS, h_b1, h_b2, h_w3, h_b3, src0, dst0, pred);
}